// round 2
// baseline (speedup 1.0000x reference)
#include <cuda_runtime.h>
#include <math.h>

// Problem constants
#define Bq   8
#define Cc   256
#define Hh   64
#define Ww   64
#define Nn   4096            // H*W
#define NH   4
#define HD   64
#define BN   (Bq*Nn)         // 32768

// ---------------- scratch (device globals; no allocation allowed) -------------
__device__ float g_xnT [Bq*Cc*Nn];     // layernormed x, (B,C,N)
__device__ float g_qraw[Bq*NH*Nn*HD];  // (B,nh,N,hd)
__device__ float g_q   [Bq*NH*HD*Nn];  // (B,nh,hd,N)
__device__ float g_k   [Bq*NH*HD*Nn];
__device__ float g_v   [Bq*NH*HD*Nn];  // == (B,C,N) head-major
__device__ float g_att [Bq*Cc*Nn];     // attened_x stored (B,C,N)
__device__ float g_conv[Bq*Cc*Nn];     // gelu(dwconv), (B,C,N)
__device__ float g_attn[Bq*NH*HD*HD];  // (B,nh,hd,hd)
__device__ float g_pool[Bq*Cc];        // sum over n of attened
__device__ float g_gc  [Bq*Cc];        // sigmoid(channel_map)
__device__ float g_gs  [Bq*Nn];        // sigmoid(spatial_map)

__device__ __forceinline__ float gelu_f(float x){
    return 0.5f * x * (1.0f + erff(x * 0.70710678118654752f));
}
__device__ __forceinline__ float sigmoid_f(float x){
    return 1.0f / (1.0f + expf(-x));
}

// ---------------- 0: zero the accumulated buffers -----------------------------
__global__ void k_zero(){
    int i = blockIdx.x * 256 + threadIdx.x;
    if (i < Bq*NH*HD*HD) g_attn[i] = 0.f;
    if (i < Bq*Cc)       g_pool[i] = 0.f;
}

// ---------------- 1: LayerNorm over C, x(B,C,N) -> xnT(B,C,N) -----------------
__global__ void k_layernorm(const float* __restrict__ x,
                            const float* __restrict__ g,
                            const float* __restrict__ b){
    int bb = blockIdx.y;
    int n  = blockIdx.x * 256 + threadIdx.x;
    const float* xb = x + (size_t)bb * Cc * Nn;
    float s = 0.f, s2 = 0.f;
    #pragma unroll 8
    for (int c = 0; c < Cc; c++){
        float v = xb[(size_t)c * Nn + n];
        s += v; s2 += v * v;
    }
    float mu  = s * (1.f/Cc);
    float var = s2 * (1.f/Cc) - mu * mu;
    float inv = rsqrtf(var + 1e-5f);
    float* ob = g_xnT + (size_t)bb * Cc * Nn;
    #pragma unroll 8
    for (int c = 0; c < Cc; c++){
        float v = xb[(size_t)c * Nn + n];
        ob[(size_t)c * Nn + n] = (v - mu) * inv * g[c] + b[c];
    }
}

// ---------------- 2: qkv GEMM  (BN x 256) @ (256 x 768) -----------------------
// A = xnT (B,C,N), B = w_qkv (C,3C). Epilogue scatters q_raw/k/v.
__global__ void k_qkv_gemm(const float* __restrict__ w){
    __shared__ float sA[16][64];
    __shared__ float sB[16][64];
    int row0 = blockIdx.y * 64;          // bn
    int col0 = blockIdx.x * 64;          // o in [0,768)
    int bb = row0 >> 12;
    int n0 = row0 & (Nn-1);
    int tid = threadIdx.x;
    int tr = (tid >> 4) * 4;
    int tc = (tid & 15) * 4;
    float acc[4][4] = {};
    for (int k0 = 0; k0 < 256; k0 += 16){
        #pragma unroll
        for (int i = 0; i < 4; i++){
            int e  = tid + i * 256;
            int cl = e >> 6, nl = e & 63;
            sA[cl][nl] = g_xnT[((size_t)(bb*Cc + k0 + cl))*Nn + n0 + nl];
            int kl = e >> 6;
            sB[kl][nl] = w[(size_t)(k0 + kl) * 768 + col0 + nl];
        }
        __syncthreads();
        #pragma unroll
        for (int kk = 0; kk < 16; kk++){
            float a[4], bv[4];
            #pragma unroll
            for (int i = 0; i < 4; i++) a[i]  = sA[kk][tr + i];
            #pragma unroll
            for (int j = 0; j < 4; j++) bv[j] = sB[kk][tc + j];
            #pragma unroll
            for (int i = 0; i < 4; i++)
                #pragma unroll
                for (int j = 0; j < 4; j++)
                    acc[i][j] += a[i] * bv[j];
        }
        __syncthreads();
    }
    int which = col0 >> 8;               // 0=q,1=k,2=v
    int head  = (col0 >> 6) & 3;
    if (which == 0){
        #pragma unroll
        for (int i = 0; i < 4; i++){
            int n = n0 + tr + i;
            float4 val = make_float4(acc[i][0], acc[i][1], acc[i][2], acc[i][3]);
            *(float4*)&g_qraw[((size_t)((bb*NH + head)*Nn + n))*HD + tc] = val;
        }
    } else {
        float* dst = (which == 1) ? g_k : g_v;
        #pragma unroll
        for (int j = 0; j < 4; j++){
            int d = tc + j;
            float4 val = make_float4(acc[0][j], acc[1][j], acc[2][j], acc[3][j]);
            *(float4*)&dst[((size_t)((bb*NH + head)*HD + d))*Nn + n0 + tr] = val;
        }
    }
}

// ---------------- 3: q projection: qraw(B,nh,N,hd) @ w_q + b_q -> q(B,nh,hd,N)
__global__ void k_qproj(const float* __restrict__ wq, const float* __restrict__ bq){
    int blk = blockIdx.x;
    int bh  = blk >> 7;                  // 0..31
    int n0  = (blk & 127) * 32;
    __shared__ float sraw[32][65];
    const float* src = g_qraw + ((size_t)bh * Nn + n0) * HD;
    #pragma unroll
    for (int i = 0; i < 8; i++){
        int idx = threadIdx.x + i * 256;
        int nl = idx >> 6, el = idx & 63;
        sraw[nl][el] = src[nl * HD + el];
    }
    __syncthreads();
    int nl = threadIdx.x & 31;
    int dg = threadIdx.x >> 5;           // 0..7
    float acc[8];
    #pragma unroll
    for (int j = 0; j < 8; j++) acc[j] = bq[dg*8 + j];
    for (int e = 0; e < 64; e++){
        float r = sraw[nl][e];
        #pragma unroll
        for (int j = 0; j < 8; j++) acc[j] += r * wq[e*HD + dg*8 + j];
    }
    float* dst = g_q + (size_t)bh * HD * Nn + n0 + nl;
    #pragma unroll
    for (int j = 0; j < 8; j++) dst[(size_t)(dg*8 + j) * Nn] = acc[j];
}

// ---------------- 4: L2 normalize q and k rows over N --------------------------
__global__ void k_l2norm(){
    int r = blockIdx.x;                  // 0..4095; <2048 q, else k
    float* ptr = (r < Bq*NH*HD) ? g_q + (size_t)r * Nn
                                : g_k + (size_t)(r - Bq*NH*HD) * Nn;
    __shared__ float red[256];
    float s = 0.f;
    for (int i = threadIdx.x; i < Nn; i += 256){ float v = ptr[i]; s += v*v; }
    red[threadIdx.x] = s;
    __syncthreads();
    for (int off = 128; off > 0; off >>= 1){
        if (threadIdx.x < off) red[threadIdx.x] += red[threadIdx.x + off];
        __syncthreads();
    }
    float inv = 1.f / fmaxf(sqrtf(red[0]), 1e-12f);
    for (int i = threadIdx.x; i < Nn; i += 256) ptr[i] *= inv;
}

// ---------------- 5: attn partial: q @ k^T over n-chunks (atomic accumulate) ---
__global__ void k_attn_qk(){
    int bh = blockIdx.y;                 // 0..31
    int n0 = blockIdx.x * 512;
    __shared__ float sQ[64][65];
    __shared__ float sK[64][65];
    int tid = threadIdx.x;
    int tr = (tid >> 4) * 4;
    int tc = (tid & 15) * 4;
    float acc[4][4] = {};
    const float* qb = g_q + (size_t)bh * HD * Nn;
    const float* kb = g_k + (size_t)bh * HD * Nn;
    for (int s = 0; s < 8; s++){
        int nn = n0 + s * 64;
        #pragma unroll
        for (int i = 0; i < 16; i++){
            int idx = tid + i * 256;
            int dl = idx >> 6, nl = idx & 63;
            sQ[dl][nl] = qb[(size_t)dl * Nn + nn + nl];
            sK[dl][nl] = kb[(size_t)dl * Nn + nn + nl];
        }
        __syncthreads();
        #pragma unroll 8
        for (int kk = 0; kk < 64; kk++){
            float a[4], bv[4];
            #pragma unroll
            for (int i = 0; i < 4; i++) a[i]  = sQ[tr + i][kk];
            #pragma unroll
            for (int j = 0; j < 4; j++) bv[j] = sK[tc + j][kk];
            #pragma unroll
            for (int i = 0; i < 4; i++)
                #pragma unroll
                for (int j = 0; j < 4; j++)
                    acc[i][j] += a[i] * bv[j];
        }
        __syncthreads();
    }
    #pragma unroll
    for (int i = 0; i < 4; i++)
        #pragma unroll
        for (int j = 0; j < 4; j++)
            atomicAdd(&g_attn[(size_t)bh*HD*HD + (tr+i)*HD + tc + j], acc[i][j]);
}

// ---------------- 6: softmax (with temperature) over e -------------------------
__global__ void k_softmax(const float* __restrict__ temp){
    int bh = blockIdx.x;
    float t = temp[bh & 3];
    float* row = g_attn + (size_t)bh * HD * HD + threadIdx.x * HD;
    float m = -1e30f;
    for (int e = 0; e < HD; e++) m = fmaxf(m, row[e] * t);
    float s = 0.f;
    for (int e = 0; e < HD; e++){ float v = expf(row[e]*t - m); row[e] = v; s += v; }
    float inv = 1.f / s;
    for (int e = 0; e < HD; e++) row[e] *= inv;
}

// ---------------- 7: attened = attn @ v  -> (B,C,N), fused global-avg-pool -----
__global__ void k_attn_v(){
    int bh = blockIdx.y;                 // 0..31
    int bb = bh >> 2, h = bh & 3;
    int n0 = blockIdx.x * 64;
    __shared__ float sAt[64][65];
    __shared__ float pool[64];
    int tid = threadIdx.x;
    #pragma unroll
    for (int i = 0; i < 16; i++){
        int idx = tid + i * 256;
        sAt[idx >> 6][idx & 63] = g_attn[(size_t)bh*HD*HD + idx];
    }
    if (tid < 64) pool[tid] = 0.f;
    __syncthreads();
    int nl = tid & 63;
    int dg = tid >> 6;                   // 0..3 (16 d's each)
    float acc[16] = {};
    const float* vb = g_v + (size_t)bh * HD * Nn + n0 + nl;
    for (int e = 0; e < 64; e++){
        float vv = vb[(size_t)e * Nn];
        #pragma unroll
        for (int j = 0; j < 16; j++) acc[j] += sAt[dg*16 + j][e] * vv;
    }
    float* dst = g_att + ((size_t)(bb*Cc + h*HD + dg*16)) * Nn + n0 + nl;
    #pragma unroll
    for (int j = 0; j < 16; j++){
        dst[(size_t)j * Nn] = acc[j];
        atomicAdd(&pool[dg*16 + j], acc[j]);
    }
    __syncthreads();
    if (tid < 64) atomicAdd(&g_pool[bb*Cc + h*HD + tid], pool[tid]);
}

// ---------------- 8: depthwise 3x3 conv + GELU on v (B,C,H,W) ------------------
__global__ void k_dwconv(const float* __restrict__ w, const float* __restrict__ bias){
    int bc = blockIdx.x;                 // b*C + c
    int c  = bc & (Cc-1);
    const float* plane = g_v + (size_t)bc * Nn;
    float wk[9];
    #pragma unroll
    for (int i = 0; i < 9; i++) wk[i] = w[c*9 + i];
    float bb = bias[c];
    for (int p = threadIdx.x; p < Nn; p += 256){
        int y = p >> 6, x = p & 63;
        float s = bb;
        #pragma unroll
        for (int dy = -1; dy <= 1; dy++){
            int yy = y + dy;
            if (yy < 0 || yy >= Hh) continue;
            #pragma unroll
            for (int dx = -1; dx <= 1; dx++){
                int xx = x + dx;
                if (xx < 0 || xx >= Ww) continue;
                s += plane[yy*Ww + xx] * wk[(dy+1)*3 + dx + 1];
            }
        }
        g_conv[(size_t)bc * Nn + p] = gelu_f(s);
    }
}

// ---------------- 9: channel interaction SE -> gc = sigmoid(map) ---------------
__global__ void k_channel_mlp(const float* __restrict__ w1, const float* __restrict__ b1,
                              const float* __restrict__ w2, const float* __restrict__ b2){
    int bb = blockIdx.x;
    int tid = threadIdx.x;
    __shared__ float sp[256];
    __shared__ float h1[32];
    sp[tid] = g_pool[bb*Cc + tid] * (1.f / Nn);
    __syncthreads();
    if (tid < 32){
        float a = b1[tid];
        for (int c = 0; c < 256; c++) a += sp[c] * w1[tid*256 + c];
        h1[tid] = gelu_f(a);
    }
    __syncthreads();
    float a = b2[tid];
    #pragma unroll
    for (int j = 0; j < 32; j++) a += h1[j] * w2[tid*32 + j];
    g_gc[bb*Cc + tid] = sigmoid_f(a);
}

// ---------------- 10: spatial interaction -> gs = sigmoid(map) -----------------
__global__ void k_spatial(const float* __restrict__ w1, const float* __restrict__ b1,
                          const float* __restrict__ w2, const float* __restrict__ b2){
    int bb = blockIdx.x >> 4;
    int n  = (blockIdx.x & 15) * 256 + threadIdx.x;
    __shared__ float sw1[16*256];
    for (int i = threadIdx.x; i < 16*256; i += 256) sw1[i] = w1[i];
    __syncthreads();
    float acc[16];
    #pragma unroll
    for (int o = 0; o < 16; o++) acc[o] = b1[o];
    const float* cb = g_conv + (size_t)bb * Cc * Nn + n;
    for (int c = 0; c < 256; c++){
        float x = cb[(size_t)c * Nn];
        #pragma unroll
        for (int o = 0; o < 16; o++) acc[o] += x * sw1[o*256 + c];
    }
    float sm = b2[0];
    #pragma unroll
    for (int o = 0; o < 16; o++) sm += gelu_f(acc[o]) * w2[o];
    g_gs[bb*Nn + n] = sigmoid_f(sm);
}

// ---------------- 11: fused gate + proj GEMM + bias + transpose out ------------
// A[bn][c] = att(B,C,N)*gs[bn] + conv(B,C,N)*gc[b][c];  out[b][o][n]
__global__ void k_proj_gemm(const float* __restrict__ w, const float* __restrict__ bias,
                            float* __restrict__ out){
    __shared__ float sA[16][64];
    __shared__ float sB[16][64];
    int row0 = blockIdx.y * 64;
    int col0 = blockIdx.x * 64;
    int bb = row0 >> 12;
    int n0 = row0 & (Nn-1);
    int tid = threadIdx.x;
    int tr = (tid >> 4) * 4;
    int tc = (tid & 15) * 4;
    float acc[4][4] = {};
    for (int k0 = 0; k0 < 256; k0 += 16){
        #pragma unroll
        for (int i = 0; i < 4; i++){
            int e = tid + i * 256;
            int cl = e >> 6, nl = e & 63;
            size_t off = ((size_t)(bb*Cc + k0 + cl))*Nn + n0 + nl;
            float a = g_att [off] * g_gs[bb*Nn + n0 + nl]
                    + g_conv[off] * g_gc[bb*Cc + k0 + cl];
            sA[cl][nl] = a;
            sB[cl][nl] = w[(size_t)(k0 + cl) * 256 + col0 + nl];
        }
        __syncthreads();
        #pragma unroll
        for (int kk = 0; kk < 16; kk++){
            float a[4], bv[4];
            #pragma unroll
            for (int i = 0; i < 4; i++) a[i]  = sA[kk][tr + i];
            #pragma unroll
            for (int j = 0; j < 4; j++) bv[j] = sB[kk][tc + j];
            #pragma unroll
            for (int i = 0; i < 4; i++)
                #pragma unroll
                for (int j = 0; j < 4; j++)
                    acc[i][j] += a[i] * bv[j];
        }
        __syncthreads();
    }
    #pragma unroll
    for (int j = 0; j < 4; j++){
        int o = col0 + tc + j;
        float bo = bias[o];
        float4 val = make_float4(acc[0][j]+bo, acc[1][j]+bo, acc[2][j]+bo, acc[3][j]+bo);
        *(float4*)&out[((size_t)(bb*Cc + o))*Nn + n0 + tr] = val;
    }
}

// =================================================================================
extern "C" void kernel_launch(void* const* d_in, const int* in_sizes, int n_in,
                              void* d_out, int out_size){
    const float* x     = (const float*)d_in[0];
    const float* ln_g  = (const float*)d_in[1];
    const float* ln_b  = (const float*)d_in[2];
    const float* w_qkv = (const float*)d_in[3];
    const float* w_q   = (const float*)d_in[4];
    const float* b_q   = (const float*)d_in[5];
    const float* temp  = (const float*)d_in[6];
    const float* dw_w  = (const float*)d_in[7];
    const float* dw_b  = (const float*)d_in[8];
    const float* ci_w1 = (const float*)d_in[9];
    const float* ci_b1 = (const float*)d_in[10];
    const float* ci_w2 = (const float*)d_in[11];
    const float* ci_b2 = (const float*)d_in[12];
    const float* si_w1 = (const float*)d_in[13];
    const float* si_b1 = (const float*)d_in[14];
    const float* si_w2 = (const float*)d_in[15];
    const float* si_b2 = (const float*)d_in[16];
    const float* pj_w  = (const float*)d_in[17];
    const float* pj_b  = (const float*)d_in[18];
    float* out = (float*)d_out;

    k_zero<<<512, 256>>>();
    k_layernorm<<<dim3(16, Bq), 256>>>(x, ln_g, ln_b);
    k_qkv_gemm<<<dim3(12, BN/64), 256>>>(w_qkv);
    k_qproj<<<Bq*NH*(Nn/32), 256>>>(w_q, b_q);
    k_l2norm<<<2*Bq*NH*HD, 256>>>();
    k_dwconv<<<Bq*Cc, 256>>>(dw_w, dw_b);
    k_attn_qk<<<dim3(8, Bq*NH), 256>>>();
    k_softmax<<<Bq*NH, 64>>>(temp);
    k_attn_v<<<dim3(Nn/64, Bq*NH), 256>>>();
    k_spatial<<<Bq*16, 256>>>(si_w1, si_b1, si_w2, si_b2);
    k_channel_mlp<<<Bq, 256>>>(ci_w1, ci_b1, ci_w2, ci_b2);
    k_proj_gemm<<<dim3(4, BN/64), 256>>>(pj_w, pj_b, out);
}

// round 3
// speedup vs baseline: 1.1889x; 1.1889x over previous
#include <cuda_runtime.h>
#include <math.h>

// Problem constants
#define Bq   8
#define Cc   256
#define Hh   64
#define Ww   64
#define Nn   4096            // H*W
#define NH   4
#define HD   64
#define BN   (Bq*Nn)         // 32768

// ---------------- scratch (device globals; no allocation allowed) -------------
__device__ float g_xnT [Bq*Cc*Nn];     // layernormed x, (B,C,N)
__device__ float g_wB  [Cc*768];       // folded qkv weight: q part = w_qkv[:, :256] @ blockdiag(w_q)
__device__ float g_q   [Bq*NH*HD*Nn];  // (B,nh,hd,N)
__device__ float g_k   [Bq*NH*HD*Nn];
__device__ float g_v   [Bq*NH*HD*Nn];  // == (B,C,N) head-major
__device__ float g_att [Bq*Cc*Nn];     // attened_x stored (B,C,N)
__device__ float g_conv[Bq*Cc*Nn];     // gelu(dwconv), (B,C,N)
__device__ float g_attn[Bq*NH*HD*HD];  // (B,nh,hd,hd)
__device__ float g_pool[Bq*Cc];        // sum over n of attened
__device__ float g_gc  [Bq*Cc];        // sigmoid(channel_map)
__device__ float g_gs  [Bq*Nn];        // sigmoid(spatial_map)

__device__ __forceinline__ float gelu_f(float x){
    return 0.5f * x * (1.0f + erff(x * 0.70710678118654752f));
}
__device__ __forceinline__ float sigmoid_f(float x){
    return 1.0f / (1.0f + expf(-x));
}

// ---------------- 0: zero the accumulated buffers -----------------------------
__global__ void k_zero(){
    int i = blockIdx.x * 256 + threadIdx.x;
    if (i < Bq*NH*HD*HD) g_attn[i] = 0.f;
    if (i < Bq*Cc)       g_pool[i] = 0.f;
}

// ---------------- 1: LayerNorm over C, x(B,C,N) -> xnT(B,C,N) -----------------
__global__ void k_layernorm(const float* __restrict__ x,
                            const float* __restrict__ g,
                            const float* __restrict__ b){
    int bb = blockIdx.y;
    int n  = blockIdx.x * 256 + threadIdx.x;
    const float* xb = x + (size_t)bb * Cc * Nn;
    float s = 0.f, s2 = 0.f;
    #pragma unroll 8
    for (int c = 0; c < Cc; c++){
        float v = xb[(size_t)c * Nn + n];
        s += v; s2 += v * v;
    }
    float mu  = s * (1.f/Cc);
    float var = s2 * (1.f/Cc) - mu * mu;
    float inv = rsqrtf(var + 1e-5f);
    float* ob = g_xnT + (size_t)bb * Cc * Nn;
    #pragma unroll 8
    for (int c = 0; c < Cc; c++){
        float v = xb[(size_t)c * Nn + n];
        ob[(size_t)c * Nn + n] = (v - mu) * inv * g[c] + b[c];
    }
}

// ---------------- 1b: fold w_q into w_qkv q-columns -> g_wB --------------------
__global__ void k_buildW(const float* __restrict__ wqkv, const float* __restrict__ wq){
    __shared__ float srow[768];
    __shared__ float swq[64*64];
    int c = blockIdx.x;
    int tid = threadIdx.x;
    for (int i = tid; i < 768; i += 256)  srow[i] = wqkv[(size_t)c*768 + i];
    for (int i = tid; i < 4096; i += 256) swq[i]  = wq[i];
    __syncthreads();
    int h = tid >> 6, d = tid & 63;
    float s = 0.f;
    #pragma unroll 16
    for (int e = 0; e < 64; e++) s += srow[h*64 + e] * swq[e*64 + d];
    g_wB[(size_t)c*768 + tid]       = s;
    g_wB[(size_t)c*768 + 256 + tid] = srow[256 + tid];
    g_wB[(size_t)c*768 + 512 + tid] = srow[512 + tid];
}

// ---------------- 2: qkv GEMM  (BN x 256) @ (256 x 768) -----------------------
// 128x128x8 tiles, double-buffered smem, 8x8 micro-tiles.
// A = xnT (k-major: [c][n]), B = g_wB ([c][o]). Epilogue scatters q(+bias)/k/v
// into (B, nh, hd, N).
__global__ void __launch_bounds__(256) k_qkv_gemm(const float* __restrict__ bq){
    __shared__ float sA[2][8][128];
    __shared__ float sB[2][8][128];
    int m0   = blockIdx.y * 128;         // bn
    int col0 = blockIdx.x * 128;         // o
    int bb = m0 >> 12;
    int n0 = m0 & (Nn-1);
    int tid = threadIdx.x;
    int lr  = tid >> 5;                  // 0..7   (k row within tile)
    int lc4 = (tid & 31) * 4;            // 0..124 (col within tile)
    int ty = tid >> 4, tx = tid & 15;

    const float* Abase = g_xnT + (size_t)(bb*Cc) * Nn + n0;
    const float* Bbase = g_wB + col0;

    float acc[8][8] = {};
    // preload tile 0
    {
        float4 ra = *(const float4*)&Abase[(size_t)lr * Nn + lc4];
        float4 rb = *(const float4*)&Bbase[(size_t)lr * 768 + lc4];
        *(float4*)&sA[0][lr][lc4] = ra;
        *(float4*)&sB[0][lr][lc4] = rb;
    }
    __syncthreads();

    #pragma unroll 1
    for (int kt = 0; kt < 32; kt++){
        int buf = kt & 1;
        float4 ra, rb;
        if (kt < 31){
            ra = *(const float4*)&Abase[(size_t)((kt+1)*8 + lr) * Nn + lc4];
            rb = *(const float4*)&Bbase[(size_t)((kt+1)*8 + lr) * 768 + lc4];
        }
        #pragma unroll
        for (int kk = 0; kk < 8; kk++){
            float a[8], bv[8];
            *(float4*)(a)    = *(const float4*)&sA[buf][kk][ty*8];
            *(float4*)(a+4)  = *(const float4*)&sA[buf][kk][ty*8 + 4];
            *(float4*)(bv)   = *(const float4*)&sB[buf][kk][tx*8];
            *(float4*)(bv+4) = *(const float4*)&sB[buf][kk][tx*8 + 4];
            #pragma unroll
            for (int i = 0; i < 8; i++)
                #pragma unroll
                for (int j = 0; j < 8; j++)
                    acc[i][j] += a[i] * bv[j];
        }
        if (kt < 31){
            *(float4*)&sA[buf^1][lr][lc4] = ra;
            *(float4*)&sB[buf^1][lr][lc4] = rb;
        }
        __syncthreads();
    }

    // Epilogue: col0 in {0,128}->q, {256,384}->k, {512,640}->v (constant/block)
    int which = col0 >> 8;
    float* arr = (which == 0) ? g_q : (which == 1) ? g_k : g_v;
    int nrow = n0 + ty * 8;
    #pragma unroll
    for (int j = 0; j < 8; j++){
        int o = col0 + tx*8 + j;
        float bo = (which == 0) ? bq[o & 63] : 0.f;
        float* dst = arr + ((size_t)(bb*Cc) + (o & 255)) * Nn + nrow;
        *(float4*)&dst[0] = make_float4(acc[0][j]+bo, acc[1][j]+bo, acc[2][j]+bo, acc[3][j]+bo);
        *(float4*)&dst[4] = make_float4(acc[4][j]+bo, acc[5][j]+bo, acc[6][j]+bo, acc[7][j]+bo);
    }
}

// ---------------- 4: L2 normalize q and k rows over N --------------------------
__global__ void k_l2norm(){
    int r = blockIdx.x;                  // 0..4095; <2048 q, else k
    float* ptr = (r < Bq*NH*HD) ? g_q + (size_t)r * Nn
                                : g_k + (size_t)(r - Bq*NH*HD) * Nn;
    __shared__ float red[256];
    float s = 0.f;
    for (int i = threadIdx.x; i < Nn; i += 256){ float v = ptr[i]; s += v*v; }
    red[threadIdx.x] = s;
    __syncthreads();
    for (int off = 128; off > 0; off >>= 1){
        if (threadIdx.x < off) red[threadIdx.x] += red[threadIdx.x + off];
        __syncthreads();
    }
    float inv = 1.f / fmaxf(sqrtf(red[0]), 1e-12f);
    for (int i = threadIdx.x; i < Nn; i += 256) ptr[i] *= inv;
}

// ---------------- 5: attn partial: q @ k^T over n-chunks (atomic accumulate) ---
__global__ void k_attn_qk(){
    int bh = blockIdx.y;                 // 0..31
    int n0 = blockIdx.x * 512;
    __shared__ float sQ[64][65];
    __shared__ float sK[64][65];
    int tid = threadIdx.x;
    int tr = (tid >> 4) * 4;
    int tc = (tid & 15) * 4;
    float acc[4][4] = {};
    const float* qb = g_q + (size_t)bh * HD * Nn;
    const float* kb = g_k + (size_t)bh * HD * Nn;
    for (int s = 0; s < 8; s++){
        int nn = n0 + s * 64;
        #pragma unroll
        for (int i = 0; i < 16; i++){
            int idx = tid + i * 256;
            int dl = idx >> 6, nl = idx & 63;
            sQ[dl][nl] = qb[(size_t)dl * Nn + nn + nl];
            sK[dl][nl] = kb[(size_t)dl * Nn + nn + nl];
        }
        __syncthreads();
        #pragma unroll 8
        for (int kk = 0; kk < 64; kk++){
            float a[4], bv[4];
            #pragma unroll
            for (int i = 0; i < 4; i++) a[i]  = sQ[tr + i][kk];
            #pragma unroll
            for (int j = 0; j < 4; j++) bv[j] = sK[tc + j][kk];
            #pragma unroll
            for (int i = 0; i < 4; i++)
                #pragma unroll
                for (int j = 0; j < 4; j++)
                    acc[i][j] += a[i] * bv[j];
        }
        __syncthreads();
    }
    #pragma unroll
    for (int i = 0; i < 4; i++)
        #pragma unroll
        for (int j = 0; j < 4; j++)
            atomicAdd(&g_attn[(size_t)bh*HD*HD + (tr+i)*HD + tc + j], acc[i][j]);
}

// ---------------- 6: softmax (with temperature) over e -------------------------
__global__ void k_softmax(const float* __restrict__ temp){
    int bh = blockIdx.x;
    float t = temp[bh & 3];
    float* row = g_attn + (size_t)bh * HD * HD + threadIdx.x * HD;
    float m = -1e30f;
    for (int e = 0; e < HD; e++) m = fmaxf(m, row[e] * t);
    float s = 0.f;
    for (int e = 0; e < HD; e++){ float v = expf(row[e]*t - m); row[e] = v; s += v; }
    float inv = 1.f / s;
    for (int e = 0; e < HD; e++) row[e] *= inv;
}

// ---------------- 7: attened = attn @ v  -> (B,C,N), fused global-avg-pool -----
__global__ void k_attn_v(){
    int bh = blockIdx.y;                 // 0..31
    int bb = bh >> 2, h = bh & 3;
    int n0 = blockIdx.x * 64;
    __shared__ float sAt[64][65];
    __shared__ float pool[64];
    int tid = threadIdx.x;
    #pragma unroll
    for (int i = 0; i < 16; i++){
        int idx = tid + i * 256;
        sAt[idx >> 6][idx & 63] = g_attn[(size_t)bh*HD*HD + idx];
    }
    if (tid < 64) pool[tid] = 0.f;
    __syncthreads();
    int nl = tid & 63;
    int dg = tid >> 6;                   // 0..3 (16 d's each)
    float acc[16] = {};
    const float* vb = g_v + (size_t)bh * HD * Nn + n0 + nl;
    for (int e = 0; e < 64; e++){
        float vv = vb[(size_t)e * Nn];
        #pragma unroll
        for (int j = 0; j < 16; j++) acc[j] += sAt[dg*16 + j][e] * vv;
    }
    float* dst = g_att + ((size_t)(bb*Cc + h*HD + dg*16)) * Nn + n0 + nl;
    #pragma unroll
    for (int j = 0; j < 16; j++){
        dst[(size_t)j * Nn] = acc[j];
        atomicAdd(&pool[dg*16 + j], acc[j]);
    }
    __syncthreads();
    if (tid < 64) atomicAdd(&g_pool[bb*Cc + h*HD + tid], pool[tid]);
}

// ---------------- 8: depthwise 3x3 conv + GELU on v (B,C,H,W) ------------------
__global__ void k_dwconv(const float* __restrict__ w, const float* __restrict__ bias){
    int bc = blockIdx.x;                 // b*C + c
    int c  = bc & (Cc-1);
    const float* plane = g_v + (size_t)bc * Nn;
    float wk[9];
    #pragma unroll
    for (int i = 0; i < 9; i++) wk[i] = w[c*9 + i];
    float bb = bias[c];
    for (int p = threadIdx.x; p < Nn; p += 256){
        int y = p >> 6, x = p & 63;
        float s = bb;
        #pragma unroll
        for (int dy = -1; dy <= 1; dy++){
            int yy = y + dy;
            if (yy < 0 || yy >= Hh) continue;
            #pragma unroll
            for (int dx = -1; dx <= 1; dx++){
                int xx = x + dx;
                if (xx < 0 || xx >= Ww) continue;
                s += plane[yy*Ww + xx] * wk[(dy+1)*3 + dx + 1];
            }
        }
        g_conv[(size_t)bc * Nn + p] = gelu_f(s);
    }
}

// ---------------- 9: channel interaction SE -> gc = sigmoid(map) ---------------
__global__ void k_channel_mlp(const float* __restrict__ w1, const float* __restrict__ b1,
                              const float* __restrict__ w2, const float* __restrict__ b2){
    int bb = blockIdx.x;
    int tid = threadIdx.x;
    __shared__ float sp[256];
    __shared__ float h1[32];
    sp[tid] = g_pool[bb*Cc + tid] * (1.f / Nn);
    __syncthreads();
    if (tid < 32){
        float a = b1[tid];
        for (int c = 0; c < 256; c++) a += sp[c] * w1[tid*256 + c];
        h1[tid] = gelu_f(a);
    }
    __syncthreads();
    float a = b2[tid];
    #pragma unroll
    for (int j = 0; j < 32; j++) a += h1[j] * w2[tid*32 + j];
    g_gc[bb*Cc + tid] = sigmoid_f(a);
}

// ---------------- 10: spatial interaction -> gs = sigmoid(map) -----------------
__global__ void k_spatial(const float* __restrict__ w1, const float* __restrict__ b1,
                          const float* __restrict__ w2, const float* __restrict__ b2){
    int bb = blockIdx.x >> 4;
    int n  = (blockIdx.x & 15) * 256 + threadIdx.x;
    __shared__ float sw1[16*256];
    for (int i = threadIdx.x; i < 16*256; i += 256) sw1[i] = w1[i];
    __syncthreads();
    float acc[16];
    #pragma unroll
    for (int o = 0; o < 16; o++) acc[o] = b1[o];
    const float* cb = g_conv + (size_t)bb * Cc * Nn + n;
    for (int c = 0; c < 256; c++){
        float x = cb[(size_t)c * Nn];
        #pragma unroll
        for (int o = 0; o < 16; o++) acc[o] += x * sw1[o*256 + c];
    }
    float sm = b2[0];
    #pragma unroll
    for (int o = 0; o < 16; o++) sm += gelu_f(acc[o]) * w2[o];
    g_gs[bb*Nn + n] = sigmoid_f(sm);
}

// ---------------- 11: fused gate + proj GEMM + bias + transpose out ------------
// A[c][n] = att*gs[n] + conv*gc[c]; 128x128x8 double-buffered.
__global__ void __launch_bounds__(256) k_proj_gemm(const float* __restrict__ w,
                                                   const float* __restrict__ bias,
                                                   float* __restrict__ out){
    __shared__ float sA[2][8][128];
    __shared__ float sB[2][8][128];
    int m0   = blockIdx.y * 128;
    int col0 = blockIdx.x * 128;
    int bb = m0 >> 12;
    int n0 = m0 & (Nn-1);
    int tid = threadIdx.x;
    int lr  = tid >> 5;
    int lc4 = (tid & 31) * 4;
    int ty = tid >> 4, tx = tid & 15;

    const float* At = g_att  + (size_t)(bb*Cc) * Nn + n0;
    const float* Cv = g_conv + (size_t)(bb*Cc) * Nn + n0;
    const float* Bbase = w + col0;
    float4 gs4 = *(const float4*)&g_gs[bb*Nn + n0 + lc4];

    float acc[8][8] = {};
    {
        float4 a  = *(const float4*)&At[(size_t)lr * Nn + lc4];
        float4 cv = *(const float4*)&Cv[(size_t)lr * Nn + lc4];
        float  gc = g_gc[bb*Cc + lr];
        float4 ra = make_float4(a.x*gs4.x + cv.x*gc, a.y*gs4.y + cv.y*gc,
                                a.z*gs4.z + cv.z*gc, a.w*gs4.w + cv.w*gc);
        float4 rb = *(const float4*)&Bbase[(size_t)lr * 256 + lc4];
        *(float4*)&sA[0][lr][lc4] = ra;
        *(float4*)&sB[0][lr][lc4] = rb;
    }
    __syncthreads();

    #pragma unroll 1
    for (int kt = 0; kt < 32; kt++){
        int buf = kt & 1;
        float4 ra, rb;
        if (kt < 31){
            int kr = (kt+1)*8 + lr;
            float4 a  = *(const float4*)&At[(size_t)kr * Nn + lc4];
            float4 cv = *(const float4*)&Cv[(size_t)kr * Nn + lc4];
            float  gc = g_gc[bb*Cc + kr];
            ra = make_float4(a.x*gs4.x + cv.x*gc, a.y*gs4.y + cv.y*gc,
                             a.z*gs4.z + cv.z*gc, a.w*gs4.w + cv.w*gc);
            rb = *(const float4*)&Bbase[(size_t)kr * 256 + lc4];
        }
        #pragma unroll
        for (int kk = 0; kk < 8; kk++){
            float a[8], bv[8];
            *(float4*)(a)    = *(const float4*)&sA[buf][kk][ty*8];
            *(float4*)(a+4)  = *(const float4*)&sA[buf][kk][ty*8 + 4];
            *(float4*)(bv)   = *(const float4*)&sB[buf][kk][tx*8];
            *(float4*)(bv+4) = *(const float4*)&sB[buf][kk][tx*8 + 4];
            #pragma unroll
            for (int i = 0; i < 8; i++)
                #pragma unroll
                for (int j = 0; j < 8; j++)
                    acc[i][j] += a[i] * bv[j];
        }
        if (kt < 31){
            *(float4*)&sA[buf^1][lr][lc4] = ra;
            *(float4*)&sB[buf^1][lr][lc4] = rb;
        }
        __syncthreads();
    }

    int nrow = n0 + ty * 8;
    #pragma unroll
    for (int j = 0; j < 8; j++){
        int o = col0 + tx*8 + j;
        float bo = bias[o];
        float* dst = out + ((size_t)(bb*Cc) + o) * Nn + nrow;
        *(float4*)&dst[0] = make_float4(acc[0][j]+bo, acc[1][j]+bo, acc[2][j]+bo, acc[3][j]+bo);
        *(float4*)&dst[4] = make_float4(acc[4][j]+bo, acc[5][j]+bo, acc[6][j]+bo, acc[7][j]+bo);
    }
}

// =================================================================================
extern "C" void kernel_launch(void* const* d_in, const int* in_sizes, int n_in,
                              void* d_out, int out_size){
    const float* x     = (const float*)d_in[0];
    const float* ln_g  = (const float*)d_in[1];
    const float* ln_b  = (const float*)d_in[2];
    const float* w_qkv = (const float*)d_in[3];
    const float* w_q   = (const float*)d_in[4];
    const float* b_q   = (const float*)d_in[5];
    const float* temp  = (const float*)d_in[6];
    const float* dw_w  = (const float*)d_in[7];
    const float* dw_b  = (const float*)d_in[8];
    const float* ci_w1 = (const float*)d_in[9];
    const float* ci_b1 = (const float*)d_in[10];
    const float* ci_w2 = (const float*)d_in[11];
    const float* ci_b2 = (const float*)d_in[12];
    const float* si_w1 = (const float*)d_in[13];
    const float* si_b1 = (const float*)d_in[14];
    const float* si_w2 = (const float*)d_in[15];
    const float* si_b2 = (const float*)d_in[16];
    const float* pj_w  = (const float*)d_in[17];
    const float* pj_b  = (const float*)d_in[18];
    float* out = (float*)d_out;

    k_zero<<<512, 256>>>();
    k_layernorm<<<dim3(16, Bq), 256>>>(x, ln_g, ln_b);
    k_buildW<<<Cc, 256>>>(w_qkv, w_q);
    k_qkv_gemm<<<dim3(6, BN/128), 256>>>(b_q);
    k_l2norm<<<2*Bq*NH*HD, 256>>>();
    k_attn_qk<<<dim3(8, Bq*NH), 256>>>();
    k_softmax<<<Bq*NH, 64>>>(temp);
    k_attn_v<<<dim3(Nn/64, Bq*NH), 256>>>();
    k_dwconv<<<Bq*Cc, 256>>>(dw_w, dw_b);
    k_spatial<<<Bq*16, 256>>>(si_w1, si_b1, si_w2, si_b2);
    k_channel_mlp<<<Bq, 256>>>(ci_w1, ci_b1, ci_w2, ci_b2);
    k_proj_gemm<<<dim3(2, BN/128), 256>>>(pj_w, pj_b, out);
}

// round 5
// speedup vs baseline: 1.4500x; 1.2196x over previous
#include <cuda_runtime.h>
#include <cuda_bf16.h>
#include <math.h>
#include <stdint.h>

// Problem constants
#define Bq   8
#define Cc   256
#define Hh   64
#define Ww   64
#define Nn   4096            // H*W
#define NH   4
#define HD   64
#define BN   (Bq*Nn)         // 32768

// ---------------- scratch (device globals; no allocation allowed) -------------
__device__ __nv_bfloat16 g_xn_hi[BN*Cc];   // layernormed x, [b*N + n][c], bf16 hi
__device__ __nv_bfloat16 g_xn_lo[BN*Cc];   // bf16 lo residual
__device__ __nv_bfloat16 g_wB_hi[768*Cc];  // folded qkv weight, [o][c] bf16 hi
__device__ __nv_bfloat16 g_wB_lo[768*Cc];
__device__ float g_q   [Bq*NH*HD*Nn];  // (B,nh,hd,N)
__device__ float g_k   [Bq*NH*HD*Nn];
__device__ float g_v   [Bq*NH*HD*Nn];  // == (B,C,N) head-major
__device__ float g_att [Bq*Cc*Nn];     // attened_x stored (B,C,N)
__device__ float g_conv[Bq*Cc*Nn];     // gelu(dwconv), (B,C,N)
__device__ float g_attn[Bq*NH*HD*HD];  // (B,nh,hd,hd)
__device__ float g_pool[Bq*Cc];        // sum over n of attened
__device__ float g_gc  [Bq*Cc];        // sigmoid(channel_map)
__device__ float g_gs  [Bq*Nn];        // sigmoid(spatial_map)
__device__ float g_invq[Bq*NH*HD];     // 1/||q_row||
__device__ float g_invk[Bq*NH*HD];

__device__ __forceinline__ float gelu_f(float x){
    return 0.5f * x * (1.0f + erff(x * 0.70710678118654752f));
}
__device__ __forceinline__ float sigmoid_f(float x){
    return 1.0f / (1.0f + expf(-x));
}

__device__ __forceinline__ uint32_t smem_u32(const void* p){
    uint32_t a;
    asm("{ .reg .u64 t; cvta.to.shared.u64 t, %1; cvt.u32.u64 %0, t; }" : "=r"(a) : "l"(p));
    return a;
}
__device__ __forceinline__ void ldmx4(uint32_t* r, uint32_t addr){
    asm volatile("ldmatrix.sync.aligned.m8n8.x4.shared.b16 {%0,%1,%2,%3}, [%4];"
                 : "=r"(r[0]), "=r"(r[1]), "=r"(r[2]), "=r"(r[3]) : "r"(addr));
}
__device__ __forceinline__ void mma_bf16(float* d, const uint32_t* a, uint32_t b0, uint32_t b1){
    asm volatile(
        "mma.sync.aligned.m16n8k16.row.col.f32.bf16.bf16.f32 "
        "{%0,%1,%2,%3}, {%4,%5,%6,%7}, {%8,%9}, {%0,%1,%2,%3};"
        : "+f"(d[0]), "+f"(d[1]), "+f"(d[2]), "+f"(d[3])
        : "r"(a[0]), "r"(a[1]), "r"(a[2]), "r"(a[3]), "r"(b0), "r"(b1));
}

// qkv mma smem layout: 4 tiles of 128 rows x 72 bf16 (144B stride) = 18KB each
#define T_STRIDE 144
#define OFF_AH 0
#define OFF_AL 18432
#define OFF_BH 36864
#define OFF_BL 55296
#define QKV_SMEM 73728

// ---------------- 0: zero the accumulated buffers -----------------------------
__global__ void k_zero(){
    int i = blockIdx.x * 256 + threadIdx.x;
    if (i < Bq*NH*HD*HD) g_attn[i] = 0.f;
    if (i < Bq*Cc)       g_pool[i] = 0.f;
}

// ---------------- 1: LayerNorm over C -> g_xn_hi/lo bf16, layout [b*N+n][c] ----
__global__ void k_layernorm(const float* __restrict__ x,
                            const float* __restrict__ g,
                            const float* __restrict__ b){
    __shared__ float sx[256][33];
    __shared__ float spart[8][32];
    __shared__ float smu[32], sinv[32];
    int bb = blockIdx.x >> 7;
    int n0 = (blockIdx.x & 127) * 32;
    int tid = threadIdx.x;
    int nl = tid & 31, part = tid >> 5;
    const float* xb = x + (size_t)bb * Cc * Nn + n0;
    #pragma unroll
    for (int c0 = 0; c0 < 256; c0 += 8)
        sx[c0 + part][nl] = xb[(size_t)(c0 + part) * Nn + nl];
    __syncthreads();
    float s = 0.f, s2 = 0.f;
    #pragma unroll
    for (int i = 0; i < 32; i++){ float v = sx[part*32 + i][nl]; s += v; s2 += v*v; }
    spart[part][nl] = s;
    __syncthreads();
    if (part == 0){ float t = 0.f; for (int p = 0; p < 8; p++) t += spart[p][nl]; smu[nl] = t * (1.f/256.f); }
    __syncthreads();
    spart[part][nl] = s2;
    __syncthreads();
    if (part == 0){
        float t = 0.f; for (int p = 0; p < 8; p++) t += spart[p][nl];
        float mu = smu[nl];
        sinv[nl] = rsqrtf(t * (1.f/256.f) - mu*mu + 1e-5f);
    }
    __syncthreads();
    float gc = g[tid], bc = b[tid];
    for (int n = 0; n < 32; n++){
        float val = (sx[tid][n] - smu[n]) * sinv[n] * gc + bc;
        __nv_bfloat16 hi = __float2bfloat16(val);
        __nv_bfloat16 lo = __float2bfloat16(val - __bfloat162float(hi));
        size_t o = ((size_t)(bb * Nn) + n0 + n) * 256 + tid;
        g_xn_hi[o] = hi;
        g_xn_lo[o] = lo;
    }
}

// ---------------- 1b: fold w_q into qkv weight -> g_wB_hi/lo [o][c] bf16 -------
__global__ void k_buildW(const float* __restrict__ wqkv, const float* __restrict__ wq){
    __shared__ float srow[768];
    __shared__ float swq[64*64];
    int c = blockIdx.x;
    int tid = threadIdx.x;
    for (int i = tid; i < 768; i += 256)  srow[i] = wqkv[(size_t)c*768 + i];
    for (int i = tid; i < 4096; i += 256) swq[i]  = wq[i];
    __syncthreads();
    int h = tid >> 6, d = tid & 63;
    float s = 0.f;
    #pragma unroll 16
    for (int e = 0; e < 64; e++) s += srow[h*64 + e] * swq[e*64 + d];
    float vals[3] = { s, srow[256 + tid], srow[512 + tid] };
    #pragma unroll
    for (int t = 0; t < 3; t++){
        int o = t*256 + tid;
        __nv_bfloat16 hi = __float2bfloat16(vals[t]);
        __nv_bfloat16 lo = __float2bfloat16(vals[t] - __bfloat162float(hi));
        g_wB_hi[(size_t)o*256 + c] = hi;
        g_wB_lo[(size_t)o*256 + c] = lo;
    }
}

// ---------------- 2: qkv GEMM via mma.sync bf16x3 ------------------------------
// gemm-M = 768 channels (A = g_wB [o][c]), gemm-N = 32768 bn (B = g_xn [bn][c]).
// Block tile 128(ch) x 128(bn) x K256. 8 warps, warp tile 64x32.
// Epilogue: float2 stores into g_q(+bias)/g_k/g_v (B,nh,hd,N).
__global__ void __launch_bounds__(256) k_qkv_mma(const float* __restrict__ bq){
    extern __shared__ char dsm[];
    uint32_t sb = smem_u32(dsm);
    int tid = threadIdx.x, wid = tid >> 5, lid = tid & 31;
    int warp_m = wid >> 2, warp_n = wid & 3;
    int cblk = blockIdx.x * 128;
    int bn0  = blockIdx.y * 128;
    int bb = bn0 >> 12, n0 = bn0 & (Nn-1);

    // per-lane ldmatrix address components
    uint32_t a_row  = (uint32_t)(warp_m*64 + (lid & 7) + ((lid >> 3) & 1) * 8);
    uint32_t a_colb = (uint32_t)(((lid >> 4) & 1) * 16);
    uint32_t b_row  = (uint32_t)(warp_n*32 + (lid & 7) + ((lid >> 4) & 1) * 8);
    uint32_t b_colb = (uint32_t)(((lid >> 3) & 1) * 16);
    uint32_t aA = sb + a_row * T_STRIDE + a_colb;
    uint32_t aB = sb + b_row * T_STRIDE + b_colb;

    // global load pointers (row = tid>>1, 64B half = tid&1)
    int gr = tid >> 1, ghf = tid & 1;
    const char* pwh = (const char*)(g_wB_hi + (size_t)(cblk + gr)*256 + ghf*32);
    const char* pwl = (const char*)(g_wB_lo + (size_t)(cblk + gr)*256 + ghf*32);
    const char* pxh = (const char*)(g_xn_hi + (size_t)(bn0  + gr)*256 + ghf*32);
    const char* pxl = (const char*)(g_xn_lo + (size_t)(bn0  + gr)*256 + ghf*32);
    char* dst = dsm + gr * T_STRIDE + ghf * 64;

    float acc[4][4][4] = {};

    #pragma unroll 1
    for (int kc = 0; kc < 4; kc++){
        // stage 64-k chunk: 4 tiles of 128 x 64 bf16
        {
            size_t go = (size_t)kc * 128;   // 64 bf16 = 128 bytes
            #pragma unroll
            for (int j = 0; j < 4; j++){
                *(uint4*)(dst + OFF_AH + j*16) = *(const uint4*)(pwh + go + j*16);
                *(uint4*)(dst + OFF_AL + j*16) = *(const uint4*)(pwl + go + j*16);
                *(uint4*)(dst + OFF_BH + j*16) = *(const uint4*)(pxh + go + j*16);
                *(uint4*)(dst + OFF_BL + j*16) = *(const uint4*)(pxl + go + j*16);
            }
        }
        __syncthreads();

        #pragma unroll
        for (int ks = 0; ks < 4; ks++){
            uint32_t kofs = (uint32_t)(ks * 32);
            uint32_t bh[8], bl[8], ar[4];
            ldmx4(bh,     aB + OFF_BH + kofs);
            ldmx4(bh + 4, aB + OFF_BH + kofs + 16*T_STRIDE);
            ldmx4(bl,     aB + OFF_BL + kofs);
            ldmx4(bl + 4, aB + OFF_BL + kofs + 16*T_STRIDE);
            #pragma unroll
            for (int mi = 0; mi < 4; mi++){
                ldmx4(ar, aA + OFF_AH + kofs + (uint32_t)(mi*16)*T_STRIDE);
                #pragma unroll
                for (int ni = 0; ni < 4; ni++){
                    const uint32_t* bf = ((ni & 1) ? ((ni>>1) ? bh+6 : bh+2)
                                                   : ((ni>>1) ? bh+4 : bh));
                    mma_bf16(acc[mi][ni], ar, bf[0], bf[1]);
                }
                #pragma unroll
                for (int ni = 0; ni < 4; ni++){
                    const uint32_t* bf = ((ni & 1) ? ((ni>>1) ? bl+6 : bl+2)
                                                   : ((ni>>1) ? bl+4 : bl));
                    mma_bf16(acc[mi][ni], ar, bf[0], bf[1]);
                }
                ldmx4(ar, aA + OFF_AL + kofs + (uint32_t)(mi*16)*T_STRIDE);
                #pragma unroll
                for (int ni = 0; ni < 4; ni++){
                    const uint32_t* bf = ((ni & 1) ? ((ni>>1) ? bh+6 : bh+2)
                                                   : ((ni>>1) ? bh+4 : bh));
                    mma_bf16(acc[mi][ni], ar, bf[0], bf[1]);
                }
            }
        }
        __syncthreads();
    }

    // epilogue
    int gid = lid >> 2, q4 = lid & 3;
    int obase = cblk + warp_m*64 + gid;
    int ot = obase >> 8;                 // 0=q,1=k,2=v (constant per block)
    float* arr = (ot == 0) ? g_q : (ot == 1) ? g_k : g_v;
    #pragma unroll
    for (int mi = 0; mi < 4; mi++){
        int o0 = obase + mi*16;
        float bo0 = (ot == 0) ? bq[o0 & 63] : 0.f;
        float bo1 = (ot == 0) ? bq[(o0 + 8) & 63] : 0.f;
        float* r0 = arr + ((size_t)(bb*Cc + (o0 & 255))) * Nn;
        float* r1 = arr + ((size_t)(bb*Cc + ((o0 + 8) & 255))) * Nn;
        #pragma unroll
        for (int ni = 0; ni < 4; ni++){
            int n = n0 + warp_n*32 + ni*8 + q4*2;
            *(float2*)&r0[n] = make_float2(acc[mi][ni][0] + bo0, acc[mi][ni][1] + bo0);
            *(float2*)&r1[n] = make_float2(acc[mi][ni][2] + bo1, acc[mi][ni][3] + bo1);
        }
    }
}

// ---------------- 4: row norms of q and k (read-only) --------------------------
__global__ void k_norms(){
    int r = blockIdx.x;                  // 0..4095; <2048 q, else k
    const float* ptr = (r < Bq*NH*HD) ? g_q + (size_t)r * Nn
                                      : g_k + (size_t)(r - Bq*NH*HD) * Nn;
    __shared__ float red[256];
    float s = 0.f;
    for (int i = threadIdx.x; i < Nn; i += 256){ float v = ptr[i]; s += v*v; }
    red[threadIdx.x] = s;
    __syncthreads();
    for (int off = 128; off > 0; off >>= 1){
        if (threadIdx.x < off) red[threadIdx.x] += red[threadIdx.x + off];
        __syncthreads();
    }
    if (threadIdx.x == 0){
        float inv = 1.f / fmaxf(sqrtf(red[0]), 1e-12f);
        if (r < Bq*NH*HD) g_invq[r] = inv;
        else              g_invk[r - Bq*NH*HD] = inv;
    }
}

// ---------------- 5: attn partial: q @ k^T over n-chunks (atomic accumulate) ---
__global__ void k_attn_qk(){
    int bh = blockIdx.y;
    int n0 = blockIdx.x * 512;
    __shared__ float sQ[64][65];
    __shared__ float sK[64][65];
    int tid = threadIdx.x;
    int tr = (tid >> 4) * 4;
    int tc = (tid & 15) * 4;
    float acc[4][4] = {};
    const float* qb = g_q + (size_t)bh * HD * Nn;
    const float* kb = g_k + (size_t)bh * HD * Nn;
    for (int s = 0; s < 8; s++){
        int nn = n0 + s * 64;
        #pragma unroll
        for (int i = 0; i < 16; i++){
            int idx = tid + i * 256;
            int dl = idx >> 6, nl = idx & 63;
            sQ[dl][nl] = qb[(size_t)dl * Nn + nn + nl];
            sK[dl][nl] = kb[(size_t)dl * Nn + nn + nl];
        }
        __syncthreads();
        #pragma unroll 8
        for (int kk = 0; kk < 64; kk++){
            float a[4], bv[4];
            #pragma unroll
            for (int i = 0; i < 4; i++) a[i]  = sQ[tr + i][kk];
            #pragma unroll
            for (int j = 0; j < 4; j++) bv[j] = sK[tc + j][kk];
            #pragma unroll
            for (int i = 0; i < 4; i++)
                #pragma unroll
                for (int j = 0; j < 4; j++)
                    acc[i][j] += a[i] * bv[j];
        }
        __syncthreads();
    }
    #pragma unroll
    for (int i = 0; i < 4; i++)
        #pragma unroll
        for (int j = 0; j < 4; j++)
            atomicAdd(&g_attn[(size_t)bh*HD*HD + (tr+i)*HD + tc + j], acc[i][j]);
}

// ---------------- 6: softmax with temperature and fused L2-norm scaling --------
__global__ void k_softmax(const float* __restrict__ temp){
    int bh = blockIdx.x;
    int d = threadIdx.x;
    float t = temp[bh & 3] * g_invq[bh*64 + d];
    float* row = g_attn + (size_t)bh * HD * HD + d * HD;
    float l[64];
    float m = -1e30f;
    #pragma unroll
    for (int e = 0; e < 64; e++){
        l[e] = row[e] * t * g_invk[bh*64 + e];
        m = fmaxf(m, l[e]);
    }
    float s = 0.f;
    #pragma unroll
    for (int e = 0; e < 64; e++){ float v = expf(l[e] - m); l[e] = v; s += v; }
    float inv = 1.f / s;
    #pragma unroll
    for (int e = 0; e < 64; e++) row[e] = l[e] * inv;
}

// ---------------- 7: attened = attn @ v  -> (B,C,N), fused global-avg-pool -----
__global__ void k_attn_v(){
    int bh = blockIdx.y;
    int bb = bh >> 2, h = bh & 3;
    int n0 = blockIdx.x * 64;
    __shared__ float sAt[64][65];
    __shared__ float pool[64];
    int tid = threadIdx.x;
    #pragma unroll
    for (int i = 0; i < 16; i++){
        int idx = tid + i * 256;
        sAt[idx >> 6][idx & 63] = g_attn[(size_t)bh*HD*HD + idx];
    }
    if (tid < 64) pool[tid] = 0.f;
    __syncthreads();
    int nl = tid & 63;
    int dg = tid >> 6;
    float acc[16] = {};
    const float* vb = g_v + (size_t)bh * HD * Nn + n0 + nl;
    for (int e = 0; e < 64; e++){
        float vv = vb[(size_t)e * Nn];
        #pragma unroll
        for (int j = 0; j < 16; j++) acc[j] += sAt[dg*16 + j][e] * vv;
    }
    float* dst = g_att + ((size_t)(bb*Cc + h*HD + dg*16)) * Nn + n0 + nl;
    #pragma unroll
    for (int j = 0; j < 16; j++){
        dst[(size_t)j * Nn] = acc[j];
        atomicAdd(&pool[dg*16 + j], acc[j]);
    }
    __syncthreads();
    if (tid < 64) atomicAdd(&g_pool[bb*Cc + h*HD + tid], pool[tid]);
}

// ---------------- 8: depthwise 3x3 conv + GELU on v (B,C,H,W) ------------------
__global__ void k_dwconv(const float* __restrict__ w, const float* __restrict__ bias){
    int bc = blockIdx.x;
    int c  = bc & (Cc-1);
    const float* plane = g_v + (size_t)bc * Nn;
    float wk[9];
    #pragma unroll
    for (int i = 0; i < 9; i++) wk[i] = w[c*9 + i];
    float bb = bias[c];
    for (int p = threadIdx.x; p < Nn; p += 256){
        int y = p >> 6, x = p & 63;
        float s = bb;
        #pragma unroll
        for (int dy = -1; dy <= 1; dy++){
            int yy = y + dy;
            if (yy < 0 || yy >= Hh) continue;
            #pragma unroll
            for (int dx = -1; dx <= 1; dx++){
                int xx = x + dx;
                if (xx < 0 || xx >= Ww) continue;
                s += plane[yy*Ww + xx] * wk[(dy+1)*3 + dx + 1];
            }
        }
        g_conv[(size_t)bc * Nn + p] = gelu_f(s);
    }
}

// ---------------- 9: channel interaction SE -> gc = sigmoid(map) ---------------
__global__ void k_channel_mlp(const float* __restrict__ w1, const float* __restrict__ b1,
                              const float* __restrict__ w2, const float* __restrict__ b2){
    int bb = blockIdx.x;
    int tid = threadIdx.x;
    __shared__ float sp[256];
    __shared__ float h1[32];
    sp[tid] = g_pool[bb*Cc + tid] * (1.f / Nn);
    __syncthreads();
    if (tid < 32){
        float a = b1[tid];
        for (int c = 0; c < 256; c++) a += sp[c] * w1[tid*256 + c];
        h1[tid] = gelu_f(a);
    }
    __syncthreads();
    float a = b2[tid];
    #pragma unroll
    for (int j = 0; j < 32; j++) a += h1[j] * w2[tid*32 + j];
    g_gc[bb*Cc + tid] = sigmoid_f(a);
}

// ---------------- 10: spatial interaction -> gs = sigmoid(map) -----------------
__global__ void k_spatial(const float* __restrict__ w1, const float* __restrict__ b1,
                          const float* __restrict__ w2, const float* __restrict__ b2){
    int bb = blockIdx.x >> 4;
    int n  = (blockIdx.x & 15) * 256 + threadIdx.x;
    __shared__ float sw1[16*256];
    for (int i = threadIdx.x; i < 16*256; i += 256) sw1[i] = w1[i];
    __syncthreads();
    float acc[16];
    #pragma unroll
    for (int o = 0; o < 16; o++) acc[o] = b1[o];
    const float* cb = g_conv + (size_t)bb * Cc * Nn + n;
    for (int c = 0; c < 256; c++){
        float x = cb[(size_t)c * Nn];
        #pragma unroll
        for (int o = 0; o < 16; o++) acc[o] += x * sw1[o*256 + c];
    }
    float sm = b2[0];
    #pragma unroll
    for (int o = 0; o < 16; o++) sm += gelu_f(acc[o]) * w2[o];
    g_gs[bb*Nn + n] = sigmoid_f(sm);
}

// ---------------- 11: fused gate + proj GEMM + bias + transpose out ------------
__global__ void __launch_bounds__(256) k_proj_gemm(const float* __restrict__ w,
                                                   const float* __restrict__ bias,
                                                   float* __restrict__ out){
    __shared__ float sA[2][8][128];
    __shared__ float sB[2][8][128];
    int m0   = blockIdx.y * 128;
    int col0 = blockIdx.x * 128;
    int bb = m0 >> 12;
    int n0 = m0 & (Nn-1);
    int tid = threadIdx.x;
    int lr  = tid >> 5;
    int lc4 = (tid & 31) * 4;
    int ty = tid >> 4, tx = tid & 15;

    const float* At = g_att  + (size_t)(bb*Cc) * Nn + n0;
    const float* Cv = g_conv + (size_t)(bb*Cc) * Nn + n0;
    const float* Bbase = w + col0;
    float4 gs4 = *(const float4*)&g_gs[bb*Nn + n0 + lc4];

    float acc[8][8] = {};
    {
        float4 a  = *(const float4*)&At[(size_t)lr * Nn + lc4];
        float4 cv = *(const float4*)&Cv[(size_t)lr * Nn + lc4];
        float  gc = g_gc[bb*Cc + lr];
        float4 ra = make_float4(a.x*gs4.x + cv.x*gc, a.y*gs4.y + cv.y*gc,
                                a.z*gs4.z + cv.z*gc, a.w*gs4.w + cv.w*gc);
        float4 rb = *(const float4*)&Bbase[(size_t)lr * 256 + lc4];
        *(float4*)&sA[0][lr][lc4] = ra;
        *(float4*)&sB[0][lr][lc4] = rb;
    }
    __syncthreads();

    #pragma unroll 1
    for (int kt = 0; kt < 32; kt++){
        int buf = kt & 1;
        float4 ra, rb;
        if (kt < 31){
            int kr = (kt+1)*8 + lr;
            float4 a  = *(const float4*)&At[(size_t)kr * Nn + lc4];
            float4 cv = *(const float4*)&Cv[(size_t)kr * Nn + lc4];
            float  gc = g_gc[bb*Cc + kr];
            ra = make_float4(a.x*gs4.x + cv.x*gc, a.y*gs4.y + cv.y*gc,
                             a.z*gs4.z + cv.z*gc, a.w*gs4.w + cv.w*gc);
            rb = *(const float4*)&Bbase[(size_t)kr * 256 + lc4];
        }
        #pragma unroll
        for (int kk = 0; kk < 8; kk++){
            float a[8], bv[8];
            *(float4*)(a)    = *(const float4*)&sA[buf][kk][ty*8];
            *(float4*)(a+4)  = *(const float4*)&sA[buf][kk][ty*8 + 4];
            *(float4*)(bv)   = *(const float4*)&sB[buf][kk][tx*8];
            *(float4*)(bv+4) = *(const float4*)&sB[buf][kk][tx*8 + 4];
            #pragma unroll
            for (int i = 0; i < 8; i++)
                #pragma unroll
                for (int j = 0; j < 8; j++)
                    acc[i][j] += a[i] * bv[j];
        }
        if (kt < 31){
            *(float4*)&sA[buf^1][lr][lc4] = ra;
            *(float4*)&sB[buf^1][lr][lc4] = rb;
        }
        __syncthreads();
    }

    int nrow = n0 + ty * 8;
    #pragma unroll
    for (int j = 0; j < 8; j++){
        int o = col0 + tx*8 + j;
        float bo = bias[o];
        float* dst = out + ((size_t)(bb*Cc) + o) * Nn + nrow;
        *(float4*)&dst[0] = make_float4(acc[0][j]+bo, acc[1][j]+bo, acc[2][j]+bo, acc[3][j]+bo);
        *(float4*)&dst[4] = make_float4(acc[4][j]+bo, acc[5][j]+bo, acc[6][j]+bo, acc[7][j]+bo);
    }
}

// =================================================================================
extern "C" void kernel_launch(void* const* d_in, const int* in_sizes, int n_in,
                              void* d_out, int out_size){
    const float* x     = (const float*)d_in[0];
    const float* ln_g  = (const float*)d_in[1];
    const float* ln_b  = (const float*)d_in[2];
    const float* w_qkv = (const float*)d_in[3];
    const float* w_q   = (const float*)d_in[4];
    const float* b_q   = (const float*)d_in[5];
    const float* temp  = (const float*)d_in[6];
    const float* dw_w  = (const float*)d_in[7];
    const float* dw_b  = (const float*)d_in[8];
    const float* ci_w1 = (const float*)d_in[9];
    const float* ci_b1 = (const float*)d_in[10];
    const float* ci_w2 = (const float*)d_in[11];
    const float* ci_b2 = (const float*)d_in[12];
    const float* si_w1 = (const float*)d_in[13];
    const float* si_b1 = (const float*)d_in[14];
    const float* si_w2 = (const float*)d_in[15];
    const float* si_b2 = (const float*)d_in[16];
    const float* pj_w  = (const float*)d_in[17];
    const float* pj_b  = (const float*)d_in[18];
    float* out = (float*)d_out;

    cudaFuncSetAttribute(k_qkv_mma, cudaFuncAttributeMaxDynamicSharedMemorySize, QKV_SMEM);

    k_zero<<<512, 256>>>();
    k_layernorm<<<Bq*(Nn/32), 256>>>(x, ln_g, ln_b);
    k_buildW<<<Cc, 256>>>(w_qkv, w_q);
    k_qkv_mma<<<dim3(6, BN/128), 256, QKV_SMEM>>>(b_q);
    k_norms<<<2*Bq*NH*HD, 256>>>();
    k_attn_qk<<<dim3(8, Bq*NH), 256>>>();
    k_softmax<<<Bq*NH, 64>>>(temp);
    k_attn_v<<<dim3(Nn/64, Bq*NH), 256>>>();
    k_dwconv<<<Bq*Cc, 256>>>(dw_w, dw_b);
    k_spatial<<<Bq*16, 256>>>(si_w1, si_b1, si_w2, si_b2);
    k_channel_mlp<<<Bq, 256>>>(ci_w1, ci_b1, ci_w2, ci_b2);
    k_proj_gemm<<<dim3(2, BN/128), 256>>>(pj_w, pj_b, out);
}

// round 6
// speedup vs baseline: 1.7122x; 1.1808x over previous
#include <cuda_runtime.h>
#include <cuda_bf16.h>
#include <math.h>
#include <stdint.h>

// Problem constants
#define Bq   8
#define Cc   256
#define Hh   64
#define Ww   64
#define Nn   4096            // H*W
#define NH   4
#define HD   64
#define BN   (Bq*Nn)         // 32768

// ---------------- scratch (device globals; no allocation allowed) -------------
__device__ __nv_bfloat16 g_xn_hi[BN*Cc];   // layernormed x, [b*N + n][c], bf16 hi
__device__ __nv_bfloat16 g_xn_lo[BN*Cc];   // bf16 lo residual
__device__ __nv_bfloat16 g_wB_hi[768*Cc];  // folded qkv weight, [o][c] bf16 hi
__device__ __nv_bfloat16 g_wB_lo[768*Cc];
__device__ __nv_bfloat16 g_wP_hi[Cc*Cc];   // proj weight transposed [o][c]
__device__ __nv_bfloat16 g_wP_lo[Cc*Cc];
__device__ float g_q   [Bq*NH*HD*Nn];  // (B,nh,hd,N)
__device__ float g_k   [Bq*NH*HD*Nn];
__device__ float g_v   [Bq*NH*HD*Nn];  // == (B,C,N) head-major
__device__ float g_att [Bq*Cc*Nn];     // attened_x stored (B,C,N)
__device__ float g_conv[Bq*Cc*Nn];     // gelu(dwconv), (B,C,N)
__device__ float g_attn[Bq*NH*HD*HD];  // (B,nh,hd,hd)
__device__ float g_pool[Bq*Cc];        // sum over n of attened
__device__ float g_gc  [Bq*Cc];        // sigmoid(channel_map)
__device__ float g_gs  [Bq*Nn];        // sigmoid(spatial_map)
__device__ float g_sqq [Bq*Cc];        // sum of squares per q row
__device__ float g_sqk [Bq*Cc];

__device__ __forceinline__ float gelu_f(float x){
    return 0.5f * x * (1.0f + erff(x * 0.70710678118654752f));
}
__device__ __forceinline__ float sigmoid_f(float x){
    return 1.0f / (1.0f + expf(-x));
}
__device__ __forceinline__ uint32_t smem_u32(const void* p){
    uint32_t a;
    asm("{ .reg .u64 t; cvta.to.shared.u64 t, %1; cvt.u32.u64 %0, t; }" : "=r"(a) : "l"(p));
    return a;
}
__device__ __forceinline__ void ldmx4(uint32_t* r, uint32_t addr){
    asm volatile("ldmatrix.sync.aligned.m8n8.x4.shared.b16 {%0,%1,%2,%3}, [%4];"
                 : "=r"(r[0]), "=r"(r[1]), "=r"(r[2]), "=r"(r[3]) : "r"(addr));
}
__device__ __forceinline__ void ldmx4t(uint32_t* r, uint32_t addr){
    asm volatile("ldmatrix.sync.aligned.m8n8.x4.trans.shared.b16 {%0,%1,%2,%3}, [%4];"
                 : "=r"(r[0]), "=r"(r[1]), "=r"(r[2]), "=r"(r[3]) : "r"(addr));
}
__device__ __forceinline__ void mma_bf16(float* d, const uint32_t* a, uint32_t b0, uint32_t b1){
    asm volatile(
        "mma.sync.aligned.m16n8k16.row.col.f32.bf16.bf16.f32 "
        "{%0,%1,%2,%3}, {%4,%5,%6,%7}, {%8,%9}, {%0,%1,%2,%3};"
        : "+f"(d[0]), "+f"(d[1]), "+f"(d[2]), "+f"(d[3])
        : "r"(a[0]), "r"(a[1]), "r"(a[2]), "r"(a[3]), "r"(b0), "r"(b1));
}
__device__ __forceinline__ void cpa16(uint32_t d, const void* s){
    asm volatile("cp.async.cg.shared.global [%0], [%1], 16;" :: "r"(d), "l"(s));
}
__device__ __forceinline__ uint32_t pack_bf2(__nv_bfloat16 a, __nv_bfloat16 b){
    return ((uint32_t)__bfloat16_as_ushort(b) << 16) | (uint32_t)__bfloat16_as_ushort(a);
}

// qkv pipeline smem: k-chunk 32 bf16 = 64B rows padded to 80B; 4 tiles/stage, 2 stages
#define QT    80
#define QSTG  40960
#define QAH   0
#define QAL   10240
#define QBH   20480
#define QBL   30720
#define QKV_SMEM 81920

// ---------------- 0: zero the accumulated buffers -----------------------------
__global__ void k_zero(){
    int i = blockIdx.x * 256 + threadIdx.x;
    if (i < Bq*NH*HD*HD) g_attn[i] = 0.f;
    if (i < Bq*Cc){ g_pool[i] = 0.f; g_sqq[i] = 0.f; g_sqk[i] = 0.f; }
}

// ---------------- 1: LayerNorm over C -> g_xn_hi/lo bf16, layout [b*N+n][c] ----
__global__ void k_layernorm(const float* __restrict__ x,
                            const float* __restrict__ g,
                            const float* __restrict__ b){
    __shared__ float sx[256][33];
    __shared__ float spart[8][32];
    __shared__ float smu[32], sinv[32];
    int bb = blockIdx.x >> 7;
    int n0 = (blockIdx.x & 127) * 32;
    int tid = threadIdx.x;
    int nl = tid & 31, part = tid >> 5;
    const float* xb = x + (size_t)bb * Cc * Nn + n0;
    #pragma unroll
    for (int c0 = 0; c0 < 256; c0 += 8)
        sx[c0 + part][nl] = xb[(size_t)(c0 + part) * Nn + nl];
    __syncthreads();
    float s = 0.f, s2 = 0.f;
    #pragma unroll
    for (int i = 0; i < 32; i++){ float v = sx[part*32 + i][nl]; s += v; s2 += v*v; }
    spart[part][nl] = s;
    __syncthreads();
    if (part == 0){ float t = 0.f; for (int p = 0; p < 8; p++) t += spart[p][nl]; smu[nl] = t * (1.f/256.f); }
    __syncthreads();
    spart[part][nl] = s2;
    __syncthreads();
    if (part == 0){
        float t = 0.f; for (int p = 0; p < 8; p++) t += spart[p][nl];
        float mu = smu[nl];
        sinv[nl] = rsqrtf(t * (1.f/256.f) - mu*mu + 1e-5f);
    }
    __syncthreads();
    float gc = g[tid], bc = b[tid];
    for (int n = 0; n < 32; n++){
        float val = (sx[tid][n] - smu[n]) * sinv[n] * gc + bc;
        __nv_bfloat16 hi = __float2bfloat16(val);
        __nv_bfloat16 lo = __float2bfloat16(val - __bfloat162float(hi));
        size_t o = ((size_t)(bb * Nn) + n0 + n) * 256 + tid;
        g_xn_hi[o] = hi;
        g_xn_lo[o] = lo;
    }
}

// ---------------- 1b: fold w_q into qkv weight -> g_wB_hi/lo [o][c] bf16 -------
__global__ void k_buildW(const float* __restrict__ wqkv, const float* __restrict__ wq){
    __shared__ float srow[768];
    __shared__ float swq[64*64];
    int c = blockIdx.x;
    int tid = threadIdx.x;
    for (int i = tid; i < 768; i += 256)  srow[i] = wqkv[(size_t)c*768 + i];
    for (int i = tid; i < 4096; i += 256) swq[i]  = wq[i];
    __syncthreads();
    int h = tid >> 6, d = tid & 63;
    float s = 0.f;
    #pragma unroll 16
    for (int e = 0; e < 64; e++) s += srow[h*64 + e] * swq[e*64 + d];
    float vals[3] = { s, srow[256 + tid], srow[512 + tid] };
    #pragma unroll
    for (int t = 0; t < 3; t++){
        int o = t*256 + tid;
        __nv_bfloat16 hi = __float2bfloat16(vals[t]);
        __nv_bfloat16 lo = __float2bfloat16(vals[t] - __bfloat162float(hi));
        g_wB_hi[(size_t)o*256 + c] = hi;
        g_wB_lo[(size_t)o*256 + c] = lo;
    }
}

// ---------------- 1c: transpose proj weight -> g_wP_hi/lo [o][c] bf16 ----------
__global__ void k_buildP(const float* __restrict__ w){
    int o = blockIdx.x, c = threadIdx.x;
    float v = w[(size_t)c*256 + o];
    __nv_bfloat16 hi = __float2bfloat16(v);
    __nv_bfloat16 lo = __float2bfloat16(v - __bfloat162float(hi));
    g_wP_hi[(size_t)o*256 + c] = hi;
    g_wP_lo[(size_t)o*256 + c] = lo;
}

// ---------------- 2: qkv GEMM via mma.sync bf16x3, cp.async 2-stage ------------
// gemm-M = 768 channels (A = g_wB [o][c]), gemm-N = 32768 bn (B = g_xn [bn][c]).
// Block 128(ch) x 128(bn), K=256 in 8 chunks of 32. Fused q/k row-norm sums.
__global__ void __launch_bounds__(256) k_qkv_mma(const float* __restrict__ bq){
    extern __shared__ char dsm[];
    uint32_t sb = smem_u32(dsm);
    int tid = threadIdx.x, wid = tid >> 5, lid = tid & 31;
    int warp_m = wid >> 2, warp_n = wid & 3;
    int cblk = blockIdx.x * 128;
    int bn0  = blockIdx.y * 128;
    int bb = bn0 >> 12, n0 = bn0 & (Nn-1);

    int gr = tid >> 1, ghf = tid & 1;
    const char* pwh = (const char*)(g_wB_hi + (size_t)(cblk + gr)*256) + ghf*32;
    const char* pwl = (const char*)(g_wB_lo + (size_t)(cblk + gr)*256) + ghf*32;
    const char* pxh = (const char*)(g_xn_hi + (size_t)(bn0  + gr)*256) + ghf*32;
    const char* pxl = (const char*)(g_xn_lo + (size_t)(bn0  + gr)*256) + ghf*32;
    uint32_t drow = sb + gr*QT + ghf*32;

    // prefetch chunk 0
    #pragma unroll
    for (int j = 0; j < 2; j++){
        cpa16(drow + QAH + j*16, pwh + j*16);
        cpa16(drow + QAL + j*16, pwl + j*16);
        cpa16(drow + QBH + j*16, pxh + j*16);
        cpa16(drow + QBL + j*16, pxl + j*16);
    }
    asm volatile("cp.async.commit_group;");

    uint32_t aAo = (uint32_t)((warp_m*64 + (lid & 7) + ((lid >> 3) & 1)*8)*QT + ((lid >> 4) & 1)*16);
    uint32_t aBo = (uint32_t)((warp_n*32 + (lid & 7) + ((lid >> 4) & 1)*8)*QT + ((lid >> 3) & 1)*16);

    float acc[4][4][4] = {};

    #pragma unroll 1
    for (int kc = 0; kc < 8; kc++){
        if (kc < 7){
            uint32_t d = drow + ((kc + 1) & 1)*QSTG;
            size_t go = (size_t)(kc + 1)*64;
            #pragma unroll
            for (int j = 0; j < 2; j++){
                cpa16(d + QAH + j*16, pwh + go + j*16);
                cpa16(d + QAL + j*16, pwl + go + j*16);
                cpa16(d + QBH + j*16, pxh + go + j*16);
                cpa16(d + QBL + j*16, pxl + go + j*16);
            }
            asm volatile("cp.async.commit_group;");
            asm volatile("cp.async.wait_group 1;");
        } else {
            asm volatile("cp.async.wait_group 0;");
        }
        __syncthreads();
        uint32_t base = sb + (kc & 1)*QSTG;
        #pragma unroll
        for (int ks = 0; ks < 2; ks++){
            uint32_t kofs = ks*32;
            uint32_t bh[8], bl[8], arh[4], arl[4];
            ldmx4(bh,     base + QBH + aBo + kofs);
            ldmx4(bh + 4, base + QBH + aBo + kofs + 16*QT);
            ldmx4(bl,     base + QBL + aBo + kofs);
            ldmx4(bl + 4, base + QBL + aBo + kofs + 16*QT);
            #pragma unroll
            for (int mi = 0; mi < 4; mi++){
                ldmx4(arh, base + QAH + aAo + kofs + (uint32_t)(mi*16)*QT);
                ldmx4(arl, base + QAL + aAo + kofs + (uint32_t)(mi*16)*QT);
                #pragma unroll
                for (int ni = 0; ni < 4; ni++) mma_bf16(acc[mi][ni], arh, bh[ni*2], bh[ni*2+1]);
                #pragma unroll
                for (int ni = 0; ni < 4; ni++) mma_bf16(acc[mi][ni], arh, bl[ni*2], bl[ni*2+1]);
                #pragma unroll
                for (int ni = 0; ni < 4; ni++) mma_bf16(acc[mi][ni], arl, bh[ni*2], bh[ni*2+1]);
            }
        }
        __syncthreads();
    }

    // epilogue + fused norm sums
    int gid = lid >> 2, q4 = lid & 3;
    int obase = cblk + warp_m*64 + gid;
    int ot = obase >> 8;                 // 0=q,1=k,2=v (constant per block)
    float* arr = (ot == 0) ? g_q : (ot == 1) ? g_k : g_v;
    #pragma unroll
    for (int mi = 0; mi < 4; mi++){
        int o0 = obase + mi*16;
        float bo0 = (ot == 0) ? bq[o0 & 63] : 0.f;
        float bo1 = (ot == 0) ? bq[(o0 + 8) & 63] : 0.f;
        float* r0 = arr + ((size_t)(bb*Cc + (o0 & 255))) * Nn;
        float* r1 = arr + ((size_t)(bb*Cc + ((o0 + 8) & 255))) * Nn;
        float s0 = 0.f, s1 = 0.f;
        #pragma unroll
        for (int ni = 0; ni < 4; ni++){
            int n = n0 + warp_n*32 + ni*8 + q4*2;
            float v0 = acc[mi][ni][0] + bo0, v1 = acc[mi][ni][1] + bo0;
            float v2 = acc[mi][ni][2] + bo1, v3 = acc[mi][ni][3] + bo1;
            *(float2*)&r0[n] = make_float2(v0, v1);
            *(float2*)&r1[n] = make_float2(v2, v3);
            s0 += v0*v0 + v1*v1;
            s1 += v2*v2 + v3*v3;
        }
        if (ot < 2){
            s0 += __shfl_xor_sync(0xFFFFFFFF, s0, 1);
            s0 += __shfl_xor_sync(0xFFFFFFFF, s0, 2);
            s1 += __shfl_xor_sync(0xFFFFFFFF, s1, 1);
            s1 += __shfl_xor_sync(0xFFFFFFFF, s1, 2);
            if (q4 == 0){
                float* sq = ot ? g_sqk : g_sqq;
                atomicAdd(&sq[bb*Cc + (o0 & 255)], s0);
                atomicAdd(&sq[bb*Cc + ((o0 + 8) & 255)], s1);
            }
        }
    }
}

// ---------------- 5: attn partial: q @ k^T over n-chunks (atomic accumulate) ---
__global__ void k_attn_qk(){
    int bh = blockIdx.y;
    int n0 = blockIdx.x * 512;
    __shared__ float sQ[64][65];
    __shared__ float sK[64][65];
    int tid = threadIdx.x;
    int tr = (tid >> 4) * 4;
    int tc = (tid & 15) * 4;
    float acc[4][4] = {};
    const float* qb = g_q + (size_t)bh * HD * Nn;
    const float* kb = g_k + (size_t)bh * HD * Nn;
    for (int s = 0; s < 8; s++){
        int nn = n0 + s * 64;
        #pragma unroll
        for (int i = 0; i < 16; i++){
            int idx = tid + i * 256;
            int dl = idx >> 6, nl = idx & 63;
            sQ[dl][nl] = qb[(size_t)dl * Nn + nn + nl];
            sK[dl][nl] = kb[(size_t)dl * Nn + nn + nl];
        }
        __syncthreads();
        #pragma unroll 8
        for (int kk = 0; kk < 64; kk++){
            float a[4], bv[4];
            #pragma unroll
            for (int i = 0; i < 4; i++) a[i]  = sQ[tr + i][kk];
            #pragma unroll
            for (int j = 0; j < 4; j++) bv[j] = sK[tc + j][kk];
            #pragma unroll
            for (int i = 0; i < 4; i++)
                #pragma unroll
                for (int j = 0; j < 4; j++)
                    acc[i][j] += a[i] * bv[j];
        }
        __syncthreads();
    }
    #pragma unroll
    for (int i = 0; i < 4; i++)
        #pragma unroll
        for (int j = 0; j < 4; j++)
            atomicAdd(&g_attn[(size_t)bh*HD*HD + (tr+i)*HD + tc + j], acc[i][j]);
}

// ---------------- 6: softmax with temperature and fused L2-norm scaling --------
__global__ void k_softmax(const float* __restrict__ temp){
    int bh = blockIdx.x;
    int d = threadIdx.x;
    float invq = 1.f / fmaxf(sqrtf(g_sqq[bh*64 + d]), 1e-12f);
    float t = temp[bh & 3] * invq;
    float* row = g_attn + (size_t)bh * HD * HD + d * HD;
    float l[64];
    float m = -1e30f;
    #pragma unroll
    for (int e = 0; e < 64; e++){
        float invk = 1.f / fmaxf(sqrtf(g_sqk[bh*64 + e]), 1e-12f);
        l[e] = row[e] * t * invk;
        m = fmaxf(m, l[e]);
    }
    float s = 0.f;
    #pragma unroll
    for (int e = 0; e < 64; e++){ float v = expf(l[e] - m); l[e] = v; s += v; }
    float inv = 1.f / s;
    #pragma unroll
    for (int e = 0; e < 64; e++) row[e] = l[e] * inv;
}

// ---------------- 7: attened = attn @ v  -> (B,C,N), fused global-avg-pool -----
__global__ void k_attn_v(){
    int bh = blockIdx.y;
    int bb = bh >> 2, h = bh & 3;
    int n0 = blockIdx.x * 64;
    __shared__ float sAt[64][65];
    __shared__ float pool[64];
    int tid = threadIdx.x;
    #pragma unroll
    for (int i = 0; i < 16; i++){
        int idx = tid + i * 256;
        sAt[idx >> 6][idx & 63] = g_attn[(size_t)bh*HD*HD + idx];
    }
    if (tid < 64) pool[tid] = 0.f;
    __syncthreads();
    int nl = tid & 63;
    int dg = tid >> 6;
    float acc[16] = {};
    const float* vb = g_v + (size_t)bh * HD * Nn + n0 + nl;
    for (int e = 0; e < 64; e++){
        float vv = vb[(size_t)e * Nn];
        #pragma unroll
        for (int j = 0; j < 16; j++) acc[j] += sAt[dg*16 + j][e] * vv;
    }
    float* dst = g_att + ((size_t)(bb*Cc + h*HD + dg*16)) * Nn + n0 + nl;
    #pragma unroll
    for (int j = 0; j < 16; j++){
        dst[(size_t)j * Nn] = acc[j];
        atomicAdd(&pool[dg*16 + j], acc[j]);
    }
    __syncthreads();
    if (tid < 64) atomicAdd(&g_pool[bb*Cc + h*HD + tid], pool[tid]);
}

// ---------------- 8: depthwise 3x3 conv + GELU on v (B,C,H,W) ------------------
__global__ void k_dwconv(const float* __restrict__ w, const float* __restrict__ bias){
    int bc = blockIdx.x;
    int c  = bc & (Cc-1);
    const float* plane = g_v + (size_t)bc * Nn;
    float wk[9];
    #pragma unroll
    for (int i = 0; i < 9; i++) wk[i] = w[c*9 + i];
    float bb = bias[c];
    for (int p = threadIdx.x; p < Nn; p += 256){
        int y = p >> 6, x = p & 63;
        float s = bb;
        #pragma unroll
        for (int dy = -1; dy <= 1; dy++){
            int yy = y + dy;
            if (yy < 0 || yy >= Hh) continue;
            #pragma unroll
            for (int dx = -1; dx <= 1; dx++){
                int xx = x + dx;
                if (xx < 0 || xx >= Ww) continue;
                s += plane[yy*Ww + xx] * wk[(dy+1)*3 + dx + 1];
            }
        }
        g_conv[(size_t)bc * Nn + p] = gelu_f(s);
    }
}

// ---------------- 9: channel interaction SE -> gc = sigmoid(map) ---------------
__global__ void k_channel_mlp(const float* __restrict__ w1, const float* __restrict__ b1,
                              const float* __restrict__ w2, const float* __restrict__ b2){
    int bb = blockIdx.x;
    int tid = threadIdx.x;
    __shared__ float sp[256];
    __shared__ float h1[32];
    sp[tid] = g_pool[bb*Cc + tid] * (1.f / Nn);
    __syncthreads();
    if (tid < 32){
        float a = b1[tid];
        for (int c = 0; c < 256; c++) a += sp[c] * w1[tid*256 + c];
        h1[tid] = gelu_f(a);
    }
    __syncthreads();
    float a = b2[tid];
    #pragma unroll
    for (int j = 0; j < 32; j++) a += h1[j] * w2[tid*32 + j];
    g_gc[bb*Cc + tid] = sigmoid_f(a);
}

// ---------------- 10: spatial interaction -> gs = sigmoid(map) -----------------
__global__ void k_spatial(const float* __restrict__ w1, const float* __restrict__ b1,
                          const float* __restrict__ w2, const float* __restrict__ b2){
    int bb = blockIdx.x >> 4;
    int n  = (blockIdx.x & 15) * 256 + threadIdx.x;
    __shared__ float sw1[16*256];
    for (int i = threadIdx.x; i < 16*256; i += 256) sw1[i] = w1[i];
    __syncthreads();
    float acc[16];
    #pragma unroll
    for (int o = 0; o < 16; o++) acc[o] = b1[o];
    const float* cb = g_conv + (size_t)bb * Cc * Nn + n;
    for (int c = 0; c < 256; c++){
        float x = cb[(size_t)c * Nn];
        #pragma unroll
        for (int o = 0; o < 16; o++) acc[o] += x * sw1[o*256 + c];
    }
    float sm = b2[0];
    #pragma unroll
    for (int o = 0; o < 16; o++) sm += gelu_f(acc[o]) * w2[o];
    g_gs[bb*Nn + n] = sigmoid_f(sm);
}

// ---------------- 11: proj GEMM via mma.sync bf16x3, fused gating ---------------
// gemm-M = 256 out channels (A = g_wP [o][c]), gemm-N = bn (B = gated act [c][n]).
// B staged [c][n] bf16 hi/lo, consumed via ldmatrix.trans. K=256 in 8 chunks.
#define PAH 0
#define PAL 10240
#define PBH 20480
#define PBL 29184
#define PBT 272
__global__ void __launch_bounds__(256) k_proj_mma(const float* __restrict__ bias,
                                                  float* __restrict__ out){
    __shared__ __align__(16) char sm[37888];
    uint32_t sb = smem_u32(sm);
    int tid = threadIdx.x, wid = tid >> 5, lid = tid & 31;
    int warp_m = wid >> 2, warp_n = wid & 3;
    int cblk = blockIdx.x * 128;         // o block
    int bn0  = blockIdx.y * 128;
    int bb = bn0 >> 12, n0 = bn0 & (Nn-1);

    // A loader (weights)
    int gr = tid >> 1, ghf = tid & 1;
    const char* pah = (const char*)(g_wP_hi + (size_t)(cblk + gr)*256) + ghf*32;
    const char* pal = (const char*)(g_wP_lo + (size_t)(cblk + gr)*256) + ghf*32;
    char* dA = sm + gr*80 + ghf*32;

    // B loader (gated activations): thread covers row c0+cr, 16 n's at ncb
    int cr = tid >> 3, ncb = (tid & 7) * 16;
    const float* At = g_att  + (size_t)(bb*Cc) * Nn + n0 + ncb;
    const float* Cv = g_conv + (size_t)(bb*Cc) * Nn + n0 + ncb;
    float4 gsr[4];
    #pragma unroll
    for (int j = 0; j < 4; j++) gsr[j] = *(const float4*)&g_gs[bb*Nn + n0 + ncb + j*4];
    char* dBh = sm + PBH + cr*PBT + ncb*2;
    char* dBl = sm + PBL + cr*PBT + ncb*2;

    uint32_t aAo = (uint32_t)((warp_m*64 + (lid & 7) + ((lid >> 3) & 1)*8)*80 + ((lid >> 4) & 1)*16);
    uint32_t aBo = (uint32_t)(((lid & 7) + ((lid >> 3) & 1)*8)*PBT + warp_n*64 + ((lid >> 4) & 1)*16);

    float acc[4][4][4] = {};

    #pragma unroll 1
    for (int kc = 0; kc < 8; kc++){
        int c0 = kc * 32;
        // stage A
        #pragma unroll
        for (int j = 0; j < 2; j++){
            *(uint4*)(dA + PAH + j*16) = *(const uint4*)(pah + c0*2 + j*16);
            *(uint4*)(dA + PAL + j*16) = *(const uint4*)(pal + c0*2 + j*16);
        }
        // stage B: gate + convert fp32 -> bf16 hi/lo, layout [c][n]
        {
            float gc = g_gc[bb*Cc + c0 + cr];
            const float* at = At + (size_t)(c0 + cr) * Nn;
            const float* cv = Cv + (size_t)(c0 + cr) * Nn;
            #pragma unroll
            for (int j = 0; j < 4; j++){
                float4 a = ((const float4*)at)[j];
                float4 c = ((const float4*)cv)[j];
                float4 g = gsr[j];
                float v0 = a.x*g.x + c.x*gc, v1 = a.y*g.y + c.y*gc;
                float v2 = a.z*g.z + c.z*gc, v3 = a.w*g.w + c.w*gc;
                __nv_bfloat16 h0 = __float2bfloat16(v0), h1 = __float2bfloat16(v1);
                __nv_bfloat16 h2 = __float2bfloat16(v2), h3 = __float2bfloat16(v3);
                __nv_bfloat16 l0 = __float2bfloat16(v0 - __bfloat162float(h0));
                __nv_bfloat16 l1 = __float2bfloat16(v1 - __bfloat162float(h1));
                __nv_bfloat16 l2 = __float2bfloat16(v2 - __bfloat162float(h2));
                __nv_bfloat16 l3 = __float2bfloat16(v3 - __bfloat162float(h3));
                uint2 hp = make_uint2(pack_bf2(h0, h1), pack_bf2(h2, h3));
                uint2 lp = make_uint2(pack_bf2(l0, l1), pack_bf2(l2, l3));
                *(uint2*)(dBh + j*8) = hp;
                *(uint2*)(dBl + j*8) = lp;
            }
        }
        __syncthreads();
        #pragma unroll
        for (int ks = 0; ks < 2; ks++){
            uint32_t kro = (uint32_t)(ks*16)*PBT;
            uint32_t bh[8], bl[8], arh[4], arl[4];
            ldmx4t(bh,     sb + PBH + aBo + kro);
            ldmx4t(bh + 4, sb + PBH + aBo + kro + 32);
            ldmx4t(bl,     sb + PBL + aBo + kro);
            ldmx4t(bl + 4, sb + PBL + aBo + kro + 32);
            uint32_t kofs = ks*32;
            #pragma unroll
            for (int mi = 0; mi < 4; mi++){
                ldmx4(arh, sb + PAH + aAo + kofs + (uint32_t)(mi*16)*80);
                ldmx4(arl, sb + PAL + aAo + kofs + (uint32_t)(mi*16)*80);
                #pragma unroll
                for (int ni = 0; ni < 4; ni++) mma_bf16(acc[mi][ni], arh, bh[ni*2], bh[ni*2+1]);
                #pragma unroll
                for (int ni = 0; ni < 4; ni++) mma_bf16(acc[mi][ni], arh, bl[ni*2], bl[ni*2+1]);
                #pragma unroll
                for (int ni = 0; ni < 4; ni++) mma_bf16(acc[mi][ni], arl, bh[ni*2], bh[ni*2+1]);
            }
        }
        __syncthreads();
    }

    // epilogue: out (B,C,N)
    int gid = lid >> 2, q4 = lid & 3;
    int obase = cblk + warp_m*64 + gid;
    #pragma unroll
    for (int mi = 0; mi < 4; mi++){
        int o0 = obase + mi*16;
        float bo0 = bias[o0], bo1 = bias[o0 + 8];
        float* r0 = out + ((size_t)(bb*Cc + o0)) * Nn;
        float* r1 = out + ((size_t)(bb*Cc + o0 + 8)) * Nn;
        #pragma unroll
        for (int ni = 0; ni < 4; ni++){
            int n = n0 + warp_n*32 + ni*8 + q4*2;
            *(float2*)&r0[n] = make_float2(acc[mi][ni][0] + bo0, acc[mi][ni][1] + bo0);
            *(float2*)&r1[n] = make_float2(acc[mi][ni][2] + bo1, acc[mi][ni][3] + bo1);
        }
    }
}

// =================================================================================
extern "C" void kernel_launch(void* const* d_in, const int* in_sizes, int n_in,
                              void* d_out, int out_size){
    const float* x     = (const float*)d_in[0];
    const float* ln_g  = (const float*)d_in[1];
    const float* ln_b  = (const float*)d_in[2];
    const float* w_qkv = (const float*)d_in[3];
    const float* w_q   = (const float*)d_in[4];
    const float* b_q   = (const float*)d_in[5];
    const float* temp  = (const float*)d_in[6];
    const float* dw_w  = (const float*)d_in[7];
    const float* dw_b  = (const float*)d_in[8];
    const float* ci_w1 = (const float*)d_in[9];
    const float* ci_b1 = (const float*)d_in[10];
    const float* ci_w2 = (const float*)d_in[11];
    const float* ci_b2 = (const float*)d_in[12];
    const float* si_w1 = (const float*)d_in[13];
    const float* si_b1 = (const float*)d_in[14];
    const float* si_w2 = (const float*)d_in[15];
    const float* si_b2 = (const float*)d_in[16];
    const float* pj_w  = (const float*)d_in[17];
    const float* pj_b  = (const float*)d_in[18];
    float* out = (float*)d_out;

    cudaFuncSetAttribute(k_qkv_mma, cudaFuncAttributeMaxDynamicSharedMemorySize, QKV_SMEM);

    k_zero<<<512, 256>>>();
    k_layernorm<<<Bq*(Nn/32), 256>>>(x, ln_g, ln_b);
    k_buildW<<<Cc, 256>>>(w_qkv, w_q);
    k_buildP<<<Cc, 256>>>(pj_w);
    k_qkv_mma<<<dim3(6, BN/128), 256, QKV_SMEM>>>(b_q);
    k_attn_qk<<<dim3(8, Bq*NH), 256>>>();
    k_softmax<<<Bq*NH, 64>>>(temp);
    k_attn_v<<<dim3(Nn/64, Bq*NH), 256>>>();
    k_dwconv<<<Bq*Cc, 256>>>(dw_w, dw_b);
    k_spatial<<<Bq*16, 256>>>(si_w1, si_b1, si_w2, si_b2);
    k_channel_mlp<<<Bq, 256>>>(ci_w1, ci_b1, ci_w2, ci_b2);
    k_proj_mma<<<dim3(2, BN/128), 256>>>(pj_b, out);
}

// round 7
// speedup vs baseline: 2.6067x; 1.5225x over previous
#include <cuda_runtime.h>
#include <cuda_bf16.h>
#include <math.h>
#include <stdint.h>

// Problem constants
#define Bq   8
#define Cc   256
#define Hh   64
#define Ww   64
#define Nn   4096            // H*W
#define NH   4
#define HD   64
#define BN   (Bq*Nn)         // 32768

// ---------------- scratch (device globals; no allocation allowed) -------------
__device__ __nv_bfloat16 g_xn_hi[BN*Cc];   // layernormed x, [b*N + n][c], bf16 hi
__device__ __nv_bfloat16 g_xn_lo[BN*Cc];   // bf16 lo residual
__device__ __nv_bfloat16 g_wB_hi[768*Cc];  // folded qkv weight, [o][c] bf16 hi
__device__ __nv_bfloat16 g_wB_lo[768*Cc];
__device__ __nv_bfloat16 g_wP_hi[Cc*Cc];   // proj weight transposed [o][c]
__device__ __nv_bfloat16 g_wP_lo[Cc*Cc];
__device__ __nv_bfloat16 g_qh[Bq*Cc*Nn];   // q bf16 hi, row = bh*64+d, col n
__device__ __nv_bfloat16 g_ql[Bq*Cc*Nn];
__device__ __nv_bfloat16 g_kh[Bq*Cc*Nn];
__device__ __nv_bfloat16 g_kl[Bq*Cc*Nn];
__device__ float g_v   [Bq*NH*HD*Nn];  // (B,nh,hd,N) == (B,C,N) head-major
__device__ float g_att [Bq*Cc*Nn];     // attened_x stored (B,C,N)
__device__ float g_conv[Bq*Cc*Nn];     // gelu(dwconv), (B,C,N)
__device__ float g_attn[Bq*NH*HD*HD];  // (B,nh,hd,hd)
__device__ float g_pool[Bq*Cc];        // sum over n of attened
__device__ float g_gc  [Bq*Cc];        // sigmoid(channel_map)
__device__ float g_gs  [Bq*Nn];        // sigmoid(spatial_map)
__device__ float g_sqq [Bq*Cc];        // sum of squares per q row
__device__ float g_sqk [Bq*Cc];

__device__ __forceinline__ float gelu_f(float x){
    return 0.5f * x * (1.0f + erff(x * 0.70710678118654752f));
}
__device__ __forceinline__ float sigmoid_f(float x){
    return 1.0f / (1.0f + expf(-x));
}
__device__ __forceinline__ uint32_t smem_u32(const void* p){
    uint32_t a;
    asm("{ .reg .u64 t; cvta.to.shared.u64 t, %1; cvt.u32.u64 %0, t; }" : "=r"(a) : "l"(p));
    return a;
}
__device__ __forceinline__ void ldmx4(uint32_t* r, uint32_t addr){
    asm volatile("ldmatrix.sync.aligned.m8n8.x4.shared.b16 {%0,%1,%2,%3}, [%4];"
                 : "=r"(r[0]), "=r"(r[1]), "=r"(r[2]), "=r"(r[3]) : "r"(addr));
}
__device__ __forceinline__ void ldmx4t(uint32_t* r, uint32_t addr){
    asm volatile("ldmatrix.sync.aligned.m8n8.x4.trans.shared.b16 {%0,%1,%2,%3}, [%4];"
                 : "=r"(r[0]), "=r"(r[1]), "=r"(r[2]), "=r"(r[3]) : "r"(addr));
}
__device__ __forceinline__ void mma_bf16(float* d, const uint32_t* a, uint32_t b0, uint32_t b1){
    asm volatile(
        "mma.sync.aligned.m16n8k16.row.col.f32.bf16.bf16.f32 "
        "{%0,%1,%2,%3}, {%4,%5,%6,%7}, {%8,%9}, {%0,%1,%2,%3};"
        : "+f"(d[0]), "+f"(d[1]), "+f"(d[2]), "+f"(d[3])
        : "r"(a[0]), "r"(a[1]), "r"(a[2]), "r"(a[3]), "r"(b0), "r"(b1));
}
__device__ __forceinline__ void cpa16(uint32_t d, const void* s){
    asm volatile("cp.async.cg.shared.global [%0], [%1], 16;" :: "r"(d), "l"(s));
}
__device__ __forceinline__ uint32_t pack_bf2(__nv_bfloat16 a, __nv_bfloat16 b){
    return ((uint32_t)__bfloat16_as_ushort(b) << 16) | (uint32_t)__bfloat16_as_ushort(a);
}
__device__ __forceinline__ void split_bf(float v, __nv_bfloat16& h, __nv_bfloat16& l){
    h = __float2bfloat16(v);
    l = __float2bfloat16(v - __bfloat162float(h));
}

// qkv pipeline smem: k-chunk 32 bf16 = 64B rows padded to 80B; 4 tiles/stage, 2 stages
#define QT    80
#define QSTG  40960
#define QAH   0
#define QAL   10240
#define QBH   20480
#define QBL   30720
#define QKV_SMEM 81920

// ---------------- 0: zero the accumulated buffers -----------------------------
__global__ void k_zero(){
    int i = blockIdx.x * 256 + threadIdx.x;
    if (i < Bq*NH*HD*HD) g_attn[i] = 0.f;
    if (i < Bq*Cc){ g_pool[i] = 0.f; g_sqq[i] = 0.f; g_sqk[i] = 0.f; }
}

// ---------------- 1: LayerNorm over C -> g_xn_hi/lo bf16, layout [b*N+n][c] ----
__global__ void k_layernorm(const float* __restrict__ x,
                            const float* __restrict__ g,
                            const float* __restrict__ b){
    __shared__ float sx[256][33];
    __shared__ float spart[8][32];
    __shared__ float smu[32], sinv[32];
    int bb = blockIdx.x >> 7;
    int n0 = (blockIdx.x & 127) * 32;
    int tid = threadIdx.x;
    int nl = tid & 31, part = tid >> 5;
    const float* xb = x + (size_t)bb * Cc * Nn + n0;
    #pragma unroll
    for (int c0 = 0; c0 < 256; c0 += 8)
        sx[c0 + part][nl] = xb[(size_t)(c0 + part) * Nn + nl];
    __syncthreads();
    float s = 0.f, s2 = 0.f;
    #pragma unroll
    for (int i = 0; i < 32; i++){ float v = sx[part*32 + i][nl]; s += v; s2 += v*v; }
    spart[part][nl] = s;
    __syncthreads();
    if (part == 0){ float t = 0.f; for (int p = 0; p < 8; p++) t += spart[p][nl]; smu[nl] = t * (1.f/256.f); }
    __syncthreads();
    spart[part][nl] = s2;
    __syncthreads();
    if (part == 0){
        float t = 0.f; for (int p = 0; p < 8; p++) t += spart[p][nl];
        float mu = smu[nl];
        sinv[nl] = rsqrtf(t * (1.f/256.f) - mu*mu + 1e-5f);
    }
    __syncthreads();
    float gc = g[tid], bc = b[tid];
    for (int n = 0; n < 32; n++){
        float val = (sx[tid][n] - smu[n]) * sinv[n] * gc + bc;
        __nv_bfloat16 hi, lo; split_bf(val, hi, lo);
        size_t o = ((size_t)(bb * Nn) + n0 + n) * 256 + tid;
        g_xn_hi[o] = hi;
        g_xn_lo[o] = lo;
    }
}

// ---------------- 1b: fold w_q into qkv weight -> g_wB_hi/lo [o][c] bf16 -------
__global__ void k_buildW(const float* __restrict__ wqkv, const float* __restrict__ wq){
    __shared__ float srow[768];
    __shared__ float swq[64*64];
    int c = blockIdx.x;
    int tid = threadIdx.x;
    for (int i = tid; i < 768; i += 256)  srow[i] = wqkv[(size_t)c*768 + i];
    for (int i = tid; i < 4096; i += 256) swq[i]  = wq[i];
    __syncthreads();
    int h = tid >> 6, d = tid & 63;
    float s = 0.f;
    #pragma unroll 16
    for (int e = 0; e < 64; e++) s += srow[h*64 + e] * swq[e*64 + d];
    float vals[3] = { s, srow[256 + tid], srow[512 + tid] };
    #pragma unroll
    for (int t = 0; t < 3; t++){
        int o = t*256 + tid;
        __nv_bfloat16 hi, lo; split_bf(vals[t], hi, lo);
        g_wB_hi[(size_t)o*256 + c] = hi;
        g_wB_lo[(size_t)o*256 + c] = lo;
    }
}

// ---------------- 1c: transpose proj weight -> g_wP_hi/lo [o][c] bf16 ----------
__global__ void k_buildP(const float* __restrict__ w){
    int o = blockIdx.x, c = threadIdx.x;
    float v = w[(size_t)c*256 + o];
    __nv_bfloat16 hi, lo; split_bf(v, hi, lo);
    g_wP_hi[(size_t)o*256 + c] = hi;
    g_wP_lo[(size_t)o*256 + c] = lo;
}

// ---------------- 2: qkv GEMM via mma.sync bf16x3, cp.async 2-stage ------------
__global__ void __launch_bounds__(256) k_qkv_mma(const float* __restrict__ bq){
    extern __shared__ char dsm[];
    uint32_t sb = smem_u32(dsm);
    int tid = threadIdx.x, wid = tid >> 5, lid = tid & 31;
    int warp_m = wid >> 2, warp_n = wid & 3;
    int cblk = blockIdx.x * 128;
    int bn0  = blockIdx.y * 128;
    int bb = bn0 >> 12, n0 = bn0 & (Nn-1);

    int gr = tid >> 1, ghf = tid & 1;
    const char* pwh = (const char*)(g_wB_hi + (size_t)(cblk + gr)*256) + ghf*32;
    const char* pwl = (const char*)(g_wB_lo + (size_t)(cblk + gr)*256) + ghf*32;
    const char* pxh = (const char*)(g_xn_hi + (size_t)(bn0  + gr)*256) + ghf*32;
    const char* pxl = (const char*)(g_xn_lo + (size_t)(bn0  + gr)*256) + ghf*32;
    uint32_t drow = sb + gr*QT + ghf*32;

    #pragma unroll
    for (int j = 0; j < 2; j++){
        cpa16(drow + QAH + j*16, pwh + j*16);
        cpa16(drow + QAL + j*16, pwl + j*16);
        cpa16(drow + QBH + j*16, pxh + j*16);
        cpa16(drow + QBL + j*16, pxl + j*16);
    }
    asm volatile("cp.async.commit_group;");

    uint32_t aAo = (uint32_t)((warp_m*64 + (lid & 7) + ((lid >> 3) & 1)*8)*QT + ((lid >> 4) & 1)*16);
    uint32_t aBo = (uint32_t)((warp_n*32 + (lid & 7) + ((lid >> 4) & 1)*8)*QT + ((lid >> 3) & 1)*16);

    float acc[4][4][4] = {};

    #pragma unroll 1
    for (int kc = 0; kc < 8; kc++){
        if (kc < 7){
            uint32_t d = drow + ((kc + 1) & 1)*QSTG;
            size_t go = (size_t)(kc + 1)*64;
            #pragma unroll
            for (int j = 0; j < 2; j++){
                cpa16(d + QAH + j*16, pwh + go + j*16);
                cpa16(d + QAL + j*16, pwl + go + j*16);
                cpa16(d + QBH + j*16, pxh + go + j*16);
                cpa16(d + QBL + j*16, pxl + go + j*16);
            }
            asm volatile("cp.async.commit_group;");
            asm volatile("cp.async.wait_group 1;");
        } else {
            asm volatile("cp.async.wait_group 0;");
        }
        __syncthreads();
        uint32_t base = sb + (kc & 1)*QSTG;
        #pragma unroll
        for (int ks = 0; ks < 2; ks++){
            uint32_t kofs = ks*32;
            uint32_t bh[8], bl[8], arh[4], arl[4];
            ldmx4(bh,     base + QBH + aBo + kofs);
            ldmx4(bh + 4, base + QBH + aBo + kofs + 16*QT);
            ldmx4(bl,     base + QBL + aBo + kofs);
            ldmx4(bl + 4, base + QBL + aBo + kofs + 16*QT);
            #pragma unroll
            for (int mi = 0; mi < 4; mi++){
                ldmx4(arh, base + QAH + aAo + kofs + (uint32_t)(mi*16)*QT);
                ldmx4(arl, base + QAL + aAo + kofs + (uint32_t)(mi*16)*QT);
                #pragma unroll
                for (int ni = 0; ni < 4; ni++) mma_bf16(acc[mi][ni], arh, bh[ni*2], bh[ni*2+1]);
                #pragma unroll
                for (int ni = 0; ni < 4; ni++) mma_bf16(acc[mi][ni], arh, bl[ni*2], bl[ni*2+1]);
                #pragma unroll
                for (int ni = 0; ni < 4; ni++) mma_bf16(acc[mi][ni], arl, bh[ni*2], bh[ni*2+1]);
            }
        }
        __syncthreads();
    }

    // epilogue: q/k -> bf16 hi/lo (+ fused norm sums), v -> fp32
    int gid = lid >> 2, q4 = lid & 3;
    int obase = cblk + warp_m*64 + gid;
    int ot = obase >> 8;                 // 0=q,1=k,2=v (constant per block)
    #pragma unroll
    for (int mi = 0; mi < 4; mi++){
        int o0 = obase + mi*16;
        float bo0 = (ot == 0) ? bq[o0 & 63] : 0.f;
        float bo1 = (ot == 0) ? bq[(o0 + 8) & 63] : 0.f;
        size_t row0 = ((size_t)(bb*Cc + (o0 & 255))) * Nn;
        size_t row1 = ((size_t)(bb*Cc + ((o0 + 8) & 255))) * Nn;
        float s0 = 0.f, s1 = 0.f;
        #pragma unroll
        for (int ni = 0; ni < 4; ni++){
            int n = n0 + warp_n*32 + ni*8 + q4*2;
            float v0 = acc[mi][ni][0] + bo0, v1 = acc[mi][ni][1] + bo0;
            float v2 = acc[mi][ni][2] + bo1, v3 = acc[mi][ni][3] + bo1;
            if (ot == 2){
                *(float2*)&g_v[row0 + n] = make_float2(v0, v1);
                *(float2*)&g_v[row1 + n] = make_float2(v2, v3);
            } else {
                __nv_bfloat16* ah = ot ? g_kh : g_qh;
                __nv_bfloat16* al = ot ? g_kl : g_ql;
                __nv_bfloat16 h0,l0,h1,l1,h2,l2,h3,l3;
                split_bf(v0,h0,l0); split_bf(v1,h1,l1);
                split_bf(v2,h2,l2); split_bf(v3,h3,l3);
                *(uint32_t*)&ah[row0 + n] = pack_bf2(h0, h1);
                *(uint32_t*)&al[row0 + n] = pack_bf2(l0, l1);
                *(uint32_t*)&ah[row1 + n] = pack_bf2(h2, h3);
                *(uint32_t*)&al[row1 + n] = pack_bf2(l2, l3);
                s0 += v0*v0 + v1*v1;
                s1 += v2*v2 + v3*v3;
            }
        }
        if (ot < 2){
            s0 += __shfl_xor_sync(0xFFFFFFFF, s0, 1);
            s0 += __shfl_xor_sync(0xFFFFFFFF, s0, 2);
            s1 += __shfl_xor_sync(0xFFFFFFFF, s1, 1);
            s1 += __shfl_xor_sync(0xFFFFFFFF, s1, 2);
            if (q4 == 0){
                float* sq = ot ? g_sqk : g_sqq;
                atomicAdd(&sq[bb*Cc + (o0 & 255)], s0);
                atomicAdd(&sq[bb*Cc + ((o0 + 8) & 255)], s1);
            }
        }
    }
}

// ---------------- 5: attn = q @ k^T via mma.sync bf16x3 (atomic accumulate) ----
// Block: one head x 512-n chunk. A = q [d][n], B = k [e][n]. 8 warps = 4m x 2n.
#define AQT 144   // 72 bf16 row stride (bytes)
__global__ void __launch_bounds__(256) k_attn_qk_mma(){
    __shared__ __align__(16) char sm[4*64*AQT];   // qh, ql, kh, kl tiles (64x64)
    uint32_t sb = smem_u32(sm);
    const int OQH = 0, OQL = 64*AQT, OKH = 2*64*AQT, OKL = 3*64*AQT;
    int tid = threadIdx.x, wid = tid >> 5, lid = tid & 31;
    int warp_m = wid >> 1, warp_n = wid & 1;
    int bh = blockIdx.y;
    int nbase = blockIdx.x * 512;

    uint32_t aAo = (uint32_t)((warp_m*16 + (lid & 7) + ((lid >> 3) & 1)*8)*AQT + ((lid >> 4) & 1)*16);
    uint32_t aBo = (uint32_t)((warp_n*32 + (lid & 7) + ((lid >> 4) & 1)*8)*AQT + ((lid >> 3) & 1)*16);

    float acc[4][4] = {};

    #pragma unroll 1
    for (int kc = 0; kc < 8; kc++){
        int nb = nbase + kc*64;
        // stage 64x64 bf16 tiles: each thread 2 x 16B chunks per array
        #pragma unroll
        for (int i = 0; i < 2; i++){
            int idx = tid*2 + i;
            int r = idx >> 3, c16 = idx & 7;
            size_t go = ((size_t)(bh*64 + r))*Nn + nb + c16*8;
            uint32_t so = r*AQT + c16*16;
            *(uint4*)(sm + OQH + so) = *(const uint4*)(g_qh + go);
            *(uint4*)(sm + OQL + so) = *(const uint4*)(g_ql + go);
            *(uint4*)(sm + OKH + so) = *(const uint4*)(g_kh + go);
            *(uint4*)(sm + OKL + so) = *(const uint4*)(g_kl + go);
        }
        __syncthreads();
        #pragma unroll
        for (int ks = 0; ks < 4; ks++){
            uint32_t kofs = ks*32;
            uint32_t bh_[8], bl_[8], arh[4], arl[4];
            ldmx4(bh_,     sb + OKH + aBo + kofs);
            ldmx4(bh_ + 4, sb + OKH + aBo + kofs + 16*AQT);
            ldmx4(bl_,     sb + OKL + aBo + kofs);
            ldmx4(bl_ + 4, sb + OKL + aBo + kofs + 16*AQT);
            ldmx4(arh, sb + OQH + aAo + kofs);
            ldmx4(arl, sb + OQL + aAo + kofs);
            #pragma unroll
            for (int ni = 0; ni < 4; ni++) mma_bf16(acc[ni], arh, bh_[ni*2], bh_[ni*2+1]);
            #pragma unroll
            for (int ni = 0; ni < 4; ni++) mma_bf16(acc[ni], arh, bl_[ni*2], bl_[ni*2+1]);
            #pragma unroll
            for (int ni = 0; ni < 4; ni++) mma_bf16(acc[ni], arl, bh_[ni*2], bh_[ni*2+1]);
        }
        __syncthreads();
    }

    int gid = lid >> 2, q4 = lid & 3;
    float* dst = g_attn + (size_t)bh*HD*HD;
    #pragma unroll
    for (int ni = 0; ni < 4; ni++){
        int e = warp_n*32 + ni*8 + q4*2;
        int d0 = warp_m*16 + gid;
        atomicAdd(&dst[d0*64 + e],     acc[ni][0]);
        atomicAdd(&dst[d0*64 + e + 1], acc[ni][1]);
        atomicAdd(&dst[(d0+8)*64 + e],     acc[ni][2]);
        atomicAdd(&dst[(d0+8)*64 + e + 1], acc[ni][3]);
    }
}

// ---------------- 6: softmax with temperature and fused L2-norm scaling --------
__global__ void k_softmax(const float* __restrict__ temp){
    int bh = blockIdx.x;
    int d = threadIdx.x;
    float invq = 1.f / fmaxf(sqrtf(g_sqq[bh*64 + d]), 1e-12f);
    float t = temp[bh & 3] * invq;
    float* row = g_attn + (size_t)bh * HD * HD + d * HD;
    float l[64];
    float m = -1e30f;
    #pragma unroll
    for (int e = 0; e < 64; e++){
        float invk = 1.f / fmaxf(sqrtf(g_sqk[bh*64 + e]), 1e-12f);
        l[e] = row[e] * t * invk;
        m = fmaxf(m, l[e]);
    }
    float s = 0.f;
    #pragma unroll
    for (int e = 0; e < 64; e++){ float v = expf(l[e] - m); l[e] = v; s += v; }
    float inv = 1.f / s;
    #pragma unroll
    for (int e = 0; e < 64; e++) row[e] = l[e] * inv;
}

// ---------------- 7: attened = attn @ v via mma.sync bf16x3, fused pool --------
// Block: head x 128-n chunk. A = attn [d][e] (conv to bf16), B = v [e][n] trans.
#define AVT 272   // v smem row stride bytes (128 bf16 + pad)
#define AVAH 0
#define AVAL 9216
#define AVVH 18432
#define AVVL 35840
#define AV_SMEM 53248
__global__ void __launch_bounds__(256) k_attn_v_mma(){
    extern __shared__ char sm[];
    uint32_t sb = smem_u32(sm);
    int tid = threadIdx.x, wid = tid >> 5, lid = tid & 31;
    int warp_m = wid >> 1, warp_n = wid & 1;
    int bh = blockIdx.y;
    int bb = bh >> 2, h = bh & 3;
    int n0 = blockIdx.x * 128;

    // stage attn (64x64 fp32 -> bf16 hi/lo, row stride 144B)
    {
        int d = tid >> 2, e0 = (tid & 3)*16;
        const float* src = g_attn + (size_t)bh*HD*HD + d*64 + e0;
        uint32_t hp[4], lp[4];
        #pragma unroll
        for (int j = 0; j < 8; j++){
            float2 v = *(const float2*)&src[j*2];
            __nv_bfloat16 h0,l0,h1,l1;
            split_bf(v.x,h0,l0); split_bf(v.y,h1,l1);
            ((uint32_t*)hp)[0] = 0; // placeholder avoided below
            hp[j>>1] = (j&1) ? (hp[j>>1] & 0xFFFFFFFFu, (hp[j>>1])) : hp[j>>1];
            // build directly:
            if ((j&1)==0){ hp[j>>1] = pack_bf2(h0,h1); lp[j>>1] = pack_bf2(l0,l1); }
            else { /* unreachable pattern */ }
        }
        // rewrite cleanly: (the above loop form confuses; do straightforward)
        #pragma unroll
        for (int j = 0; j < 4; j++){
            float4 v = *(const float4*)&src[j*4];
            __nv_bfloat16 h0,l0,h1,l1,h2,l2,h3,l3;
            split_bf(v.x,h0,l0); split_bf(v.y,h1,l1);
            split_bf(v.z,h2,l2); split_bf(v.w,h3,l3);
            hp[j] = pack_bf2(h0,h1); lp[j] = pack_bf2(l0,l1);
            uint32_t hq = pack_bf2(h2,h3), lq = pack_bf2(l2,l3);
            uint32_t so = d*AQT + e0*2 + j*8;
            *(uint32_t*)(sm + AVAH + so)     = hp[j];
            *(uint32_t*)(sm + AVAH + so + 4) = hq;
            *(uint32_t*)(sm + AVAL + so)     = lp[j];
            *(uint32_t*)(sm + AVAL + so + 4) = lq;
        }
    }
    // stage v (64 x 128 fp32 -> bf16 hi/lo, row stride 272B)
    {
        int e = tid >> 2, c0 = (tid & 3)*32;
        const float* src = g_v + ((size_t)(bb*Cc + h*64 + e))*Nn + n0 + c0;
        #pragma unroll
        for (int j = 0; j < 8; j++){
            float4 v = *(const float4*)&src[j*4];
            __nv_bfloat16 h0,l0,h1,l1,h2,l2,h3,l3;
            split_bf(v.x,h0,l0); split_bf(v.y,h1,l1);
            split_bf(v.z,h2,l2); split_bf(v.w,h3,l3);
            uint32_t so = e*AVT + c0*2 + j*8;
            *(uint32_t*)(sm + AVVH + so)     = pack_bf2(h0,h1);
            *(uint32_t*)(sm + AVVH + so + 4) = pack_bf2(h2,h3);
            *(uint32_t*)(sm + AVVL + so)     = pack_bf2(l0,l1);
            *(uint32_t*)(sm + AVVL + so + 4) = pack_bf2(l2,l3);
        }
    }
    __syncthreads();

    uint32_t aAo = (uint32_t)((warp_m*16 + (lid & 7) + ((lid >> 3) & 1)*8)*AQT + ((lid >> 4) & 1)*16);
    uint32_t aBo = (uint32_t)(((lid & 7) + ((lid >> 3) & 1)*8)*AVT + warp_n*128 + ((lid >> 4) & 1)*16);

    float acc[8][4] = {};
    #pragma unroll
    for (int ks = 0; ks < 4; ks++){
        uint32_t kro = (uint32_t)(ks*16)*AVT;
        uint32_t bh_[16], bl_[16], arh[4], arl[4];
        #pragma unroll
        for (int j = 0; j < 4; j++){
            ldmx4t(bh_ + j*4, sb + AVVH + aBo + kro + j*32);
            ldmx4t(bl_ + j*4, sb + AVVL + aBo + kro + j*32);
        }
        ldmx4(arh, sb + AVAH + aAo + ks*32);
        ldmx4(arl, sb + AVAL + aAo + ks*32);
        #pragma unroll
        for (int ni = 0; ni < 8; ni++) mma_bf16(acc[ni], arh, bh_[ni*2], bh_[ni*2+1]);
        #pragma unroll
        for (int ni = 0; ni < 8; ni++) mma_bf16(acc[ni], arh, bl_[ni*2], bl_[ni*2+1]);
        #pragma unroll
        for (int ni = 0; ni < 8; ni++) mma_bf16(acc[ni], arl, bh_[ni*2], bh_[ni*2+1]);
    }

    // epilogue: write attened (B,C,N) + pool partial sums
    int gid = lid >> 2, q4 = lid & 3;
    int d0 = warp_m*16 + gid;
    size_t row0 = ((size_t)(bb*Cc + h*64 + d0)) * Nn;
    size_t row1 = ((size_t)(bb*Cc + h*64 + d0 + 8)) * Nn;
    float s0 = 0.f, s1 = 0.f;
    #pragma unroll
    for (int ni = 0; ni < 8; ni++){
        int n = n0 + warp_n*64 + ni*8 + q4*2;
        *(float2*)&g_att[row0 + n] = make_float2(acc[ni][0], acc[ni][1]);
        *(float2*)&g_att[row1 + n] = make_float2(acc[ni][2], acc[ni][3]);
        s0 += acc[ni][0] + acc[ni][1];
        s1 += acc[ni][2] + acc[ni][3];
    }
    s0 += __shfl_xor_sync(0xFFFFFFFF, s0, 1);
    s0 += __shfl_xor_sync(0xFFFFFFFF, s0, 2);
    s1 += __shfl_xor_sync(0xFFFFFFFF, s1, 1);
    s1 += __shfl_xor_sync(0xFFFFFFFF, s1, 2);
    if (q4 == 0){
        atomicAdd(&g_pool[bb*Cc + h*64 + d0], s0);
        atomicAdd(&g_pool[bb*Cc + h*64 + d0 + 8], s1);
    }
}

// ---------------- 8: depthwise 3x3 conv + GELU on v (B,C,H,W) ------------------
__global__ void k_dwconv(const float* __restrict__ w, const float* __restrict__ bias){
    int bc = blockIdx.x;
    int c  = bc & (Cc-1);
    const float* plane = g_v + (size_t)bc * Nn;
    float wk[9];
    #pragma unroll
    for (int i = 0; i < 9; i++) wk[i] = w[c*9 + i];
    float bb = bias[c];
    for (int p = threadIdx.x; p < Nn; p += 256){
        int y = p >> 6, x = p & 63;
        float s = bb;
        #pragma unroll
        for (int dy = -1; dy <= 1; dy++){
            int yy = y + dy;
            if (yy < 0 || yy >= Hh) continue;
            #pragma unroll
            for (int dx = -1; dx <= 1; dx++){
                int xx = x + dx;
                if (xx < 0 || xx >= Ww) continue;
                s += plane[yy*Ww + xx] * wk[(dy+1)*3 + dx + 1];
            }
        }
        g_conv[(size_t)bc * Nn + p] = gelu_f(s);
    }
}

// ---------------- 9: channel interaction SE -> gc = sigmoid(map) ---------------
__global__ void k_channel_mlp(const float* __restrict__ w1, const float* __restrict__ b1,
                              const float* __restrict__ w2, const float* __restrict__ b2){
    int bb = blockIdx.x;
    int tid = threadIdx.x;
    __shared__ float sp[256];
    __shared__ float h1[32];
    sp[tid] = g_pool[bb*Cc + tid] * (1.f / Nn);
    __syncthreads();
    if (tid < 32){
        float a = b1[tid];
        for (int c = 0; c < 256; c++) a += sp[c] * w1[tid*256 + c];
        h1[tid] = gelu_f(a);
    }
    __syncthreads();
    float a = b2[tid];
    #pragma unroll
    for (int j = 0; j < 32; j++) a += h1[j] * w2[tid*32 + j];
    g_gc[bb*Cc + tid] = sigmoid_f(a);
}

// ---------------- 10: spatial interaction -> gs = sigmoid(map) -----------------
__global__ void k_spatial(const float* __restrict__ w1, const float* __restrict__ b1,
                          const float* __restrict__ w2, const float* __restrict__ b2){
    int bb = blockIdx.x >> 4;
    int n  = (blockIdx.x & 15) * 256 + threadIdx.x;
    __shared__ float sw1[16*256];
    for (int i = threadIdx.x; i < 16*256; i += 256) sw1[i] = w1[i];
    __syncthreads();
    float acc[16];
    #pragma unroll
    for (int o = 0; o < 16; o++) acc[o] = b1[o];
    const float* cb = g_conv + (size_t)bb * Cc * Nn + n;
    for (int c = 0; c < 256; c++){
        float x = cb[(size_t)c * Nn];
        #pragma unroll
        for (int o = 0; o < 16; o++) acc[o] += x * sw1[o*256 + c];
    }
    float sm = b2[0];
    #pragma unroll
    for (int o = 0; o < 16; o++) sm += gelu_f(acc[o]) * w2[o];
    g_gs[bb*Nn + n] = sigmoid_f(sm);
}

// ---------------- 11: proj GEMM via mma.sync bf16x3, fused gating ---------------
#define PAH 0
#define PAL 10240
#define PBH 20480
#define PBL 29184
#define PBT 272
__global__ void __launch_bounds__(256) k_proj_mma(const float* __restrict__ bias,
                                                  float* __restrict__ out){
    __shared__ __align__(16) char sm[37888];
    uint32_t sb = smem_u32(sm);
    int tid = threadIdx.x, wid = tid >> 5, lid = tid & 31;
    int warp_m = wid >> 2, warp_n = wid & 3;
    int cblk = blockIdx.x * 128;         // o block
    int bn0  = blockIdx.y * 128;
    int bb = bn0 >> 12, n0 = bn0 & (Nn-1);

    int gr = tid >> 1, ghf = tid & 1;
    const char* pah = (const char*)(g_wP_hi + (size_t)(cblk + gr)*256) + ghf*32;
    const char* pal = (const char*)(g_wP_lo + (size_t)(cblk + gr)*256) + ghf*32;
    char* dA = sm + gr*80 + ghf*32;

    int cr = tid >> 3, ncb = (tid & 7) * 16;
    const float* At = g_att  + (size_t)(bb*Cc) * Nn + n0 + ncb;
    const float* Cv = g_conv + (size_t)(bb*Cc) * Nn + n0 + ncb;
    float4 gsr[4];
    #pragma unroll
    for (int j = 0; j < 4; j++) gsr[j] = *(const float4*)&g_gs[bb*Nn + n0 + ncb + j*4];
    char* dBh = sm + PBH + cr*PBT + ncb*2;
    char* dBl = sm + PBL + cr*PBT + ncb*2;

    uint32_t aAo = (uint32_t)((warp_m*64 + (lid & 7) + ((lid >> 3) & 1)*8)*80 + ((lid >> 4) & 1)*16);
    uint32_t aBo = (uint32_t)(((lid & 7) + ((lid >> 3) & 1)*8)*PBT + warp_n*64 + ((lid >> 4) & 1)*16);

    float acc[4][4][4] = {};

    #pragma unroll 1
    for (int kc = 0; kc < 8; kc++){
        int c0 = kc * 32;
        #pragma unroll
        for (int j = 0; j < 2; j++){
            *(uint4*)(dA + PAH + j*16) = *(const uint4*)(pah + c0*2 + j*16);
            *(uint4*)(dA + PAL + j*16) = *(const uint4*)(pal + c0*2 + j*16);
        }
        {
            float gc = g_gc[bb*Cc + c0 + cr];
            const float* at = At + (size_t)(c0 + cr) * Nn;
            const float* cv = Cv + (size_t)(c0 + cr) * Nn;
            #pragma unroll
            for (int j = 0; j < 4; j++){
                float4 a = ((const float4*)at)[j];
                float4 c = ((const float4*)cv)[j];
                float4 g = gsr[j];
                float v0 = a.x*g.x + c.x*gc, v1 = a.y*g.y + c.y*gc;
                float v2 = a.z*g.z + c.z*gc, v3 = a.w*g.w + c.w*gc;
                __nv_bfloat16 h0,l0,h1,l1,h2,l2,h3,l3;
                split_bf(v0,h0,l0); split_bf(v1,h1,l1);
                split_bf(v2,h2,l2); split_bf(v3,h3,l3);
                *(uint2*)(dBh + j*8) = make_uint2(pack_bf2(h0,h1), pack_bf2(h2,h3));
                *(uint2*)(dBl + j*8) = make_uint2(pack_bf2(l0,l1), pack_bf2(l2,l3));
            }
        }
        __syncthreads();
        #pragma unroll
        for (int ks = 0; ks < 2; ks++){
            uint32_t kro = (uint32_t)(ks*16)*PBT;
            uint32_t bh[8], bl[8], arh[4], arl[4];
            ldmx4t(bh,     sb + PBH + aBo + kro);
            ldmx4t(bh + 4, sb + PBH + aBo + kro + 32);
            ldmx4t(bl,     sb + PBL + aBo + kro);
            ldmx4t(bl + 4, sb + PBL + aBo + kro + 32);
            uint32_t kofs = ks*32;
            #pragma unroll
            for (int mi = 0; mi < 4; mi++){
                ldmx4(arh, sb + PAH + aAo + kofs + (uint32_t)(mi*16)*80);
                ldmx4(arl, sb + PAL + aAo + kofs + (uint32_t)(mi*16)*80);
                #pragma unroll
                for (int ni = 0; ni < 4; ni++) mma_bf16(acc[mi][ni], arh, bh[ni*2], bh[ni*2+1]);
                #pragma unroll
                for (int ni = 0; ni < 4; ni++) mma_bf16(acc[mi][ni], arh, bl[ni*2], bl[ni*2+1]);
                #pragma unroll
                for (int ni = 0; ni < 4; ni++) mma_bf16(acc[mi][ni], arl, bh[ni*2], bh[ni*2+1]);
            }
        }
        __syncthreads();
    }

    int gid = lid >> 2, q4 = lid & 3;
    int obase = cblk + warp_m*64 + gid;
    #pragma unroll
    for (int mi = 0; mi < 4; mi++){
        int o0 = obase + mi*16;
        float bo0 = bias[o0], bo1 = bias[o0 + 8];
        float* r0 = out + ((size_t)(bb*Cc + o0)) * Nn;
        float* r1 = out + ((size_t)(bb*Cc + o0 + 8)) * Nn;
        #pragma unroll
        for (int ni = 0; ni < 4; ni++){
            int n = n0 + warp_n*32 + ni*8 + q4*2;
            *(float2*)&r0[n] = make_float2(acc[mi][ni][0] + bo0, acc[mi][ni][1] + bo0);
            *(float2*)&r1[n] = make_float2(acc[mi][ni][2] + bo1, acc[mi][ni][3] + bo1);
        }
    }
}

// =================================================================================
extern "C" void kernel_launch(void* const* d_in, const int* in_sizes, int n_in,
                              void* d_out, int out_size){
    const float* x     = (const float*)d_in[0];
    const float* ln_g  = (const float*)d_in[1];
    const float* ln_b  = (const float*)d_in[2];
    const float* w_qkv = (const float*)d_in[3];
    const float* w_q   = (const float*)d_in[4];
    const float* b_q   = (const float*)d_in[5];
    const float* temp  = (const float*)d_in[6];
    const float* dw_w  = (const float*)d_in[7];
    const float* dw_b  = (const float*)d_in[8];
    const float* ci_w1 = (const float*)d_in[9];
    const float* ci_b1 = (const float*)d_in[10];
    const float* ci_w2 = (const float*)d_in[11];
    const float* ci_b2 = (const float*)d_in[12];
    const float* si_w1 = (const float*)d_in[13];
    const float* si_b1 = (const float*)d_in[14];
    const float* si_w2 = (const float*)d_in[15];
    const float* si_b2 = (const float*)d_in[16];
    const float* pj_w  = (const float*)d_in[17];
    const float* pj_b  = (const float*)d_in[18];
    float* out = (float*)d_out;

    cudaFuncSetAttribute(k_qkv_mma, cudaFuncAttributeMaxDynamicSharedMemorySize, QKV_SMEM);
    cudaFuncSetAttribute(k_attn_v_mma, cudaFuncAttributeMaxDynamicSharedMemorySize, AV_SMEM);

    k_zero<<<512, 256>>>();
    k_layernorm<<<Bq*(Nn/32), 256>>>(x, ln_g, ln_b);
    k_buildW<<<Cc, 256>>>(w_qkv, w_q);
    k_buildP<<<Cc, 256>>>(pj_w);
    k_qkv_mma<<<dim3(6, BN/128), 256, QKV_SMEM>>>(b_q);
    k_attn_qk_mma<<<dim3(8, Bq*NH), 256>>>();
    k_softmax<<<Bq*NH, 64>>>(temp);
    k_attn_v_mma<<<dim3(Nn/128, Bq*NH), 256, AV_SMEM>>>();
    k_dwconv<<<Bq*Cc, 256>>>(dw_w, dw_b);
    k_spatial<<<Bq*16, 256>>>(si_w1, si_b1, si_w2, si_b2);
    k_channel_mlp<<<Bq, 256>>>(ci_w1, ci_b1, ci_w2, ci_b2);
    k_proj_mma<<<dim3(2, BN/128), 256>>>(pj_b, out);
}

// round 8
// speedup vs baseline: 3.0158x; 1.1569x over previous
#include <cuda_runtime.h>
#include <cuda_fp16.h>
#include <math.h>
#include <stdint.h>

// Problem constants
#define Bq   8
#define Cc   256
#define Hh   64
#define Ww   64
#define Nn   4096            // H*W
#define NH   4
#define HD   64
#define BN   (Bq*Nn)         // 32768

// ---------------- scratch (device globals; no allocation allowed) -------------
__device__ __half g_xn_h[BN*Cc];     // layernormed x (fp16 rounded), [b*N+n][c]
__device__ __half g_wB_h[768*Cc];    // folded qkv weight [o][c], fp16 hi
__device__ __half g_wB_l[768*Cc];    // fp16 lo residual
__device__ __half g_wP_h[Cc*Cc];     // proj weight transposed [o][c], fp16 (rounded)
__device__ __half g_qh[Bq*Cc*Nn];    // q fp16 (rounded), row = bh*64+d, col n
__device__ __half g_kh[Bq*Cc*Nn];    // k fp16 hi
__device__ __half g_kl[Bq*Cc*Nn];    // k fp16 lo
__device__ float g_v   [Bq*NH*HD*Nn];  // (B,nh,hd,N) == (B,C,N) head-major
__device__ float g_att [Bq*Cc*Nn];     // attened_x stored (B,C,N)
__device__ float g_conv[Bq*Cc*Nn];     // gelu(dwconv), (B,C,N)
__device__ float g_attn[Bq*NH*HD*HD];  // (B,nh,hd,hd)
__device__ float g_pool[Bq*Cc];        // sum over n of attened
__device__ float g_gc  [Bq*Cc];        // sigmoid(channel_map)
__device__ float g_gs  [Bq*Nn];        // sigmoid(spatial_map)
__device__ float g_sqq [Bq*Cc];        // sum of squares per q row
__device__ float g_sqk [Bq*Cc];

__device__ __forceinline__ float gelu_f(float x){
    return 0.5f * x * (1.0f + erff(x * 0.70710678118654752f));
}
__device__ __forceinline__ float sigmoid_f(float x){
    return 1.0f / (1.0f + expf(-x));
}
__device__ __forceinline__ uint32_t smem_u32(const void* p){
    uint32_t a;
    asm("{ .reg .u64 t; cvta.to.shared.u64 t, %1; cvt.u32.u64 %0, t; }" : "=r"(a) : "l"(p));
    return a;
}
__device__ __forceinline__ void ldmx4(uint32_t* r, uint32_t addr){
    asm volatile("ldmatrix.sync.aligned.m8n8.x4.shared.b16 {%0,%1,%2,%3}, [%4];"
                 : "=r"(r[0]), "=r"(r[1]), "=r"(r[2]), "=r"(r[3]) : "r"(addr));
}
__device__ __forceinline__ void ldmx4t(uint32_t* r, uint32_t addr){
    asm volatile("ldmatrix.sync.aligned.m8n8.x4.trans.shared.b16 {%0,%1,%2,%3}, [%4];"
                 : "=r"(r[0]), "=r"(r[1]), "=r"(r[2]), "=r"(r[3]) : "r"(addr));
}
__device__ __forceinline__ void mma_f16(float* d, const uint32_t* a, uint32_t b0, uint32_t b1){
    asm volatile(
        "mma.sync.aligned.m16n8k16.row.col.f32.f16.f16.f32 "
        "{%0,%1,%2,%3}, {%4,%5,%6,%7}, {%8,%9}, {%0,%1,%2,%3};"
        : "+f"(d[0]), "+f"(d[1]), "+f"(d[2]), "+f"(d[3])
        : "r"(a[0]), "r"(a[1]), "r"(a[2]), "r"(a[3]), "r"(b0), "r"(b1));
}
__device__ __forceinline__ void cpa16(uint32_t d, const void* s){
    asm volatile("cp.async.cg.shared.global [%0], [%1], 16;" :: "r"(d), "l"(s));
}
__device__ __forceinline__ uint32_t pack_h2(__half a, __half b){
    return ((uint32_t)__half_as_ushort(b) << 16) | (uint32_t)__half_as_ushort(a);
}
__device__ __forceinline__ void split_h(float v, __half& h, __half& l){
    h = __float2half(v);
    l = __float2half(v - __half2float(h));
}

// qkv pipeline smem: k-chunk 32 fp16 = 64B rows padded to 80B; 3 arrays/stage, 3 stages
#define QT    80
#define QSTG  30720
#define QAH   0
#define QAL   10240
#define QBH   20480
#define QKV_SMEM 92160

// ---------------- 0: zero the accumulated buffers -----------------------------
__global__ void k_zero(){
    int i = blockIdx.x * 256 + threadIdx.x;
    if (i < Bq*NH*HD*HD) g_attn[i] = 0.f;
    if (i < Bq*Cc){ g_pool[i] = 0.f; g_sqq[i] = 0.f; g_sqk[i] = 0.f; }
}

// ---------------- 1: LayerNorm over C -> g_xn_h fp16, layout [b*N+n][c] --------
__global__ void k_layernorm(const float* __restrict__ x,
                            const float* __restrict__ g,
                            const float* __restrict__ b){
    __shared__ float sx[256][33];
    __shared__ float spart[8][32];
    __shared__ float smu[32], sinv[32];
    int bb = blockIdx.x >> 7;
    int n0 = (blockIdx.x & 127) * 32;
    int tid = threadIdx.x;
    int nl = tid & 31, part = tid >> 5;
    const float* xb = x + (size_t)bb * Cc * Nn + n0;
    #pragma unroll
    for (int c0 = 0; c0 < 256; c0 += 8)
        sx[c0 + part][nl] = xb[(size_t)(c0 + part) * Nn + nl];
    __syncthreads();
    float s = 0.f, s2 = 0.f;
    #pragma unroll
    for (int i = 0; i < 32; i++){ float v = sx[part*32 + i][nl]; s += v; s2 += v*v; }
    spart[part][nl] = s;
    __syncthreads();
    if (part == 0){ float t = 0.f; for (int p = 0; p < 8; p++) t += spart[p][nl]; smu[nl] = t * (1.f/256.f); }
    __syncthreads();
    spart[part][nl] = s2;
    __syncthreads();
    if (part == 0){
        float t = 0.f; for (int p = 0; p < 8; p++) t += spart[p][nl];
        float mu = smu[nl];
        sinv[nl] = rsqrtf(t * (1.f/256.f) - mu*mu + 1e-5f);
    }
    __syncthreads();
    float gc = g[tid], bc = b[tid];
    for (int n = 0; n < 32; n++){
        float val = (sx[tid][n] - smu[n]) * sinv[n] * gc + bc;
        g_xn_h[((size_t)(bb * Nn) + n0 + n) * 256 + tid] = __float2half(val);
    }
}

// ---------------- 1b: fold w_q into qkv weight -> g_wB_h/l [o][c] fp16 ---------
__global__ void k_buildW(const float* __restrict__ wqkv, const float* __restrict__ wq){
    __shared__ float srow[768];
    __shared__ float swq[64*64];
    int c = blockIdx.x;
    int tid = threadIdx.x;
    for (int i = tid; i < 768; i += 256)  srow[i] = wqkv[(size_t)c*768 + i];
    for (int i = tid; i < 4096; i += 256) swq[i]  = wq[i];
    __syncthreads();
    int h = tid >> 6, d = tid & 63;
    float s = 0.f;
    #pragma unroll 16
    for (int e = 0; e < 64; e++) s += srow[h*64 + e] * swq[e*64 + d];
    float vals[3] = { s, srow[256 + tid], srow[512 + tid] };
    #pragma unroll
    for (int t = 0; t < 3; t++){
        int o = t*256 + tid;
        __half hi, lo; split_h(vals[t], hi, lo);
        g_wB_h[(size_t)o*256 + c] = hi;
        g_wB_l[(size_t)o*256 + c] = lo;
    }
}

// ---------------- 1c: transpose proj weight -> g_wP_h [o][c] fp16 --------------
__global__ void k_buildP(const float* __restrict__ w){
    int o = blockIdx.x, c = threadIdx.x;
    g_wP_h[(size_t)o*256 + c] = __float2half(w[(size_t)c*256 + o]);
}

// ---------------- 2: qkv GEMM via mma.sync fp16x2 (A=w hi+lo, B=xn rounded) ----
// 3-stage cp.async pipeline, k-chunks of 32.
#define QKV_ISSUE(kc_) do{ \
    uint32_t d_ = drow + ((kc_) % 3) * QSTG; \
    size_t go_ = (size_t)(kc_) * 64; \
    cpa16(d_ + QAH,      pwh + go_);      cpa16(d_ + QAH + 16, pwh + go_ + 16); \
    cpa16(d_ + QAL,      pwl + go_);      cpa16(d_ + QAL + 16, pwl + go_ + 16); \
    cpa16(d_ + QBH,      pxh + go_);      cpa16(d_ + QBH + 16, pxh + go_ + 16); \
    asm volatile("cp.async.commit_group;"); } while(0)

__global__ void __launch_bounds__(256) k_qkv_mma(const float* __restrict__ bq){
    extern __shared__ char dsm[];
    uint32_t sb = smem_u32(dsm);
    int tid = threadIdx.x, wid = tid >> 5, lid = tid & 31;
    int warp_m = wid >> 2, warp_n = wid & 3;
    int cblk = blockIdx.x * 128;
    int bn0  = blockIdx.y * 128;
    int bb = bn0 >> 12, n0 = bn0 & (Nn-1);

    int gr = tid >> 1, ghf = tid & 1;
    const char* pwh = (const char*)(g_wB_h + (size_t)(cblk + gr)*256) + ghf*32;
    const char* pwl = (const char*)(g_wB_l + (size_t)(cblk + gr)*256) + ghf*32;
    const char* pxh = (const char*)(g_xn_h + (size_t)(bn0  + gr)*256) + ghf*32;
    uint32_t drow = sb + gr*QT + ghf*32;

    QKV_ISSUE(0);
    QKV_ISSUE(1);

    uint32_t aAo = (uint32_t)((warp_m*64 + (lid & 7) + ((lid >> 3) & 1)*8)*QT + ((lid >> 4) & 1)*16);
    uint32_t aBo = (uint32_t)((warp_n*32 + (lid & 7) + ((lid >> 4) & 1)*8)*QT + ((lid >> 3) & 1)*16);

    float acc[4][4][4] = {};

    #pragma unroll 1
    for (int kc = 0; kc < 8; kc++){
        if (kc + 2 < 8){
            QKV_ISSUE(kc + 2);
            asm volatile("cp.async.wait_group 2;");
        } else if (kc == 6){
            asm volatile("cp.async.wait_group 1;");
        } else {
            asm volatile("cp.async.wait_group 0;");
        }
        __syncthreads();
        uint32_t base = sb + (kc % 3)*QSTG;
        #pragma unroll
        for (int ks = 0; ks < 2; ks++){
            uint32_t kofs = ks*32;
            uint32_t bh[8], arh[4], arl[4];
            ldmx4(bh,     base + QBH + aBo + kofs);
            ldmx4(bh + 4, base + QBH + aBo + kofs + 16*QT);
            #pragma unroll
            for (int mi = 0; mi < 4; mi++){
                ldmx4(arh, base + QAH + aAo + kofs + (uint32_t)(mi*16)*QT);
                ldmx4(arl, base + QAL + aAo + kofs + (uint32_t)(mi*16)*QT);
                #pragma unroll
                for (int ni = 0; ni < 4; ni++) mma_f16(acc[mi][ni], arh, bh[ni*2], bh[ni*2+1]);
                #pragma unroll
                for (int ni = 0; ni < 4; ni++) mma_f16(acc[mi][ni], arl, bh[ni*2], bh[ni*2+1]);
            }
        }
        __syncthreads();
    }

    // epilogue: q -> fp16 hi (+norms), k -> fp16 hi/lo (+norms), v -> fp32
    int gid = lid >> 2, q4 = lid & 3;
    int obase = cblk + warp_m*64 + gid;
    int ot = obase >> 8;                 // 0=q,1=k,2=v (constant per block)
    #pragma unroll
    for (int mi = 0; mi < 4; mi++){
        int o0 = obase + mi*16;
        float bo0 = (ot == 0) ? bq[o0 & 63] : 0.f;
        float bo1 = (ot == 0) ? bq[(o0 + 8) & 63] : 0.f;
        size_t row0 = ((size_t)(bb*Cc + (o0 & 255))) * Nn;
        size_t row1 = ((size_t)(bb*Cc + ((o0 + 8) & 255))) * Nn;
        float s0 = 0.f, s1 = 0.f;
        #pragma unroll
        for (int ni = 0; ni < 4; ni++){
            int n = n0 + warp_n*32 + ni*8 + q4*2;
            float v0 = acc[mi][ni][0] + bo0, v1 = acc[mi][ni][1] + bo0;
            float v2 = acc[mi][ni][2] + bo1, v3 = acc[mi][ni][3] + bo1;
            if (ot == 2){
                *(float2*)&g_v[row0 + n] = make_float2(v0, v1);
                *(float2*)&g_v[row1 + n] = make_float2(v2, v3);
            } else if (ot == 0){
                *(uint32_t*)&g_qh[row0 + n] = pack_h2(__float2half(v0), __float2half(v1));
                *(uint32_t*)&g_qh[row1 + n] = pack_h2(__float2half(v2), __float2half(v3));
                s0 += v0*v0 + v1*v1;
                s1 += v2*v2 + v3*v3;
            } else {
                __half h0,l0,h1,l1,h2,l2,h3,l3;
                split_h(v0,h0,l0); split_h(v1,h1,l1);
                split_h(v2,h2,l2); split_h(v3,h3,l3);
                *(uint32_t*)&g_kh[row0 + n] = pack_h2(h0, h1);
                *(uint32_t*)&g_kl[row0 + n] = pack_h2(l0, l1);
                *(uint32_t*)&g_kh[row1 + n] = pack_h2(h2, h3);
                *(uint32_t*)&g_kl[row1 + n] = pack_h2(l2, l3);
                s0 += v0*v0 + v1*v1;
                s1 += v2*v2 + v3*v3;
            }
        }
        if (ot < 2){
            s0 += __shfl_xor_sync(0xFFFFFFFF, s0, 1);
            s0 += __shfl_xor_sync(0xFFFFFFFF, s0, 2);
            s1 += __shfl_xor_sync(0xFFFFFFFF, s1, 1);
            s1 += __shfl_xor_sync(0xFFFFFFFF, s1, 2);
            if (q4 == 0){
                float* sq = ot ? g_sqk : g_sqq;
                atomicAdd(&sq[bb*Cc + (o0 & 255)], s0);
                atomicAdd(&sq[bb*Cc + ((o0 + 8) & 255)], s1);
            }
        }
    }
}

// ---------------- 5: attn = q @ k^T via mma.sync fp16x2 (atomic accumulate) ----
// A = q (rounded hi), B = k (hi+lo). Block: one head x 512-n chunk.
#define AQT 144   // 72 fp16 row stride (bytes)
__global__ void __launch_bounds__(256) k_attn_qk_mma(){
    __shared__ __align__(16) char sm[3*64*AQT];   // qh, kh, kl tiles (64x64)
    uint32_t sb = smem_u32(sm);
    const int OQH = 0, OKH = 64*AQT, OKL = 2*64*AQT;
    int tid = threadIdx.x, wid = tid >> 5, lid = tid & 31;
    int warp_m = wid >> 1, warp_n = wid & 1;
    int bh = blockIdx.y;
    int nbase = blockIdx.x * 512;

    uint32_t aAo = (uint32_t)((warp_m*16 + (lid & 7) + ((lid >> 3) & 1)*8)*AQT + ((lid >> 4) & 1)*16);
    uint32_t aBo = (uint32_t)((warp_n*32 + (lid & 7) + ((lid >> 4) & 1)*8)*AQT + ((lid >> 3) & 1)*16);

    float acc[4][4] = {};

    #pragma unroll 1
    for (int kc = 0; kc < 8; kc++){
        int nb = nbase + kc*64;
        #pragma unroll
        for (int i = 0; i < 2; i++){
            int idx = tid*2 + i;
            int r = idx >> 3, c16 = idx & 7;
            size_t go = ((size_t)(bh*64 + r))*Nn + nb + c16*8;
            uint32_t so = r*AQT + c16*16;
            *(uint4*)(sm + OQH + so) = *(const uint4*)(g_qh + go);
            *(uint4*)(sm + OKH + so) = *(const uint4*)(g_kh + go);
            *(uint4*)(sm + OKL + so) = *(const uint4*)(g_kl + go);
        }
        __syncthreads();
        #pragma unroll
        for (int ks = 0; ks < 4; ks++){
            uint32_t kofs = ks*32;
            uint32_t bh_[8], bl_[8], arh[4];
            ldmx4(bh_,     sb + OKH + aBo + kofs);
            ldmx4(bh_ + 4, sb + OKH + aBo + kofs + 16*AQT);
            ldmx4(bl_,     sb + OKL + aBo + kofs);
            ldmx4(bl_ + 4, sb + OKL + aBo + kofs + 16*AQT);
            ldmx4(arh, sb + OQH + aAo + kofs);
            #pragma unroll
            for (int ni = 0; ni < 4; ni++) mma_f16(acc[ni], arh, bh_[ni*2], bh_[ni*2+1]);
            #pragma unroll
            for (int ni = 0; ni < 4; ni++) mma_f16(acc[ni], arh, bl_[ni*2], bl_[ni*2+1]);
        }
        __syncthreads();
    }

    int gid = lid >> 2, q4 = lid & 3;
    float* dst = g_attn + (size_t)bh*HD*HD;
    #pragma unroll
    for (int ni = 0; ni < 4; ni++){
        int e = warp_n*32 + ni*8 + q4*2;
        int d0 = warp_m*16 + gid;
        atomicAdd(&dst[d0*64 + e],     acc[ni][0]);
        atomicAdd(&dst[d0*64 + e + 1], acc[ni][1]);
        atomicAdd(&dst[(d0+8)*64 + e],     acc[ni][2]);
        atomicAdd(&dst[(d0+8)*64 + e + 1], acc[ni][3]);
    }
}

// ---------------- 6: softmax with temperature and fused L2-norm scaling --------
__global__ void k_softmax(const float* __restrict__ temp){
    int bh = blockIdx.x;
    int d = threadIdx.x;
    float invq = 1.f / fmaxf(sqrtf(g_sqq[bh*64 + d]), 1e-12f);
    float t = temp[bh & 3] * invq;
    float* row = g_attn + (size_t)bh * HD * HD + d * HD;
    float l[64];
    float m = -1e30f;
    #pragma unroll
    for (int e = 0; e < 64; e++){
        float invk = 1.f / fmaxf(sqrtf(g_sqk[bh*64 + e]), 1e-12f);
        l[e] = row[e] * t * invk;
        m = fmaxf(m, l[e]);
    }
    float s = 0.f;
    #pragma unroll
    for (int e = 0; e < 64; e++){ float v = expf(l[e] - m); l[e] = v; s += v; }
    float inv = 1.f / s;
    #pragma unroll
    for (int e = 0; e < 64; e++) row[e] = l[e] * inv;
}

// ---------------- 7: attened = attn @ v via mma.sync fp16x2, fused pool --------
// A = attn probs (rounded), B = v (split hi+lo in loader, trans ldmatrix).
#define AVT 272   // v smem row stride bytes (128 fp16 + pad)
#define AVAH 0
#define AVVH 9216
#define AVVL 26624
__global__ void __launch_bounds__(256) k_attn_v_mma(){
    __shared__ __align__(16) char sm[44032];
    uint32_t sb = smem_u32(sm);
    int tid = threadIdx.x, wid = tid >> 5, lid = tid & 31;
    int warp_m = wid >> 1, warp_n = wid & 1;
    int bh = blockIdx.y;
    int bb = bh >> 2, h = bh & 3;
    int n0 = blockIdx.x * 128;

    // stage attn (64x64 fp32 -> fp16 rounded, row stride 144B)
    {
        int d = tid >> 2, e0 = (tid & 3)*16;
        const float* src = g_attn + (size_t)bh*HD*HD + d*64 + e0;
        #pragma unroll
        for (int j = 0; j < 4; j++){
            float4 v = *(const float4*)&src[j*4];
            uint32_t so = d*AQT + e0*2 + j*8;
            *(uint32_t*)(sm + AVAH + so)     = pack_h2(__float2half(v.x), __float2half(v.y));
            *(uint32_t*)(sm + AVAH + so + 4) = pack_h2(__float2half(v.z), __float2half(v.w));
        }
    }
    // stage v (64 x 128 fp32 -> fp16 hi/lo, row stride 272B)
    {
        int e = tid >> 2, c0 = (tid & 3)*32;
        const float* src = g_v + ((size_t)(bb*Cc + h*64 + e))*Nn + n0 + c0;
        #pragma unroll
        for (int j = 0; j < 8; j++){
            float4 v = *(const float4*)&src[j*4];
            __half h0,l0,h1,l1,h2,l2,h3,l3;
            split_h(v.x,h0,l0); split_h(v.y,h1,l1);
            split_h(v.z,h2,l2); split_h(v.w,h3,l3);
            uint32_t so = e*AVT + c0*2 + j*8;
            *(uint32_t*)(sm + AVVH + so)     = pack_h2(h0,h1);
            *(uint32_t*)(sm + AVVH + so + 4) = pack_h2(h2,h3);
            *(uint32_t*)(sm + AVVL + so)     = pack_h2(l0,l1);
            *(uint32_t*)(sm + AVVL + so + 4) = pack_h2(l2,l3);
        }
    }
    __syncthreads();

    uint32_t aAo = (uint32_t)((warp_m*16 + (lid & 7) + ((lid >> 3) & 1)*8)*AQT + ((lid >> 4) & 1)*16);
    uint32_t aBo = (uint32_t)(((lid & 7) + ((lid >> 3) & 1)*8)*AVT + warp_n*128 + ((lid >> 4) & 1)*16);

    float acc[8][4] = {};
    #pragma unroll
    for (int ks = 0; ks < 4; ks++){
        uint32_t kro = (uint32_t)(ks*16)*AVT;
        uint32_t bh_[16], bl_[16], arh[4];
        #pragma unroll
        for (int j = 0; j < 4; j++){
            ldmx4t(bh_ + j*4, sb + AVVH + aBo + kro + j*32);
            ldmx4t(bl_ + j*4, sb + AVVL + aBo + kro + j*32);
        }
        ldmx4(arh, sb + AVAH + aAo + ks*32);
        #pragma unroll
        for (int ni = 0; ni < 8; ni++) mma_f16(acc[ni], arh, bh_[ni*2], bh_[ni*2+1]);
        #pragma unroll
        for (int ni = 0; ni < 8; ni++) mma_f16(acc[ni], arh, bl_[ni*2], bl_[ni*2+1]);
    }

    // epilogue: write attened (B,C,N) + pool partial sums
    int gid = lid >> 2, q4 = lid & 3;
    int d0 = warp_m*16 + gid;
    size_t row0 = ((size_t)(bb*Cc + h*64 + d0)) * Nn;
    size_t row1 = ((size_t)(bb*Cc + h*64 + d0 + 8)) * Nn;
    float s0 = 0.f, s1 = 0.f;
    #pragma unroll
    for (int ni = 0; ni < 8; ni++){
        int n = n0 + warp_n*64 + ni*8 + q4*2;
        *(float2*)&g_att[row0 + n] = make_float2(acc[ni][0], acc[ni][1]);
        *(float2*)&g_att[row1 + n] = make_float2(acc[ni][2], acc[ni][3]);
        s0 += acc[ni][0] + acc[ni][1];
        s1 += acc[ni][2] + acc[ni][3];
    }
    s0 += __shfl_xor_sync(0xFFFFFFFF, s0, 1);
    s0 += __shfl_xor_sync(0xFFFFFFFF, s0, 2);
    s1 += __shfl_xor_sync(0xFFFFFFFF, s1, 1);
    s1 += __shfl_xor_sync(0xFFFFFFFF, s1, 2);
    if (q4 == 0){
        atomicAdd(&g_pool[bb*Cc + h*64 + d0], s0);
        atomicAdd(&g_pool[bb*Cc + h*64 + d0 + 8], s1);
    }
}

// ---------------- 8: depthwise 3x3 conv + GELU on v (B,C,H,W) ------------------
__global__ void k_dwconv(const float* __restrict__ w, const float* __restrict__ bias){
    int bc = blockIdx.x;
    int c  = bc & (Cc-1);
    const float* plane = g_v + (size_t)bc * Nn;
    float wk[9];
    #pragma unroll
    for (int i = 0; i < 9; i++) wk[i] = w[c*9 + i];
    float bb = bias[c];
    for (int p = threadIdx.x; p < Nn; p += 256){
        int y = p >> 6, x = p & 63;
        float s = bb;
        #pragma unroll
        for (int dy = -1; dy <= 1; dy++){
            int yy = y + dy;
            if (yy < 0 || yy >= Hh) continue;
            #pragma unroll
            for (int dx = -1; dx <= 1; dx++){
                int xx = x + dx;
                if (xx < 0 || xx >= Ww) continue;
                s += plane[yy*Ww + xx] * wk[(dy+1)*3 + dx + 1];
            }
        }
        g_conv[(size_t)bc * Nn + p] = gelu_f(s);
    }
}

// ---------------- 9: channel interaction SE -> gc = sigmoid(map) ---------------
__global__ void k_channel_mlp(const float* __restrict__ w1, const float* __restrict__ b1,
                              const float* __restrict__ w2, const float* __restrict__ b2){
    int bb = blockIdx.x;
    int tid = threadIdx.x;
    __shared__ float sp[256];
    __shared__ float h1[32];
    sp[tid] = g_pool[bb*Cc + tid] * (1.f / Nn);
    __syncthreads();
    if (tid < 32){
        float a = b1[tid];
        for (int c = 0; c < 256; c++) a += sp[c] * w1[tid*256 + c];
        h1[tid] = gelu_f(a);
    }
    __syncthreads();
    float a = b2[tid];
    #pragma unroll
    for (int j = 0; j < 32; j++) a += h1[j] * w2[tid*32 + j];
    g_gc[bb*Cc + tid] = sigmoid_f(a);
}

// ---------------- 10: spatial interaction -> gs = sigmoid(map) -----------------
__global__ void k_spatial(const float* __restrict__ w1, const float* __restrict__ b1,
                          const float* __restrict__ w2, const float* __restrict__ b2){
    int bb = blockIdx.x >> 4;
    int n  = (blockIdx.x & 15) * 256 + threadIdx.x;
    __shared__ float sw1[16*256];
    for (int i = threadIdx.x; i < 16*256; i += 256) sw1[i] = w1[i];
    __syncthreads();
    float acc[16];
    #pragma unroll
    for (int o = 0; o < 16; o++) acc[o] = b1[o];
    const float* cb = g_conv + (size_t)bb * Cc * Nn + n;
    for (int c = 0; c < 256; c++){
        float x = cb[(size_t)c * Nn];
        #pragma unroll
        for (int o = 0; o < 16; o++) acc[o] += x * sw1[o*256 + c];
    }
    float sm = b2[0];
    #pragma unroll
    for (int o = 0; o < 16; o++) sm += gelu_f(acc[o]) * w2[o];
    g_gs[bb*Nn + n] = sigmoid_f(sm);
}

// ---------------- 11: proj GEMM via mma.sync fp16x2, fused gating ---------------
// A = wP (rounded hi), B = gated act (split hi+lo in loader, trans ldmatrix).
#define PAH 0
#define PBH 10240
#define PBL 18944
#define PBT 272
__global__ void __launch_bounds__(256) k_proj_mma(const float* __restrict__ bias,
                                                  float* __restrict__ out){
    __shared__ __align__(16) char sm[27648];
    uint32_t sb = smem_u32(sm);
    int tid = threadIdx.x, wid = tid >> 5, lid = tid & 31;
    int warp_m = wid >> 2, warp_n = wid & 3;
    int cblk = blockIdx.x * 128;         // o block
    int bn0  = blockIdx.y * 128;
    int bb = bn0 >> 12, n0 = bn0 & (Nn-1);

    int gr = tid >> 1, ghf = tid & 1;
    const char* pah = (const char*)(g_wP_h + (size_t)(cblk + gr)*256) + ghf*32;
    char* dA = sm + gr*80 + ghf*32;

    int cr = tid >> 3, ncb = (tid & 7) * 16;
    const float* At = g_att  + (size_t)(bb*Cc) * Nn + n0 + ncb;
    const float* Cv = g_conv + (size_t)(bb*Cc) * Nn + n0 + ncb;
    float4 gsr[4];
    #pragma unroll
    for (int j = 0; j < 4; j++) gsr[j] = *(const float4*)&g_gs[bb*Nn + n0 + ncb + j*4];
    char* dBh = sm + PBH + cr*PBT + ncb*2;
    char* dBl = sm + PBL + cr*PBT + ncb*2;

    uint32_t aAo = (uint32_t)((warp_m*64 + (lid & 7) + ((lid >> 3) & 1)*8)*80 + ((lid >> 4) & 1)*16);
    uint32_t aBo = (uint32_t)(((lid & 7) + ((lid >> 3) & 1)*8)*PBT + warp_n*64 + ((lid >> 4) & 1)*16);

    float acc[4][4][4] = {};

    #pragma unroll 1
    for (int kc = 0; kc < 8; kc++){
        int c0 = kc * 32;
        #pragma unroll
        for (int j = 0; j < 2; j++)
            *(uint4*)(dA + PAH + j*16) = *(const uint4*)(pah + c0*2 + j*16);
        {
            float gc = g_gc[bb*Cc + c0 + cr];
            const float* at = At + (size_t)(c0 + cr) * Nn;
            const float* cv = Cv + (size_t)(c0 + cr) * Nn;
            #pragma unroll
            for (int j = 0; j < 4; j++){
                float4 a = ((const float4*)at)[j];
                float4 c = ((const float4*)cv)[j];
                float4 g = gsr[j];
                float v0 = a.x*g.x + c.x*gc, v1 = a.y*g.y + c.y*gc;
                float v2 = a.z*g.z + c.z*gc, v3 = a.w*g.w + c.w*gc;
                __half h0,l0,h1,l1,h2,l2,h3,l3;
                split_h(v0,h0,l0); split_h(v1,h1,l1);
                split_h(v2,h2,l2); split_h(v3,h3,l3);
                *(uint2*)(dBh + j*8) = make_uint2(pack_h2(h0,h1), pack_h2(h2,h3));
                *(uint2*)(dBl + j*8) = make_uint2(pack_h2(l0,l1), pack_h2(l2,l3));
            }
        }
        __syncthreads();
        #pragma unroll
        for (int ks = 0; ks < 2; ks++){
            uint32_t kro = (uint32_t)(ks*16)*PBT;
            uint32_t bh[8], bl[8], arh[4];
            ldmx4t(bh,     sb + PBH + aBo + kro);
            ldmx4t(bh + 4, sb + PBH + aBo + kro + 32);
            ldmx4t(bl,     sb + PBL + aBo + kro);
            ldmx4t(bl + 4, sb + PBL + aBo + kro + 32);
            uint32_t kofs = ks*32;
            #pragma unroll
            for (int mi = 0; mi < 4; mi++){
                ldmx4(arh, sb + PAH + aAo + kofs + (uint32_t)(mi*16)*80);
                #pragma unroll
                for (int ni = 0; ni < 4; ni++) mma_f16(acc[mi][ni], arh, bh[ni*2], bh[ni*2+1]);
                #pragma unroll
                for (int ni = 0; ni < 4; ni++) mma_f16(acc[mi][ni], arh, bl[ni*2], bl[ni*2+1]);
            }
        }
        __syncthreads();
    }

    int gid = lid >> 2, q4 = lid & 3;
    int obase = cblk + warp_m*64 + gid;
    #pragma unroll
    for (int mi = 0; mi < 4; mi++){
        int o0 = obase + mi*16;
        float bo0 = bias[o0], bo1 = bias[o0 + 8];
        float* r0 = out + ((size_t)(bb*Cc + o0)) * Nn;
        float* r1 = out + ((size_t)(bb*Cc + o0 + 8)) * Nn;
        #pragma unroll
        for (int ni = 0; ni < 4; ni++){
            int n = n0 + warp_n*32 + ni*8 + q4*2;
            *(float2*)&r0[n] = make_float2(acc[mi][ni][0] + bo0, acc[mi][ni][1] + bo0);
            *(float2*)&r1[n] = make_float2(acc[mi][ni][2] + bo1, acc[mi][ni][3] + bo1);
        }
    }
}

// =================================================================================
extern "C" void kernel_launch(void* const* d_in, const int* in_sizes, int n_in,
                              void* d_out, int out_size){
    const float* x     = (const float*)d_in[0];
    const float* ln_g  = (const float*)d_in[1];
    const float* ln_b  = (const float*)d_in[2];
    const float* w_qkv = (const float*)d_in[3];
    const float* w_q   = (const float*)d_in[4];
    const float* b_q   = (const float*)d_in[5];
    const float* temp  = (const float*)d_in[6];
    const float* dw_w  = (const float*)d_in[7];
    const float* dw_b  = (const float*)d_in[8];
    const float* ci_w1 = (const float*)d_in[9];
    const float* ci_b1 = (const float*)d_in[10];
    const float* ci_w2 = (const float*)d_in[11];
    const float* ci_b2 = (const float*)d_in[12];
    const float* si_w1 = (const float*)d_in[13];
    const float* si_b1 = (const float*)d_in[14];
    const float* si_w2 = (const float*)d_in[15];
    const float* si_b2 = (const float*)d_in[16];
    const float* pj_w  = (const float*)d_in[17];
    const float* pj_b  = (const float*)d_in[18];
    float* out = (float*)d_out;

    cudaFuncSetAttribute(k_qkv_mma, cudaFuncAttributeMaxDynamicSharedMemorySize, QKV_SMEM);

    k_zero<<<512, 256>>>();
    k_layernorm<<<Bq*(Nn/32), 256>>>(x, ln_g, ln_b);
    k_buildW<<<Cc, 256>>>(w_qkv, w_q);
    k_buildP<<<Cc, 256>>>(pj_w);
    k_qkv_mma<<<dim3(6, BN/128), 256, QKV_SMEM>>>(b_q);
    k_attn_qk_mma<<<dim3(8, Bq*NH), 256>>>();
    k_softmax<<<Bq*NH, 64>>>(temp);
    k_attn_v_mma<<<dim3(Nn/128, Bq*NH), 256>>>();
    k_dwconv<<<Bq*Cc, 256>>>(dw_w, dw_b);
    k_spatial<<<Bq*16, 256>>>(si_w1, si_b1, si_w2, si_b2);
    k_channel_mlp<<<Bq, 256>>>(ci_w1, ci_b1, ci_w2, ci_b2);
    k_proj_mma<<<dim3(2, BN/128), 256>>>(pj_b, out);
}

// round 9
// speedup vs baseline: 3.2623x; 1.0817x over previous
#include <cuda_runtime.h>
#include <cuda_fp16.h>
#include <math.h>
#include <stdint.h>

// Problem constants
#define Bq   8
#define Cc   256
#define Hh   64
#define Ww   64
#define Nn   4096            // H*W
#define NH   4
#define HD   64
#define BN   (Bq*Nn)         // 32768

// ---------------- scratch (device globals; no allocation allowed) -------------
__device__ __half g_xn_h[BN*Cc];     // layernormed x (fp16 rounded), [b*N+n][c]
__device__ __half g_wB_h[768*Cc];    // folded qkv weight [o][c], fp16 hi
__device__ __half g_wB_l[768*Cc];    // fp16 lo residual
__device__ __half g_wP_h[Cc*Cc];     // proj weight transposed [o][c], fp16 (rounded)
__device__ __half g_qh[Bq*Cc*Nn];    // q fp16 (rounded), row = bh*64+d, col n
__device__ __half g_kh[Bq*Cc*Nn];    // k fp16 hi
__device__ __half g_kl[Bq*Cc*Nn];    // k fp16 lo
__device__ __half g_v   [Bq*Cc*Nn];  // v fp16, (B,C,N) head-major
__device__ __half g_att [Bq*Cc*Nn];  // attened_x fp16, (B,C,N)
__device__ __half g_conv[Bq*Cc*Nn];  // gelu(dwconv) fp16, (B,C,N)
__device__ float g_attn[Bq*NH*HD*HD];  // (B,nh,hd,hd)
__device__ float g_pool[Bq*Cc];        // sum over n of attened
__device__ float g_gc  [Bq*Cc];        // sigmoid(channel_map)
__device__ float g_gs  [Bq*Nn];        // sigmoid(spatial_map)
__device__ float g_sqq [Bq*Cc];        // sum of squares per q row
__device__ float g_sqk [Bq*Cc];

__device__ __forceinline__ float gelu_f(float x){
    return 0.5f * x * (1.0f + erff(x * 0.70710678118654752f));
}
__device__ __forceinline__ float sigmoid_f(float x){
    return 1.0f / (1.0f + expf(-x));
}
__device__ __forceinline__ uint32_t smem_u32(const void* p){
    uint32_t a;
    asm("{ .reg .u64 t; cvta.to.shared.u64 t, %1; cvt.u32.u64 %0, t; }" : "=r"(a) : "l"(p));
    return a;
}
__device__ __forceinline__ void ldmx4(uint32_t* r, uint32_t addr){
    asm volatile("ldmatrix.sync.aligned.m8n8.x4.shared.b16 {%0,%1,%2,%3}, [%4];"
                 : "=r"(r[0]), "=r"(r[1]), "=r"(r[2]), "=r"(r[3]) : "r"(addr));
}
__device__ __forceinline__ void ldmx4t(uint32_t* r, uint32_t addr){
    asm volatile("ldmatrix.sync.aligned.m8n8.x4.trans.shared.b16 {%0,%1,%2,%3}, [%4];"
                 : "=r"(r[0]), "=r"(r[1]), "=r"(r[2]), "=r"(r[3]) : "r"(addr));
}
__device__ __forceinline__ void mma_f16(float* d, const uint32_t* a, uint32_t b0, uint32_t b1){
    asm volatile(
        "mma.sync.aligned.m16n8k16.row.col.f32.f16.f16.f32 "
        "{%0,%1,%2,%3}, {%4,%5,%6,%7}, {%8,%9}, {%0,%1,%2,%3};"
        : "+f"(d[0]), "+f"(d[1]), "+f"(d[2]), "+f"(d[3])
        : "r"(a[0]), "r"(a[1]), "r"(a[2]), "r"(a[3]), "r"(b0), "r"(b1));
}
__device__ __forceinline__ void cpa16(uint32_t d, const void* s){
    asm volatile("cp.async.cg.shared.global [%0], [%1], 16;" :: "r"(d), "l"(s));
}
__device__ __forceinline__ uint32_t pack_h2(__half a, __half b){
    return ((uint32_t)__half_as_ushort(b) << 16) | (uint32_t)__half_as_ushort(a);
}
__device__ __forceinline__ void split_h(float v, __half& h, __half& l){
    h = __float2half(v);
    l = __float2half(v - __half2float(h));
}

// qkv pipeline smem: k-chunk 32 fp16 = 64B rows padded to 80B; 3 arrays/stage, 3 stages
#define QT    80
#define QSTG  30720
#define QAH   0
#define QAL   10240
#define QBH   20480
#define QKV_SMEM 92160

// ---------------- 0: zero the accumulated buffers -----------------------------
__global__ void k_zero(){
    int i = blockIdx.x * 256 + threadIdx.x;
    if (i < Bq*NH*HD*HD) g_attn[i] = 0.f;
    if (i < Bq*Cc){ g_pool[i] = 0.f; g_sqq[i] = 0.f; g_sqk[i] = 0.f; }
}

// ---------------- 1: LayerNorm over C -> g_xn_h fp16, layout [b*N+n][c] --------
__global__ void k_layernorm(const float* __restrict__ x,
                            const float* __restrict__ g,
                            const float* __restrict__ b){
    __shared__ float sx[256][33];
    __shared__ float spart[8][32];
    __shared__ float smu[32], sinv[32];
    int bb = blockIdx.x >> 7;
    int n0 = (blockIdx.x & 127) * 32;
    int tid = threadIdx.x;
    int nl = tid & 31, part = tid >> 5;
    const float* xb = x + (size_t)bb * Cc * Nn + n0;
    #pragma unroll
    for (int c0 = 0; c0 < 256; c0 += 8)
        sx[c0 + part][nl] = xb[(size_t)(c0 + part) * Nn + nl];
    __syncthreads();
    float s = 0.f, s2 = 0.f;
    #pragma unroll
    for (int i = 0; i < 32; i++){ float v = sx[part*32 + i][nl]; s += v; s2 += v*v; }
    spart[part][nl] = s;
    __syncthreads();
    if (part == 0){ float t = 0.f; for (int p = 0; p < 8; p++) t += spart[p][nl]; smu[nl] = t * (1.f/256.f); }
    __syncthreads();
    spart[part][nl] = s2;
    __syncthreads();
    if (part == 0){
        float t = 0.f; for (int p = 0; p < 8; p++) t += spart[p][nl];
        float mu = smu[nl];
        sinv[nl] = rsqrtf(t * (1.f/256.f) - mu*mu + 1e-5f);
    }
    __syncthreads();
    float gc = g[tid], bc = b[tid];
    for (int n = 0; n < 32; n++){
        float val = (sx[tid][n] - smu[n]) * sinv[n] * gc + bc;
        g_xn_h[((size_t)(bb * Nn) + n0 + n) * 256 + tid] = __float2half(val);
    }
}

// ---------------- 1b: fold w_q into qkv weight -> g_wB_h/l [o][c] fp16 ---------
__global__ void k_buildW(const float* __restrict__ wqkv, const float* __restrict__ wq){
    __shared__ float srow[768];
    __shared__ float swq[64*64];
    int c = blockIdx.x;
    int tid = threadIdx.x;
    for (int i = tid; i < 768; i += 256)  srow[i] = wqkv[(size_t)c*768 + i];
    for (int i = tid; i < 4096; i += 256) swq[i]  = wq[i];
    __syncthreads();
    int h = tid >> 6, d = tid & 63;
    float s = 0.f;
    #pragma unroll 16
    for (int e = 0; e < 64; e++) s += srow[h*64 + e] * swq[e*64 + d];
    float vals[3] = { s, srow[256 + tid], srow[512 + tid] };
    #pragma unroll
    for (int t = 0; t < 3; t++){
        int o = t*256 + tid;
        __half hi, lo; split_h(vals[t], hi, lo);
        g_wB_h[(size_t)o*256 + c] = hi;
        g_wB_l[(size_t)o*256 + c] = lo;
    }
}

// ---------------- 1c: transpose proj weight -> g_wP_h [o][c] fp16 --------------
__global__ void k_buildP(const float* __restrict__ w){
    int o = blockIdx.x, c = threadIdx.x;
    g_wP_h[(size_t)o*256 + c] = __float2half(w[(size_t)c*256 + o]);
}

// ---------------- 2: qkv GEMM via mma.sync fp16x2 (A=w hi+lo, B=xn rounded) ----
#define QKV_ISSUE(kc_) do{ \
    uint32_t d_ = drow + ((kc_) % 3) * QSTG; \
    size_t go_ = (size_t)(kc_) * 64; \
    cpa16(d_ + QAH,      pwh + go_);      cpa16(d_ + QAH + 16, pwh + go_ + 16); \
    cpa16(d_ + QAL,      pwl + go_);      cpa16(d_ + QAL + 16, pwl + go_ + 16); \
    cpa16(d_ + QBH,      pxh + go_);      cpa16(d_ + QBH + 16, pxh + go_ + 16); \
    asm volatile("cp.async.commit_group;"); } while(0)

__global__ void __launch_bounds__(256) k_qkv_mma(const float* __restrict__ bq){
    extern __shared__ char dsm[];
    uint32_t sb = smem_u32(dsm);
    int tid = threadIdx.x, wid = tid >> 5, lid = tid & 31;
    int warp_m = wid >> 2, warp_n = wid & 3;
    int cblk = blockIdx.x * 128;
    int bn0  = blockIdx.y * 128;
    int bb = bn0 >> 12, n0 = bn0 & (Nn-1);

    int gr = tid >> 1, ghf = tid & 1;
    const char* pwh = (const char*)(g_wB_h + (size_t)(cblk + gr)*256) + ghf*32;
    const char* pwl = (const char*)(g_wB_l + (size_t)(cblk + gr)*256) + ghf*32;
    const char* pxh = (const char*)(g_xn_h + (size_t)(bn0  + gr)*256) + ghf*32;
    uint32_t drow = sb + gr*QT + ghf*32;

    QKV_ISSUE(0);
    QKV_ISSUE(1);

    uint32_t aAo = (uint32_t)((warp_m*64 + (lid & 7) + ((lid >> 3) & 1)*8)*QT + ((lid >> 4) & 1)*16);
    uint32_t aBo = (uint32_t)((warp_n*32 + (lid & 7) + ((lid >> 4) & 1)*8)*QT + ((lid >> 3) & 1)*16);

    float acc[4][4][4] = {};

    #pragma unroll 1
    for (int kc = 0; kc < 8; kc++){
        if (kc + 2 < 8){
            QKV_ISSUE(kc + 2);
            asm volatile("cp.async.wait_group 2;");
        } else if (kc == 6){
            asm volatile("cp.async.wait_group 1;");
        } else {
            asm volatile("cp.async.wait_group 0;");
        }
        __syncthreads();
        uint32_t base = sb + (kc % 3)*QSTG;
        #pragma unroll
        for (int ks = 0; ks < 2; ks++){
            uint32_t kofs = ks*32;
            uint32_t bh[8], arh[4], arl[4];
            ldmx4(bh,     base + QBH + aBo + kofs);
            ldmx4(bh + 4, base + QBH + aBo + kofs + 16*QT);
            #pragma unroll
            for (int mi = 0; mi < 4; mi++){
                ldmx4(arh, base + QAH + aAo + kofs + (uint32_t)(mi*16)*QT);
                ldmx4(arl, base + QAL + aAo + kofs + (uint32_t)(mi*16)*QT);
                #pragma unroll
                for (int ni = 0; ni < 4; ni++) mma_f16(acc[mi][ni], arh, bh[ni*2], bh[ni*2+1]);
                #pragma unroll
                for (int ni = 0; ni < 4; ni++) mma_f16(acc[mi][ni], arl, bh[ni*2], bh[ni*2+1]);
            }
        }
        __syncthreads();
    }

    // epilogue: q -> fp16 (+norms), k -> fp16 hi/lo (+norms), v -> fp16
    int gid = lid >> 2, q4 = lid & 3;
    int obase = cblk + warp_m*64 + gid;
    int ot = obase >> 8;                 // 0=q,1=k,2=v (constant per block)
    #pragma unroll
    for (int mi = 0; mi < 4; mi++){
        int o0 = obase + mi*16;
        float bo0 = (ot == 0) ? bq[o0 & 63] : 0.f;
        float bo1 = (ot == 0) ? bq[(o0 + 8) & 63] : 0.f;
        size_t row0 = ((size_t)(bb*Cc + (o0 & 255))) * Nn;
        size_t row1 = ((size_t)(bb*Cc + ((o0 + 8) & 255))) * Nn;
        float s0 = 0.f, s1 = 0.f;
        #pragma unroll
        for (int ni = 0; ni < 4; ni++){
            int n = n0 + warp_n*32 + ni*8 + q4*2;
            float v0 = acc[mi][ni][0] + bo0, v1 = acc[mi][ni][1] + bo0;
            float v2 = acc[mi][ni][2] + bo1, v3 = acc[mi][ni][3] + bo1;
            if (ot == 2){
                *(uint32_t*)&g_v[row0 + n] = pack_h2(__float2half(v0), __float2half(v1));
                *(uint32_t*)&g_v[row1 + n] = pack_h2(__float2half(v2), __float2half(v3));
            } else if (ot == 0){
                *(uint32_t*)&g_qh[row0 + n] = pack_h2(__float2half(v0), __float2half(v1));
                *(uint32_t*)&g_qh[row1 + n] = pack_h2(__float2half(v2), __float2half(v3));
                s0 += v0*v0 + v1*v1;
                s1 += v2*v2 + v3*v3;
            } else {
                __half h0,l0,h1,l1,h2,l2,h3,l3;
                split_h(v0,h0,l0); split_h(v1,h1,l1);
                split_h(v2,h2,l2); split_h(v3,h3,l3);
                *(uint32_t*)&g_kh[row0 + n] = pack_h2(h0, h1);
                *(uint32_t*)&g_kl[row0 + n] = pack_h2(l0, l1);
                *(uint32_t*)&g_kh[row1 + n] = pack_h2(h2, h3);
                *(uint32_t*)&g_kl[row1 + n] = pack_h2(l2, l3);
                s0 += v0*v0 + v1*v1;
                s1 += v2*v2 + v3*v3;
            }
        }
        if (ot < 2){
            s0 += __shfl_xor_sync(0xFFFFFFFF, s0, 1);
            s0 += __shfl_xor_sync(0xFFFFFFFF, s0, 2);
            s1 += __shfl_xor_sync(0xFFFFFFFF, s1, 1);
            s1 += __shfl_xor_sync(0xFFFFFFFF, s1, 2);
            if (q4 == 0){
                float* sq = ot ? g_sqk : g_sqq;
                atomicAdd(&sq[bb*Cc + (o0 & 255)], s0);
                atomicAdd(&sq[bb*Cc + ((o0 + 8) & 255)], s1);
            }
        }
    }
}

// ---------------- 5: attn = q @ k^T via mma.sync fp16x2 (atomic accumulate) ----
#define AQT 144   // 72 fp16 row stride (bytes)
__global__ void __launch_bounds__(256) k_attn_qk_mma(){
    __shared__ __align__(16) char sm[3*64*AQT];   // qh, kh, kl tiles (64x64)
    uint32_t sb = smem_u32(sm);
    const int OQH = 0, OKH = 64*AQT, OKL = 2*64*AQT;
    int tid = threadIdx.x, wid = tid >> 5, lid = tid & 31;
    int warp_m = wid >> 1, warp_n = wid & 1;
    int bh = blockIdx.y;
    int nbase = blockIdx.x * 512;

    uint32_t aAo = (uint32_t)((warp_m*16 + (lid & 7) + ((lid >> 3) & 1)*8)*AQT + ((lid >> 4) & 1)*16);
    uint32_t aBo = (uint32_t)((warp_n*32 + (lid & 7) + ((lid >> 4) & 1)*8)*AQT + ((lid >> 3) & 1)*16);

    float acc[4][4] = {};

    #pragma unroll 1
    for (int kc = 0; kc < 8; kc++){
        int nb = nbase + kc*64;
        #pragma unroll
        for (int i = 0; i < 2; i++){
            int idx = tid*2 + i;
            int r = idx >> 3, c16 = idx & 7;
            size_t go = ((size_t)(bh*64 + r))*Nn + nb + c16*8;
            uint32_t so = r*AQT + c16*16;
            *(uint4*)(sm + OQH + so) = *(const uint4*)(g_qh + go);
            *(uint4*)(sm + OKH + so) = *(const uint4*)(g_kh + go);
            *(uint4*)(sm + OKL + so) = *(const uint4*)(g_kl + go);
        }
        __syncthreads();
        #pragma unroll
        for (int ks = 0; ks < 4; ks++){
            uint32_t kofs = ks*32;
            uint32_t bh_[8], bl_[8], arh[4];
            ldmx4(bh_,     sb + OKH + aBo + kofs);
            ldmx4(bh_ + 4, sb + OKH + aBo + kofs + 16*AQT);
            ldmx4(bl_,     sb + OKL + aBo + kofs);
            ldmx4(bl_ + 4, sb + OKL + aBo + kofs + 16*AQT);
            ldmx4(arh, sb + OQH + aAo + kofs);
            #pragma unroll
            for (int ni = 0; ni < 4; ni++) mma_f16(acc[ni], arh, bh_[ni*2], bh_[ni*2+1]);
            #pragma unroll
            for (int ni = 0; ni < 4; ni++) mma_f16(acc[ni], arh, bl_[ni*2], bl_[ni*2+1]);
        }
        __syncthreads();
    }

    int gid = lid >> 2, q4 = lid & 3;
    float* dst = g_attn + (size_t)bh*HD*HD;
    #pragma unroll
    for (int ni = 0; ni < 4; ni++){
        int e = warp_n*32 + ni*8 + q4*2;
        int d0 = warp_m*16 + gid;
        atomicAdd(&dst[d0*64 + e],     acc[ni][0]);
        atomicAdd(&dst[d0*64 + e + 1], acc[ni][1]);
        atomicAdd(&dst[(d0+8)*64 + e],     acc[ni][2]);
        atomicAdd(&dst[(d0+8)*64 + e + 1], acc[ni][3]);
    }
}

// ---------------- 6: softmax with temperature and fused L2-norm scaling --------
__global__ void k_softmax(const float* __restrict__ temp){
    int bh = blockIdx.x;
    int d = threadIdx.x;
    float invq = 1.f / fmaxf(sqrtf(g_sqq[bh*64 + d]), 1e-12f);
    float t = temp[bh & 3] * invq;
    float* row = g_attn + (size_t)bh * HD * HD + d * HD;
    float l[64];
    float m = -1e30f;
    #pragma unroll
    for (int e = 0; e < 64; e++){
        float invk = 1.f / fmaxf(sqrtf(g_sqk[bh*64 + e]), 1e-12f);
        l[e] = row[e] * t * invk;
        m = fmaxf(m, l[e]);
    }
    float s = 0.f;
    #pragma unroll
    for (int e = 0; e < 64; e++){ float v = expf(l[e] - m); l[e] = v; s += v; }
    float inv = 1.f / s;
    #pragma unroll
    for (int e = 0; e < 64; e++) row[e] = l[e] * inv;
}

// ---------------- 7: attened = attn @ v via mma.sync fp16, fused pool ----------
// A = attn probs (rounded), B = v fp16 (exact operand, raw copy), trans ldmatrix.
#define AVT 272   // v smem row stride bytes (128 fp16 + pad)
#define AVAH 0
#define AVVH 9216
__global__ void __launch_bounds__(256) k_attn_v_mma(){
    __shared__ __align__(16) char sm[26624];
    uint32_t sb = smem_u32(sm);
    int tid = threadIdx.x, wid = tid >> 5, lid = tid & 31;
    int warp_m = wid >> 1, warp_n = wid & 1;
    int bh = blockIdx.y;
    int bb = bh >> 2, h = bh & 3;
    int n0 = blockIdx.x * 128;

    // stage attn (64x64 fp32 -> fp16 rounded, row stride 144B)
    {
        int d = tid >> 2, e0 = (tid & 3)*16;
        const float* src = g_attn + (size_t)bh*HD*HD + d*64 + e0;
        #pragma unroll
        for (int j = 0; j < 4; j++){
            float4 v = *(const float4*)&src[j*4];
            uint32_t so = d*AQT + e0*2 + j*8;
            *(uint32_t*)(sm + AVAH + so)     = pack_h2(__float2half(v.x), __float2half(v.y));
            *(uint32_t*)(sm + AVAH + so + 4) = pack_h2(__float2half(v.z), __float2half(v.w));
        }
    }
    // stage v (64 x 128 fp16, raw copy, row stride 272B)
    {
        int e = tid >> 2, q = tid & 3;
        const uint4* src = (const uint4*)(g_v + ((size_t)(bb*Cc + h*64 + e))*Nn + n0) + q*4;
        uint4* dst = (uint4*)(sm + AVVH + e*AVT + q*64);
        #pragma unroll
        for (int j = 0; j < 4; j++) dst[j] = src[j];
    }
    __syncthreads();

    uint32_t aAo = (uint32_t)((warp_m*16 + (lid & 7) + ((lid >> 3) & 1)*8)*AQT + ((lid >> 4) & 1)*16);
    uint32_t aBo = (uint32_t)(((lid & 7) + ((lid >> 3) & 1)*8)*AVT + warp_n*128 + ((lid >> 4) & 1)*16);

    float acc[8][4] = {};
    #pragma unroll
    for (int ks = 0; ks < 4; ks++){
        uint32_t kro = (uint32_t)(ks*16)*AVT;
        uint32_t bh_[16], arh[4];
        #pragma unroll
        for (int j = 0; j < 4; j++)
            ldmx4t(bh_ + j*4, sb + AVVH + aBo + kro + j*32);
        ldmx4(arh, sb + AVAH + aAo + ks*32);
        #pragma unroll
        for (int ni = 0; ni < 8; ni++) mma_f16(acc[ni], arh, bh_[ni*2], bh_[ni*2+1]);
    }

    // epilogue: write attened fp16 (B,C,N) + pool partial sums (fp32 acc)
    int gid = lid >> 2, q4 = lid & 3;
    int d0 = warp_m*16 + gid;
    size_t row0 = ((size_t)(bb*Cc + h*64 + d0)) * Nn;
    size_t row1 = ((size_t)(bb*Cc + h*64 + d0 + 8)) * Nn;
    float s0 = 0.f, s1 = 0.f;
    #pragma unroll
    for (int ni = 0; ni < 8; ni++){
        int n = n0 + warp_n*64 + ni*8 + q4*2;
        *(uint32_t*)&g_att[row0 + n] = pack_h2(__float2half(acc[ni][0]), __float2half(acc[ni][1]));
        *(uint32_t*)&g_att[row1 + n] = pack_h2(__float2half(acc[ni][2]), __float2half(acc[ni][3]));
        s0 += acc[ni][0] + acc[ni][1];
        s1 += acc[ni][2] + acc[ni][3];
    }
    s0 += __shfl_xor_sync(0xFFFFFFFF, s0, 1);
    s0 += __shfl_xor_sync(0xFFFFFFFF, s0, 2);
    s1 += __shfl_xor_sync(0xFFFFFFFF, s1, 1);
    s1 += __shfl_xor_sync(0xFFFFFFFF, s1, 2);
    if (q4 == 0){
        atomicAdd(&g_pool[bb*Cc + h*64 + d0], s0);
        atomicAdd(&g_pool[bb*Cc + h*64 + d0 + 8], s1);
    }
}

// ---------------- 8: depthwise 3x3 conv + GELU on v fp16 -----------------------
__global__ void k_dwconv(const float* __restrict__ w, const float* __restrict__ bias){
    int bc = blockIdx.x;
    int c  = bc & (Cc-1);
    const __half* plane = g_v + (size_t)bc * Nn;
    float wk[9];
    #pragma unroll
    for (int i = 0; i < 9; i++) wk[i] = w[c*9 + i];
    float bb = bias[c];
    for (int p = threadIdx.x; p < Nn; p += 256){
        int y = p >> 6, x = p & 63;
        float s = bb;
        #pragma unroll
        for (int dy = -1; dy <= 1; dy++){
            int yy = y + dy;
            if (yy < 0 || yy >= Hh) continue;
            #pragma unroll
            for (int dx = -1; dx <= 1; dx++){
                int xx = x + dx;
                if (xx < 0 || xx >= Ww) continue;
                s += __half2float(plane[yy*Ww + xx]) * wk[(dy+1)*3 + dx + 1];
            }
        }
        g_conv[(size_t)bc * Nn + p] = __float2half(gelu_f(s));
    }
}

// ---------------- 9: channel interaction SE -> gc = sigmoid(map) ---------------
__global__ void k_channel_mlp(const float* __restrict__ w1, const float* __restrict__ b1,
                              const float* __restrict__ w2, const float* __restrict__ b2){
    int bb = blockIdx.x;
    int tid = threadIdx.x;
    __shared__ float sp[256];
    __shared__ float h1[32];
    sp[tid] = g_pool[bb*Cc + tid] * (1.f / Nn);
    __syncthreads();
    if (tid < 32){
        float a = b1[tid];
        for (int c = 0; c < 256; c++) a += sp[c] * w1[tid*256 + c];
        h1[tid] = gelu_f(a);
    }
    __syncthreads();
    float a = b2[tid];
    #pragma unroll
    for (int j = 0; j < 32; j++) a += h1[j] * w2[tid*32 + j];
    g_gc[bb*Cc + tid] = sigmoid_f(a);
}

// ---------------- 10: spatial interaction -> gs = sigmoid(map) -----------------
__global__ void k_spatial(const float* __restrict__ w1, const float* __restrict__ b1,
                          const float* __restrict__ w2, const float* __restrict__ b2){
    int bb = blockIdx.x >> 4;
    int n  = (blockIdx.x & 15) * 256 + threadIdx.x;
    __shared__ float sw1[16*256];
    for (int i = threadIdx.x; i < 16*256; i += 256) sw1[i] = w1[i];
    __syncthreads();
    float acc[16];
    #pragma unroll
    for (int o = 0; o < 16; o++) acc[o] = b1[o];
    const __half* cb = g_conv + (size_t)bb * Cc * Nn + n;
    for (int c = 0; c < 256; c++){
        float x = __half2float(cb[(size_t)c * Nn]);
        #pragma unroll
        for (int o = 0; o < 16; o++) acc[o] += x * sw1[o*256 + c];
    }
    float sm = b2[0];
    #pragma unroll
    for (int o = 0; o < 16; o++) sm += gelu_f(acc[o]) * w2[o];
    g_gs[bb*Nn + n] = sigmoid_f(sm);
}

// ---------------- 11: proj GEMM via mma.sync fp16, fused gating -----------------
// A = wP (rounded), B = gated act rounded to fp16 in loader, trans ldmatrix.
#define PAH 0
#define PBH 10240
#define PBT 272
__global__ void __launch_bounds__(256) k_proj_mma(const float* __restrict__ bias,
                                                  float* __restrict__ out){
    __shared__ __align__(16) char sm[18944];
    uint32_t sb = smem_u32(sm);
    int tid = threadIdx.x, wid = tid >> 5, lid = tid & 31;
    int warp_m = wid >> 2, warp_n = wid & 3;
    int cblk = blockIdx.x * 128;         // o block
    int bn0  = blockIdx.y * 128;
    int bb = bn0 >> 12, n0 = bn0 & (Nn-1);

    int gr = tid >> 1, ghf = tid & 1;
    const char* pah = (const char*)(g_wP_h + (size_t)(cblk + gr)*256) + ghf*32;
    char* dA = sm + gr*80 + ghf*32;

    int cr = tid >> 3, ncb = (tid & 7) * 16;
    const __half* At = g_att  + (size_t)(bb*Cc) * Nn + n0 + ncb;
    const __half* Cv = g_conv + (size_t)(bb*Cc) * Nn + n0 + ncb;
    float gsa[16];
    #pragma unroll
    for (int j = 0; j < 4; j++){
        float4 g4 = *(const float4*)&g_gs[bb*Nn + n0 + ncb + j*4];
        gsa[j*4] = g4.x; gsa[j*4+1] = g4.y; gsa[j*4+2] = g4.z; gsa[j*4+3] = g4.w;
    }
    char* dB = sm + PBH + cr*PBT + ncb*2;

    uint32_t aAo = (uint32_t)((warp_m*64 + (lid & 7) + ((lid >> 3) & 1)*8)*80 + ((lid >> 4) & 1)*16);
    uint32_t aBo = (uint32_t)(((lid & 7) + ((lid >> 3) & 1)*8)*PBT + warp_n*64 + ((lid >> 4) & 1)*16);

    float acc[4][4][4] = {};

    #pragma unroll 1
    for (int kc = 0; kc < 8; kc++){
        int c0 = kc * 32;
        #pragma unroll
        for (int j = 0; j < 2; j++)
            *(uint4*)(dA + PAH + j*16) = *(const uint4*)(pah + c0*2 + j*16);
        {
            float gc = g_gc[bb*Cc + c0 + cr];
            const __half2* at2 = (const __half2*)(At + (size_t)(c0 + cr) * Nn);
            const __half2* cv2 = (const __half2*)(Cv + (size_t)(c0 + cr) * Nn);
            uint32_t o[8];
            #pragma unroll
            for (int j = 0; j < 8; j++){
                float2 a = __half22float2(at2[j]);
                float2 c = __half22float2(cv2[j]);
                float v0 = a.x*gsa[j*2]   + c.x*gc;
                float v1 = a.y*gsa[j*2+1] + c.y*gc;
                o[j] = pack_h2(__float2half(v0), __float2half(v1));
            }
            *(uint4*)(dB)      = make_uint4(o[0], o[1], o[2], o[3]);
            *(uint4*)(dB + 16) = make_uint4(o[4], o[5], o[6], o[7]);
        }
        __syncthreads();
        #pragma unroll
        for (int ks = 0; ks < 2; ks++){
            uint32_t kro = (uint32_t)(ks*16)*PBT;
            uint32_t bh[8], arh[4];
            ldmx4t(bh,     sb + PBH + aBo + kro);
            ldmx4t(bh + 4, sb + PBH + aBo + kro + 32);
            uint32_t kofs = ks*32;
            #pragma unroll
            for (int mi = 0; mi < 4; mi++){
                ldmx4(arh, sb + PAH + aAo + kofs + (uint32_t)(mi*16)*80);
                #pragma unroll
                for (int ni = 0; ni < 4; ni++) mma_f16(acc[mi][ni], arh, bh[ni*2], bh[ni*2+1]);
            }
        }
        __syncthreads();
    }

    int gid = lid >> 2, q4 = lid & 3;
    int obase = cblk + warp_m*64 + gid;
    #pragma unroll
    for (int mi = 0; mi < 4; mi++){
        int o0 = obase + mi*16;
        float bo0 = bias[o0], bo1 = bias[o0 + 8];
        float* r0 = out + ((size_t)(bb*Cc + o0)) * Nn;
        float* r1 = out + ((size_t)(bb*Cc + o0 + 8)) * Nn;
        #pragma unroll
        for (int ni = 0; ni < 4; ni++){
            int n = n0 + warp_n*32 + ni*8 + q4*2;
            *(float2*)&r0[n] = make_float2(acc[mi][ni][0] + bo0, acc[mi][ni][1] + bo0);
            *(float2*)&r1[n] = make_float2(acc[mi][ni][2] + bo1, acc[mi][ni][3] + bo1);
        }
    }
}

// =================================================================================
extern "C" void kernel_launch(void* const* d_in, const int* in_sizes, int n_in,
                              void* d_out, int out_size){
    const float* x     = (const float*)d_in[0];
    const float* ln_g  = (const float*)d_in[1];
    const float* ln_b  = (const float*)d_in[2];
    const float* w_qkv = (const float*)d_in[3];
    const float* w_q   = (const float*)d_in[4];
    const float* b_q   = (const float*)d_in[5];
    const float* temp  = (const float*)d_in[6];
    const float* dw_w  = (const float*)d_in[7];
    const float* dw_b  = (const float*)d_in[8];
    const float* ci_w1 = (const float*)d_in[9];
    const float* ci_b1 = (const float*)d_in[10];
    const float* ci_w2 = (const float*)d_in[11];
    const float* ci_b2 = (const float*)d_in[12];
    const float* si_w1 = (const float*)d_in[13];
    const float* si_b1 = (const float*)d_in[14];
    const float* si_w2 = (const float*)d_in[15];
    const float* si_b2 = (const float*)d_in[16];
    const float* pj_w  = (const float*)d_in[17];
    const float* pj_b  = (const float*)d_in[18];
    float* out = (float*)d_out;

    cudaFuncSetAttribute(k_qkv_mma, cudaFuncAttributeMaxDynamicSharedMemorySize, QKV_SMEM);

    k_zero<<<512, 256>>>();
    k_layernorm<<<Bq*(Nn/32), 256>>>(x, ln_g, ln_b);
    k_buildW<<<Cc, 256>>>(w_qkv, w_q);
    k_buildP<<<Cc, 256>>>(pj_w);
    k_qkv_mma<<<dim3(6, BN/128), 256, QKV_SMEM>>>(b_q);
    k_attn_qk_mma<<<dim3(8, Bq*NH), 256>>>();
    k_softmax<<<Bq*NH, 64>>>(temp);
    k_attn_v_mma<<<dim3(Nn/128, Bq*NH), 256>>>();
    k_dwconv<<<Bq*Cc, 256>>>(dw_w, dw_b);
    k_spatial<<<Bq*16, 256>>>(si_w1, si_b1, si_w2, si_b2);
    k_channel_mlp<<<Bq, 256>>>(ci_w1, ci_b1, ci_w2, ci_b2);
    k_proj_mma<<<dim3(2, BN/128), 256>>>(pj_b, out);
}

// round 10
// speedup vs baseline: 3.3686x; 1.0326x over previous
#include <cuda_runtime.h>
#include <cuda_fp16.h>
#include <math.h>
#include <stdint.h>

// Problem constants
#define Bq   8
#define Cc   256
#define Hh   64
#define Ww   64
#define Nn   4096            // H*W
#define NH   4
#define HD   64
#define BN   (Bq*Nn)         // 32768

// ---------------- scratch (device globals; no allocation allowed) -------------
__device__ __half g_xn_h[BN*Cc];     // layernormed x (fp16 rounded), [b*N+n][c]
__device__ __half g_wB_h[768*Cc];    // folded qkv weight [o][c], fp16 hi
__device__ __half g_wB_l[768*Cc];    // fp16 lo residual
__device__ __half g_wP_h[Cc*Cc];     // proj weight transposed [o][c], fp16 (rounded)
__device__ __half g_qh[Bq*Cc*Nn];    // q fp16 (rounded), row = bh*64+d, col n
__device__ __half g_kh[Bq*Cc*Nn];    // k fp16 hi
__device__ __half g_kl[Bq*Cc*Nn];    // k fp16 lo
__device__ __half g_v   [Bq*Cc*Nn];  // v fp16, (B,C,N) head-major
__device__ __half g_att [Bq*Cc*Nn];  // attened_x fp16, (B,C,N)
__device__ __half g_conv[Bq*Cc*Nn];  // gelu(dwconv) fp16, (B,C,N)
__device__ float g_attn[Bq*NH*HD*HD];  // (B,nh,hd,hd)
__device__ float g_pool[Bq*Cc];        // sum over n of attened
__device__ float g_gc  [Bq*Cc];        // sigmoid(channel_map)
__device__ float g_gs  [Bq*Nn];        // sigmoid(spatial_map)
__device__ float g_sqq [Bq*Cc];        // sum of squares per q row
__device__ float g_sqk [Bq*Cc];

__device__ __forceinline__ float gelu_f(float x){
    return 0.5f * x * (1.0f + erff(x * 0.70710678118654752f));
}
__device__ __forceinline__ float sigmoid_f(float x){
    return 1.0f / (1.0f + expf(-x));
}
__device__ __forceinline__ uint32_t smem_u32(const void* p){
    uint32_t a;
    asm("{ .reg .u64 t; cvta.to.shared.u64 t, %1; cvt.u32.u64 %0, t; }" : "=r"(a) : "l"(p));
    return a;
}
__device__ __forceinline__ void ldmx4(uint32_t* r, uint32_t addr){
    asm volatile("ldmatrix.sync.aligned.m8n8.x4.shared.b16 {%0,%1,%2,%3}, [%4];"
                 : "=r"(r[0]), "=r"(r[1]), "=r"(r[2]), "=r"(r[3]) : "r"(addr));
}
__device__ __forceinline__ void ldmx4t(uint32_t* r, uint32_t addr){
    asm volatile("ldmatrix.sync.aligned.m8n8.x4.trans.shared.b16 {%0,%1,%2,%3}, [%4];"
                 : "=r"(r[0]), "=r"(r[1]), "=r"(r[2]), "=r"(r[3]) : "r"(addr));
}
__device__ __forceinline__ void mma_f16(float* d, const uint32_t* a, uint32_t b0, uint32_t b1){
    asm volatile(
        "mma.sync.aligned.m16n8k16.row.col.f32.f16.f16.f32 "
        "{%0,%1,%2,%3}, {%4,%5,%6,%7}, {%8,%9}, {%0,%1,%2,%3};"
        : "+f"(d[0]), "+f"(d[1]), "+f"(d[2]), "+f"(d[3])
        : "r"(a[0]), "r"(a[1]), "r"(a[2]), "r"(a[3]), "r"(b0), "r"(b1));
}
__device__ __forceinline__ void cpa16(uint32_t d, const void* s){
    asm volatile("cp.async.cg.shared.global [%0], [%1], 16;" :: "r"(d), "l"(s));
}
__device__ __forceinline__ uint32_t pack_h2(__half a, __half b){
    return ((uint32_t)__half_as_ushort(b) << 16) | (uint32_t)__half_as_ushort(a);
}
__device__ __forceinline__ void split_h(float v, __half& h, __half& l){
    h = __float2half(v);
    l = __float2half(v - __half2float(h));
}

// qkv pipeline smem: k-chunk 32 fp16 = 64B rows padded to 80B; 3 arrays/stage, 3 stages
#define QT    80
#define QSTG  30720
#define QAH   0
#define QAL   10240
#define QBH   20480
#define QKV_SMEM 92160

// ---------------- 0: zero the accumulated buffers -----------------------------
__global__ void k_zero(){
    int i = blockIdx.x * 256 + threadIdx.x;
    if (i < Bq*NH*HD*HD) g_attn[i] = 0.f;
    if (i < Bq*Cc){ g_pool[i] = 0.f; g_sqq[i] = 0.f; g_sqk[i] = 0.f; }
}

// ---------------- 1: LayerNorm over C -> g_xn_h fp16, layout [b*N+n][c] --------
__global__ void k_layernorm(const float* __restrict__ x,
                            const float* __restrict__ g,
                            const float* __restrict__ b){
    __shared__ float sx[256][33];
    __shared__ float spart[8][32];
    __shared__ float smu[32], sinv[32];
    int bb = blockIdx.x >> 7;
    int n0 = (blockIdx.x & 127) * 32;
    int tid = threadIdx.x;
    int nl = tid & 31, part = tid >> 5;
    const float* xb = x + (size_t)bb * Cc * Nn + n0;
    #pragma unroll
    for (int c0 = 0; c0 < 256; c0 += 8)
        sx[c0 + part][nl] = xb[(size_t)(c0 + part) * Nn + nl];
    __syncthreads();
    float s = 0.f, s2 = 0.f;
    #pragma unroll
    for (int i = 0; i < 32; i++){ float v = sx[part*32 + i][nl]; s += v; s2 += v*v; }
    spart[part][nl] = s;
    __syncthreads();
    if (part == 0){ float t = 0.f; for (int p = 0; p < 8; p++) t += spart[p][nl]; smu[nl] = t * (1.f/256.f); }
    __syncthreads();
    spart[part][nl] = s2;
    __syncthreads();
    if (part == 0){
        float t = 0.f; for (int p = 0; p < 8; p++) t += spart[p][nl];
        float mu = smu[nl];
        sinv[nl] = rsqrtf(t * (1.f/256.f) - mu*mu + 1e-5f);
    }
    __syncthreads();
    float gc = g[tid], bc = b[tid];
    for (int n = 0; n < 32; n++){
        float val = (sx[tid][n] - smu[n]) * sinv[n] * gc + bc;
        g_xn_h[((size_t)(bb * Nn) + n0 + n) * 256 + tid] = __float2half(val);
    }
}

// ---------------- 1b: fold w_q into qkv weight -> g_wB_h/l [o][c] fp16 ---------
__global__ void k_buildW(const float* __restrict__ wqkv, const float* __restrict__ wq){
    __shared__ float srow[768];
    __shared__ float swq[64*64];
    int c = blockIdx.x;
    int tid = threadIdx.x;
    for (int i = tid; i < 768; i += 256)  srow[i] = wqkv[(size_t)c*768 + i];
    for (int i = tid; i < 4096; i += 256) swq[i]  = wq[i];
    __syncthreads();
    int h = tid >> 6, d = tid & 63;
    float s = 0.f;
    #pragma unroll 16
    for (int e = 0; e < 64; e++) s += srow[h*64 + e] * swq[e*64 + d];
    float vals[3] = { s, srow[256 + tid], srow[512 + tid] };
    #pragma unroll
    for (int t = 0; t < 3; t++){
        int o = t*256 + tid;
        __half hi, lo; split_h(vals[t], hi, lo);
        g_wB_h[(size_t)o*256 + c] = hi;
        g_wB_l[(size_t)o*256 + c] = lo;
    }
}

// ---------------- 1c: transpose proj weight -> g_wP_h [o][c] fp16 (coalesced) --
__global__ void k_buildP(const float* __restrict__ w){
    __shared__ float t[32][33];
    int tx = threadIdx.x & 31, ty = threadIdx.x >> 5;   // 32 x 8
    int c0 = (blockIdx.x & 7) * 32, o0 = (blockIdx.x >> 3) * 32;
    #pragma unroll
    for (int r = 0; r < 32; r += 8)
        t[ty + r][tx] = w[(size_t)(c0 + ty + r) * 256 + o0 + tx];
    __syncthreads();
    #pragma unroll
    for (int r = 0; r < 32; r += 8)
        g_wP_h[(size_t)(o0 + ty + r) * 256 + c0 + tx] = __float2half(t[tx][ty + r]);
}

// ---------------- 2: qkv GEMM via mma.sync fp16x2, 3-stage, 1 sync/chunk -------
#define QKV_ISSUE(kc_) do{ \
    uint32_t d_ = drow + ((kc_) % 3) * QSTG; \
    size_t go_ = (size_t)(kc_) * 64; \
    cpa16(d_ + QAH,      pwh + go_);      cpa16(d_ + QAH + 16, pwh + go_ + 16); \
    cpa16(d_ + QAL,      pwl + go_);      cpa16(d_ + QAL + 16, pwl + go_ + 16); \
    cpa16(d_ + QBH,      pxh + go_);      cpa16(d_ + QBH + 16, pxh + go_ + 16); \
    asm volatile("cp.async.commit_group;"); } while(0)

__global__ void __launch_bounds__(256, 2) k_qkv_mma(const float* __restrict__ bq){
    extern __shared__ char dsm[];
    uint32_t sb = smem_u32(dsm);
    int tid = threadIdx.x, wid = tid >> 5, lid = tid & 31;
    int warp_m = wid >> 2, warp_n = wid & 3;
    int cblk = blockIdx.x * 128;
    int bn0  = blockIdx.y * 128;
    int bb = bn0 >> 12, n0 = bn0 & (Nn-1);

    int gr = tid >> 1, ghf = tid & 1;
    const char* pwh = (const char*)(g_wB_h + (size_t)(cblk + gr)*256) + ghf*32;
    const char* pwl = (const char*)(g_wB_l + (size_t)(cblk + gr)*256) + ghf*32;
    const char* pxh = (const char*)(g_xn_h + (size_t)(bn0  + gr)*256) + ghf*32;
    uint32_t drow = sb + gr*QT + ghf*32;

    QKV_ISSUE(0);
    QKV_ISSUE(1);

    uint32_t aAo = (uint32_t)((warp_m*64 + (lid & 7) + ((lid >> 3) & 1)*8)*QT + ((lid >> 4) & 1)*16);
    uint32_t aBo = (uint32_t)((warp_n*32 + (lid & 7) + ((lid >> 4) & 1)*8)*QT + ((lid >> 3) & 1)*16);

    float acc[4][4][4] = {};

    #pragma unroll 1
    for (int kc = 0; kc < 8; kc++){
        if (kc < 7) asm volatile("cp.async.wait_group 1;");
        else        asm volatile("cp.async.wait_group 0;");
        __syncthreads();
        if (kc < 6) QKV_ISSUE(kc + 2);
        uint32_t base = sb + (kc % 3)*QSTG;
        #pragma unroll
        for (int ks = 0; ks < 2; ks++){
            uint32_t kofs = ks*32;
            uint32_t bh[8], arh[4], arl[4];
            ldmx4(bh,     base + QBH + aBo + kofs);
            ldmx4(bh + 4, base + QBH + aBo + kofs + 16*QT);
            #pragma unroll
            for (int mi = 0; mi < 4; mi++){
                ldmx4(arh, base + QAH + aAo + kofs + (uint32_t)(mi*16)*QT);
                ldmx4(arl, base + QAL + aAo + kofs + (uint32_t)(mi*16)*QT);
                #pragma unroll
                for (int ni = 0; ni < 4; ni++) mma_f16(acc[mi][ni], arh, bh[ni*2], bh[ni*2+1]);
                #pragma unroll
                for (int ni = 0; ni < 4; ni++) mma_f16(acc[mi][ni], arl, bh[ni*2], bh[ni*2+1]);
            }
        }
    }

    // epilogue: q -> fp16 (+norms), k -> fp16 hi/lo (+norms), v -> fp16
    int gid = lid >> 2, q4 = lid & 3;
    int obase = cblk + warp_m*64 + gid;
    int ot = obase >> 8;                 // 0=q,1=k,2=v (constant per block)
    #pragma unroll
    for (int mi = 0; mi < 4; mi++){
        int o0 = obase + mi*16;
        float bo0 = (ot == 0) ? bq[o0 & 63] : 0.f;
        float bo1 = (ot == 0) ? bq[(o0 + 8) & 63] : 0.f;
        size_t row0 = ((size_t)(bb*Cc + (o0 & 255))) * Nn;
        size_t row1 = ((size_t)(bb*Cc + ((o0 + 8) & 255))) * Nn;
        float s0 = 0.f, s1 = 0.f;
        #pragma unroll
        for (int ni = 0; ni < 4; ni++){
            int n = n0 + warp_n*32 + ni*8 + q4*2;
            float v0 = acc[mi][ni][0] + bo0, v1 = acc[mi][ni][1] + bo0;
            float v2 = acc[mi][ni][2] + bo1, v3 = acc[mi][ni][3] + bo1;
            if (ot == 2){
                *(uint32_t*)&g_v[row0 + n] = pack_h2(__float2half(v0), __float2half(v1));
                *(uint32_t*)&g_v[row1 + n] = pack_h2(__float2half(v2), __float2half(v3));
            } else if (ot == 0){
                *(uint32_t*)&g_qh[row0 + n] = pack_h2(__float2half(v0), __float2half(v1));
                *(uint32_t*)&g_qh[row1 + n] = pack_h2(__float2half(v2), __float2half(v3));
                s0 += v0*v0 + v1*v1;
                s1 += v2*v2 + v3*v3;
            } else {
                __half h0,l0,h1,l1,h2,l2,h3,l3;
                split_h(v0,h0,l0); split_h(v1,h1,l1);
                split_h(v2,h2,l2); split_h(v3,h3,l3);
                *(uint32_t*)&g_kh[row0 + n] = pack_h2(h0, h1);
                *(uint32_t*)&g_kl[row0 + n] = pack_h2(l0, l1);
                *(uint32_t*)&g_kh[row1 + n] = pack_h2(h2, h3);
                *(uint32_t*)&g_kl[row1 + n] = pack_h2(l2, l3);
                s0 += v0*v0 + v1*v1;
                s1 += v2*v2 + v3*v3;
            }
        }
        if (ot < 2){
            s0 += __shfl_xor_sync(0xFFFFFFFF, s0, 1);
            s0 += __shfl_xor_sync(0xFFFFFFFF, s0, 2);
            s1 += __shfl_xor_sync(0xFFFFFFFF, s1, 1);
            s1 += __shfl_xor_sync(0xFFFFFFFF, s1, 2);
            if (q4 == 0){
                float* sq = ot ? g_sqk : g_sqq;
                atomicAdd(&sq[bb*Cc + (o0 & 255)], s0);
                atomicAdd(&sq[bb*Cc + ((o0 + 8) & 255)], s1);
            }
        }
    }
}

// ---------------- 5: attn = q @ k^T, cp.async 2-stage, 1 sync/chunk ------------
#define AQT   144   // 72 fp16 row stride (bytes)
#define AQSTG 27648 // 3 arrays x 64 x 144
__global__ void __launch_bounds__(256) k_attn_qk_mma(){
    __shared__ __align__(16) char sm[2*AQSTG];
    uint32_t sb = smem_u32(sm);
    const int OQH = 0, OKH = 64*AQT, OKL = 2*64*AQT;
    int tid = threadIdx.x, wid = tid >> 5, lid = tid & 31;
    int warp_m = wid >> 1, warp_n = wid & 1;
    int bh = blockIdx.y;
    int nbase = blockIdx.x * 512;

    int r_ = tid >> 2, c16_ = (tid & 3)*2;   // 2 chunks of 16B per thread
    size_t gbase = ((size_t)(bh*64 + r_))*Nn;
    uint32_t sobase = r_*AQT + c16_*16;

    #define AQ_ISSUE(kc_) do{ \
        uint32_t st_ = sb + ((kc_) & 1)*AQSTG + sobase; \
        size_t g_ = gbase + (size_t)(nbase + (kc_)*64) + c16_*8; \
        cpa16(st_ + OQH,      g_qh + g_);  cpa16(st_ + OQH + 16, g_qh + g_ + 8); \
        cpa16(st_ + OKH,      g_kh + g_);  cpa16(st_ + OKH + 16, g_kh + g_ + 8); \
        cpa16(st_ + OKL,      g_kl + g_);  cpa16(st_ + OKL + 16, g_kl + g_ + 8); \
        asm volatile("cp.async.commit_group;"); } while(0)

    AQ_ISSUE(0);

    uint32_t aAo = (uint32_t)((warp_m*16 + (lid & 7) + ((lid >> 3) & 1)*8)*AQT + ((lid >> 4) & 1)*16);
    uint32_t aBo = (uint32_t)((warp_n*32 + (lid & 7) + ((lid >> 4) & 1)*8)*AQT + ((lid >> 3) & 1)*16);

    float acc[4][4] = {};

    #pragma unroll 1
    for (int kc = 0; kc < 8; kc++){
        asm volatile("cp.async.wait_group 0;");
        __syncthreads();
        if (kc < 7) AQ_ISSUE(kc + 1);
        uint32_t base = sb + (kc & 1)*AQSTG;
        #pragma unroll
        for (int ks = 0; ks < 4; ks++){
            uint32_t kofs = ks*32;
            uint32_t bh_[8], bl_[8], arh[4];
            ldmx4(bh_,     base + OKH + aBo + kofs);
            ldmx4(bh_ + 4, base + OKH + aBo + kofs + 16*AQT);
            ldmx4(bl_,     base + OKL + aBo + kofs);
            ldmx4(bl_ + 4, base + OKL + aBo + kofs + 16*AQT);
            ldmx4(arh, base + OQH + aAo + kofs);
            #pragma unroll
            for (int ni = 0; ni < 4; ni++) mma_f16(acc[ni], arh, bh_[ni*2], bh_[ni*2+1]);
            #pragma unroll
            for (int ni = 0; ni < 4; ni++) mma_f16(acc[ni], arh, bl_[ni*2], bl_[ni*2+1]);
        }
        __syncthreads();
    }

    int gid = lid >> 2, q4 = lid & 3;
    float* dst = g_attn + (size_t)bh*HD*HD;
    #pragma unroll
    for (int ni = 0; ni < 4; ni++){
        int e = warp_n*32 + ni*8 + q4*2;
        int d0 = warp_m*16 + gid;
        atomicAdd(&dst[d0*64 + e],     acc[ni][0]);
        atomicAdd(&dst[d0*64 + e + 1], acc[ni][1]);
        atomicAdd(&dst[(d0+8)*64 + e],     acc[ni][2]);
        atomicAdd(&dst[(d0+8)*64 + e + 1], acc[ni][3]);
    }
}

// ---------------- 6: softmax with temperature and fused L2-norm scaling --------
__global__ void k_softmax(const float* __restrict__ temp){
    int bh = blockIdx.x;
    int d = threadIdx.x;
    float invq = 1.f / fmaxf(sqrtf(g_sqq[bh*64 + d]), 1e-12f);
    float t = temp[bh & 3] * invq;
    float* row = g_attn + (size_t)bh * HD * HD + d * HD;
    float l[64];
    float m = -1e30f;
    #pragma unroll
    for (int e = 0; e < 64; e++){
        float invk = 1.f / fmaxf(sqrtf(g_sqk[bh*64 + e]), 1e-12f);
        l[e] = row[e] * t * invk;
        m = fmaxf(m, l[e]);
    }
    float s = 0.f;
    #pragma unroll
    for (int e = 0; e < 64; e++){ float v = expf(l[e] - m); l[e] = v; s += v; }
    float inv = 1.f / s;
    #pragma unroll
    for (int e = 0; e < 64; e++) row[e] = l[e] * inv;
}

// ---------------- 7: attened = attn @ v via mma.sync fp16, fused pool ----------
#define AVT 272   // v smem row stride bytes (128 fp16 + pad)
#define AVAH 0
#define AVVH 9216
__global__ void __launch_bounds__(256) k_attn_v_mma(){
    __shared__ __align__(16) char sm[26624];
    uint32_t sb = smem_u32(sm);
    int tid = threadIdx.x, wid = tid >> 5, lid = tid & 31;
    int warp_m = wid >> 1, warp_n = wid & 1;
    int bh = blockIdx.y;
    int bb = bh >> 2, h = bh & 3;
    int n0 = blockIdx.x * 128;

    // stage attn (64x64 fp32 -> fp16 rounded, row stride 144B)
    {
        int d = tid >> 2, e0 = (tid & 3)*16;
        const float* src = g_attn + (size_t)bh*HD*HD + d*64 + e0;
        #pragma unroll
        for (int j = 0; j < 4; j++){
            float4 v = *(const float4*)&src[j*4];
            uint32_t so = d*AQT + e0*2 + j*8;
            *(uint32_t*)(sm + AVAH + so)     = pack_h2(__float2half(v.x), __float2half(v.y));
            *(uint32_t*)(sm + AVAH + so + 4) = pack_h2(__float2half(v.z), __float2half(v.w));
        }
    }
    // stage v (64 x 128 fp16, raw copy, row stride 272B)
    {
        int e = tid >> 2, q = tid & 3;
        const uint4* src = (const uint4*)(g_v + ((size_t)(bb*Cc + h*64 + e))*Nn + n0) + q*4;
        uint4* dst = (uint4*)(sm + AVVH + e*AVT + q*64);
        #pragma unroll
        for (int j = 0; j < 4; j++) dst[j] = src[j];
    }
    __syncthreads();

    uint32_t aAo = (uint32_t)((warp_m*16 + (lid & 7) + ((lid >> 3) & 1)*8)*AQT + ((lid >> 4) & 1)*16);
    uint32_t aBo = (uint32_t)(((lid & 7) + ((lid >> 3) & 1)*8)*AVT + warp_n*128 + ((lid >> 4) & 1)*16);

    float acc[8][4] = {};
    #pragma unroll
    for (int ks = 0; ks < 4; ks++){
        uint32_t kro = (uint32_t)(ks*16)*AVT;
        uint32_t bh_[16], arh[4];
        #pragma unroll
        for (int j = 0; j < 4; j++)
            ldmx4t(bh_ + j*4, sb + AVVH + aBo + kro + j*32);
        ldmx4(arh, sb + AVAH + aAo + ks*32);
        #pragma unroll
        for (int ni = 0; ni < 8; ni++) mma_f16(acc[ni], arh, bh_[ni*2], bh_[ni*2+1]);
    }

    // epilogue: write attened fp16 (B,C,N) + pool partial sums (fp32 acc)
    int gid = lid >> 2, q4 = lid & 3;
    int d0 = warp_m*16 + gid;
    size_t row0 = ((size_t)(bb*Cc + h*64 + d0)) * Nn;
    size_t row1 = ((size_t)(bb*Cc + h*64 + d0 + 8)) * Nn;
    float s0 = 0.f, s1 = 0.f;
    #pragma unroll
    for (int ni = 0; ni < 8; ni++){
        int n = n0 + warp_n*64 + ni*8 + q4*2;
        *(uint32_t*)&g_att[row0 + n] = pack_h2(__float2half(acc[ni][0]), __float2half(acc[ni][1]));
        *(uint32_t*)&g_att[row1 + n] = pack_h2(__float2half(acc[ni][2]), __float2half(acc[ni][3]));
        s0 += acc[ni][0] + acc[ni][1];
        s1 += acc[ni][2] + acc[ni][3];
    }
    s0 += __shfl_xor_sync(0xFFFFFFFF, s0, 1);
    s0 += __shfl_xor_sync(0xFFFFFFFF, s0, 2);
    s1 += __shfl_xor_sync(0xFFFFFFFF, s1, 1);
    s1 += __shfl_xor_sync(0xFFFFFFFF, s1, 2);
    if (q4 == 0){
        atomicAdd(&g_pool[bb*Cc + h*64 + d0], s0);
        atomicAdd(&g_pool[bb*Cc + h*64 + d0 + 8], s1);
    }
}

// ---------------- 8: depthwise 3x3 conv + GELU on v fp16 -----------------------
__global__ void k_dwconv(const float* __restrict__ w, const float* __restrict__ bias){
    int bc = blockIdx.x;
    int c  = bc & (Cc-1);
    const __half* plane = g_v + (size_t)bc * Nn;
    float wk[9];
    #pragma unroll
    for (int i = 0; i < 9; i++) wk[i] = w[c*9 + i];
    float bb = bias[c];
    for (int p = threadIdx.x; p < Nn; p += 256){
        int y = p >> 6, x = p & 63;
        float s = bb;
        #pragma unroll
        for (int dy = -1; dy <= 1; dy++){
            int yy = y + dy;
            if (yy < 0 || yy >= Hh) continue;
            #pragma unroll
            for (int dx = -1; dx <= 1; dx++){
                int xx = x + dx;
                if (xx < 0 || xx >= Ww) continue;
                s += __half2float(plane[yy*Ww + xx]) * wk[(dy+1)*3 + dx + 1];
            }
        }
        g_conv[(size_t)bc * Nn + p] = __float2half(gelu_f(s));
    }
}

// ---------------- 9: channel interaction SE -> gc = sigmoid(map) ---------------
__global__ void k_channel_mlp(const float* __restrict__ w1, const float* __restrict__ b1,
                              const float* __restrict__ w2, const float* __restrict__ b2){
    int bb = blockIdx.x;
    int tid = threadIdx.x;
    __shared__ float sp[256];
    __shared__ float h1[32];
    sp[tid] = g_pool[bb*Cc + tid] * (1.f / Nn);
    __syncthreads();
    if (tid < 32){
        float a = b1[tid];
        for (int c = 0; c < 256; c++) a += sp[c] * w1[tid*256 + c];
        h1[tid] = gelu_f(a);
    }
    __syncthreads();
    float a = b2[tid];
    #pragma unroll
    for (int j = 0; j < 32; j++) a += h1[j] * w2[tid*32 + j];
    g_gc[bb*Cc + tid] = sigmoid_f(a);
}

// ---------------- 10: spatial interaction -> gs = sigmoid(map) -----------------
__global__ void k_spatial(const float* __restrict__ w1, const float* __restrict__ b1,
                          const float* __restrict__ w2, const float* __restrict__ b2){
    int bb = blockIdx.x >> 4;
    int n  = (blockIdx.x & 15) * 256 + threadIdx.x;
    __shared__ float sw1[16*256];
    for (int i = threadIdx.x; i < 16*256; i += 256) sw1[i] = w1[i];
    __syncthreads();
    float acc[16];
    #pragma unroll
    for (int o = 0; o < 16; o++) acc[o] = b1[o];
    const __half* cb = g_conv + (size_t)bb * Cc * Nn + n;
    for (int c = 0; c < 256; c++){
        float x = __half2float(cb[(size_t)c * Nn]);
        #pragma unroll
        for (int o = 0; o < 16; o++) acc[o] += x * sw1[o*256 + c];
    }
    float sm = b2[0];
    #pragma unroll
    for (int o = 0; o < 16; o++) sm += gelu_f(acc[o]) * w2[o];
    g_gs[bb*Nn + n] = sigmoid_f(sm);
}

// ---------------- 11: proj GEMM via mma.sync fp16, fused gating, reg prefetch ---
#define PAH 0
#define PBH 10240
#define PBT 272
__global__ void __launch_bounds__(256) k_proj_mma(const float* __restrict__ bias,
                                                  float* __restrict__ out){
    __shared__ __align__(16) char sm[18944];
    uint32_t sb = smem_u32(sm);
    int tid = threadIdx.x, wid = tid >> 5, lid = tid & 31;
    int warp_m = wid >> 2, warp_n = wid & 3;
    int cblk = blockIdx.x * 128;         // o block
    int bn0  = blockIdx.y * 128;
    int bb = bn0 >> 12, n0 = bn0 & (Nn-1);

    int gr = tid >> 1, ghf = tid & 1;
    const char* pah = (const char*)(g_wP_h + (size_t)(cblk + gr)*256) + ghf*32;
    char* dA = sm + gr*80 + ghf*32;

    int cr = tid >> 3, ncb = (tid & 7) * 16;
    const __half* At = g_att  + (size_t)(bb*Cc) * Nn + n0 + ncb;
    const __half* Cv = g_conv + (size_t)(bb*Cc) * Nn + n0 + ncb;
    float gsa[16];
    #pragma unroll
    for (int j = 0; j < 4; j++){
        float4 g4 = *(const float4*)&g_gs[bb*Nn + n0 + ncb + j*4];
        gsa[j*4] = g4.x; gsa[j*4+1] = g4.y; gsa[j*4+2] = g4.z; gsa[j*4+3] = g4.w;
    }
    char* dB = sm + PBH + cr*PBT + ncb*2;

    uint32_t aAo = (uint32_t)((warp_m*64 + (lid & 7) + ((lid >> 3) & 1)*8)*80 + ((lid >> 4) & 1)*16);
    uint32_t aBo = (uint32_t)(((lid & 7) + ((lid >> 3) & 1)*8)*PBT + warp_n*64 + ((lid >> 4) & 1)*16);

    float acc[4][4][4] = {};

    // register prefetch state
    uint4 rA0, rA1;
    uint2 rAt[4], rCv[4];
    float rGc;
    #define PROJ_LOAD(kc_) do{ \
        int c0_ = (kc_) * 32; \
        rA0 = *(const uint4*)(pah + c0_*2); \
        rA1 = *(const uint4*)(pah + c0_*2 + 16); \
        rGc = g_gc[bb*Cc + c0_ + cr]; \
        const uint2* at_ = (const uint2*)(At + (size_t)(c0_ + cr) * Nn); \
        const uint2* cv_ = (const uint2*)(Cv + (size_t)(c0_ + cr) * Nn); \
        rAt[0] = at_[0]; rAt[1] = at_[1]; rAt[2] = at_[2]; rAt[3] = at_[3]; \
        rCv[0] = cv_[0]; rCv[1] = cv_[1]; rCv[2] = cv_[2]; rCv[3] = cv_[3]; \
    } while(0)

    PROJ_LOAD(0);

    #pragma unroll 1
    for (int kc = 0; kc < 8; kc++){
        // stage from registers
        *(uint4*)(dA + PAH)      = rA0;
        *(uint4*)(dA + PAH + 16) = rA1;
        {
            uint32_t o[8];
            #pragma unroll
            for (int jj = 0; jj < 4; jj++){
                __half2 a0 = *(__half2*)&rAt[jj].x, a1 = *(__half2*)&rAt[jj].y;
                __half2 c0h = *(__half2*)&rCv[jj].x, c1h = *(__half2*)&rCv[jj].y;
                float2 a = __half22float2(a0), c = __half22float2(c0h);
                float2 a2 = __half22float2(a1), c2 = __half22float2(c1h);
                float v0 = a.x*gsa[jj*4]   + c.x*rGc;
                float v1 = a.y*gsa[jj*4+1] + c.y*rGc;
                float v2 = a2.x*gsa[jj*4+2] + c2.x*rGc;
                float v3 = a2.y*gsa[jj*4+3] + c2.y*rGc;
                o[jj*2]   = pack_h2(__float2half(v0), __float2half(v1));
                o[jj*2+1] = pack_h2(__float2half(v2), __float2half(v3));
            }
            *(uint4*)(dB)      = make_uint4(o[0], o[1], o[2], o[3]);
            *(uint4*)(dB + 16) = make_uint4(o[4], o[5], o[6], o[7]);
        }
        __syncthreads();
        if (kc < 7) PROJ_LOAD(kc + 1);
        #pragma unroll
        for (int ks = 0; ks < 2; ks++){
            uint32_t kro = (uint32_t)(ks*16)*PBT;
            uint32_t bh[8], arh[4];
            ldmx4t(bh,     sb + PBH + aBo + kro);
            ldmx4t(bh + 4, sb + PBH + aBo + kro + 32);
            uint32_t kofs = ks*32;
            #pragma unroll
            for (int mi = 0; mi < 4; mi++){
                ldmx4(arh, sb + PAH + aAo + kofs + (uint32_t)(mi*16)*80);
                #pragma unroll
                for (int ni = 0; ni < 4; ni++) mma_f16(acc[mi][ni], arh, bh[ni*2], bh[ni*2+1]);
            }
        }
        __syncthreads();
    }

    int gid = lid >> 2, q4 = lid & 3;
    int obase = cblk + warp_m*64 + gid;
    #pragma unroll
    for (int mi = 0; mi < 4; mi++){
        int o0 = obase + mi*16;
        float bo0 = bias[o0], bo1 = bias[o0 + 8];
        float* r0 = out + ((size_t)(bb*Cc + o0)) * Nn;
        float* r1 = out + ((size_t)(bb*Cc + o0 + 8)) * Nn;
        #pragma unroll
        for (int ni = 0; ni < 4; ni++){
            int n = n0 + warp_n*32 + ni*8 + q4*2;
            *(float2*)&r0[n] = make_float2(acc[mi][ni][0] + bo0, acc[mi][ni][1] + bo0);
            *(float2*)&r1[n] = make_float2(acc[mi][ni][2] + bo1, acc[mi][ni][3] + bo1);
        }
    }
}

// =================================================================================
extern "C" void kernel_launch(void* const* d_in, const int* in_sizes, int n_in,
                              void* d_out, int out_size){
    const float* x     = (const float*)d_in[0];
    const float* ln_g  = (const float*)d_in[1];
    const float* ln_b  = (const float*)d_in[2];
    const float* w_qkv = (const float*)d_in[3];
    const float* w_q   = (const float*)d_in[4];
    const float* b_q   = (const float*)d_in[5];
    const float* temp  = (const float*)d_in[6];
    const float* dw_w  = (const float*)d_in[7];
    const float* dw_b  = (const float*)d_in[8];
    const float* ci_w1 = (const float*)d_in[9];
    const float* ci_b1 = (const float*)d_in[10];
    const float* ci_w2 = (const float*)d_in[11];
    const float* ci_b2 = (const float*)d_in[12];
    const float* si_w1 = (const float*)d_in[13];
    const float* si_b1 = (const float*)d_in[14];
    const float* si_w2 = (const float*)d_in[15];
    const float* si_b2 = (const float*)d_in[16];
    const float* pj_w  = (const float*)d_in[17];
    const float* pj_b  = (const float*)d_in[18];
    float* out = (float*)d_out;

    cudaFuncSetAttribute(k_qkv_mma, cudaFuncAttributeMaxDynamicSharedMemorySize, QKV_SMEM);

    k_zero<<<512, 256>>>();
    k_layernorm<<<Bq*(Nn/32), 256>>>(x, ln_g, ln_b);
    k_buildW<<<Cc, 256>>>(w_qkv, w_q);
    k_buildP<<<64, 256>>>(pj_w);
    k_qkv_mma<<<dim3(6, BN/128), 256, QKV_SMEM>>>(b_q);
    k_attn_qk_mma<<<dim3(8, Bq*NH), 256>>>();
    k_softmax<<<Bq*NH, 64>>>(temp);
    k_attn_v_mma<<<dim3(Nn/128, Bq*NH), 256>>>();
    k_dwconv<<<Bq*Cc, 256>>>(dw_w, dw_b);
    k_spatial<<<Bq*16, 256>>>(si_w1, si_b1, si_w2, si_b2);
    k_channel_mlp<<<Bq, 256>>>(ci_w1, ci_b1, ci_w2, ci_b2);
    k_proj_mma<<<dim3(2, BN/128), 256>>>(pj_b, out);
}